// round 3
// baseline (speedup 1.0000x reference)
#include <cuda_runtime.h>
#include <cuda_bf16.h>
#include <cstdint>

#define N_NODES 50000
#define N_EDGES 800000
#define N_GRAPHS 256
#define HID 64
#define OUT_CLS 7
#define NEG_SLOPE 0.01f

// Output layout: logits [256*7] | reconstructed [N*1024] | original [N*1024]
#define OFF_RECON (N_GRAPHS * OUT_CLS)
#define OFF_ORIG  (OFF_RECON + N_NODES * 1024)

// ---------------- scratch (static device globals; no allocation allowed) ----------
__device__ float g_h0   [N_NODES * 3];
__device__ float g_aggr0[N_NODES * 3];
__device__ float g_h1   [N_NODES * 64];
__device__ float g_aggr1[N_NODES * 64];
__device__ float g_bufA [N_NODES * 256];
__device__ float g_bufB [N_NODES * 256];
__device__ float g_lat  [N_NODES * 256];
__device__ float g_pool [N_GRAPHS * 256];
__device__ float g_cnt  [N_GRAPHS];

// ---------------- helpers ---------------------------------------------------------
__device__ __forceinline__ void red_add_v4(float4* addr, float4 v) {
    asm volatile("red.global.add.v4.f32 [%0], {%1, %2, %3, %4};"
                 :: "l"(addr), "f"(v.x), "f"(v.y), "f"(v.z), "f"(v.w) : "memory");
}
__device__ __forceinline__ float lrelu(float v) { return v >= 0.f ? v : NEG_SLOPE * v; }

__device__ __forceinline__ uint32_t pack_bf16(float x, float y) {
    __nv_bfloat162 t = __floats2bfloat162_rn(x, y);
    return *reinterpret_cast<uint32_t*>(&t);
}

__device__ __forceinline__ void mma_bf16(float* d, const uint32_t* a, const uint32_t* b) {
    asm volatile(
        "mma.sync.aligned.m16n8k16.row.col.f32.bf16.bf16.f32 "
        "{%0,%1,%2,%3}, {%4,%5,%6,%7}, {%8,%9}, {%0,%1,%2,%3};"
        : "+f"(d[0]), "+f"(d[1]), "+f"(d[2]), "+f"(d[3])
        : "r"(a[0]), "r"(a[1]), "r"(a[2]), "r"(a[3]), "r"(b[0]), "r"(b[1]));
}

__global__ void zero4_kernel(float4* p, int n4) {
    int i = blockIdx.x * blockDim.x + threadIdx.x;
    if (i < n4) p[i] = make_float4(0.f, 0.f, 0.f, 0.f);
}

// ---------------- embedding lookup ------------------------------------------------
__global__ void embed_kernel(const int* __restrict__ x, const float* __restrict__ emb,
                             float* __restrict__ h0) {
    int i = blockIdx.x * blockDim.x + threadIdx.x;
    if (i < N_NODES) {
        int lab = x[i];
        const float* e = emb + lab * 3;
        float* o = h0 + i * 3;
        o[0] = e[0]; o[1] = e[1]; o[2] = e[2];
    }
}

// ---------------- 3-wide edge aggregation (conv1) ---------------------------------
__global__ void edge3_kernel(const float* __restrict__ xin, float* __restrict__ out,
                             const int* __restrict__ src, const int* __restrict__ dst) {
    int e = blockIdx.x * blockDim.x + threadIdx.x;
    if (e < N_EDGES) {
        int s = src[e], d = dst[e];
        atomicAdd(&out[d * 3 + 0], xin[s * 3 + 0]);
        atomicAdd(&out[d * 3 + 1], xin[s * 3 + 1]);
        atomicAdd(&out[d * 3 + 2], xin[s * 3 + 2]);
    }
}

// ---------------- vectorized edge aggregation -------------------------------------
__global__ void edge_agg_v4(const float* __restrict__ xin, float* __restrict__ out,
                            const int* __restrict__ src, const int* __restrict__ dst,
                            int c4shift, int total) {
    int i = blockIdx.x * blockDim.x + threadIdx.x;
    if (i >= total) return;
    int e = i >> c4shift;
    int c = i & ((1 << c4shift) - 1);
    int s = src[e], d = dst[e];
    int c4 = 1 << c4shift;
    float4 v = reinterpret_cast<const float4*>(xin)[(size_t)s * c4 + c];
    red_add_v4(reinterpret_cast<float4*>(out) + (size_t)d * c4 + c, v);
}

// ---------------- conv1 -----------------------------------------------------------
__global__ void conv1_kernel(const float* __restrict__ aggr0, const float* __restrict__ h0,
                             const float* __restrict__ w_rel, const float* __restrict__ w_root,
                             const float* __restrict__ b, float* __restrict__ h1) {
    __shared__ float swr[192], swo[192], sb[64];
    int tid = threadIdx.x;
    if (tid < 192) { swr[tid] = w_rel[tid]; swo[tid] = w_root[tid]; }
    if (tid < 64) sb[tid] = b[tid];
    __syncthreads();
    int idx = blockIdx.x * blockDim.x + tid;
    if (idx >= N_NODES * 64) return;
    int node = idx >> 6, c = idx & 63;
    float a0 = aggr0[node*3+0], a1 = aggr0[node*3+1], a2 = aggr0[node*3+2];
    float x0 = h0[node*3+0],   x1 = h0[node*3+1],   x2 = h0[node*3+2];
    float v = sb[c]
            + a0 * swr[c] + a1 * swr[64 + c] + a2 * swr[128 + c]
            + x0 * swo[c] + x1 * swo[64 + c] + x2 * swo[128 + c];
    h1[idx] = lrelu(v);
}

// ---------------- double-buffered bf16-split tensor-core GEMM ---------------------
// C = act(A1@W1 + A2@W2 + add + bias). fp32 in/out, Markidis 3-product split.
// Block 128x128, BK=32, 256 threads (8 warps, 32x64 warp tiles).
#define BM 128
#define BN 128
#define BK 32
#define SROW 40            // bf16 per A/B smem row (32 + 8 pad) = 20 words
#define TILE_BF16 (128 * SROW)          // one array (e.g. AsH) per stage
#define STAGE_BF16 (4 * TILE_BF16)      // AsH, AsL, BsH, BsL
// total dynamic smem = 2 stages * STAGE_BF16 * 2B = 81920 B

__global__ void __launch_bounds__(256, 1)
gemm_bf16_dual(const float* __restrict__ A1, const float* __restrict__ W1, int K1,
               const float* __restrict__ A2, const float* __restrict__ W2, int K2,
               const float* __restrict__ add, const float* __restrict__ bias,
               float* __restrict__ C, int M, int N, int leaky) {
    extern __shared__ __align__(16) __nv_bfloat16 smem_dyn[];

    int tid = threadIdx.x;
    int lane = tid & 31, wid = tid >> 5;
    int wm = (wid & 3) * 32;    // 4 warps over 128 rows
    int wn = (wid >> 2) * 64;   // 2 warps over 128 cols
    int brow = blockIdx.y * BM;
    int bcol = blockIdx.x * BN;

    float acc[2][8][4];
#pragma unroll
    for (int mt = 0; mt < 2; mt++)
#pragma unroll
        for (int nt = 0; nt < 8; nt++)
#pragma unroll
            for (int r = 0; r < 4; r++) acc[mt][nt][r] = 0.f;

    int T1 = A1 ? (K1 / BK) : 0;
    int T2 = A2 ? (K2 / BK) : 0;
    int T = T1 + T2;

    // staging index precompute
    int a_row = 0, a_c4 = 0, b_k = 0, b_n4 = 0;
    // per-p values derived inside loops

    float4 pa[4], pb[4];

    // ---- tile load into registers ----
    auto load_tile = [&](int t) {
        const float* A; const float* W; int K; int k0;
        if (t < T1) { A = A1; W = W1; K = K1; k0 = t * BK; }
        else        { A = A2; W = W2; K = K2; k0 = (t - T1) * BK; }
#pragma unroll
        for (int p = 0; p < 4; p++) {
            int idx = tid + p * 256;          // 0..1023
            int row = idx >> 3;
            int c4  = idx & 7;
            int grow = brow + row;
            float4 v = make_float4(0.f, 0.f, 0.f, 0.f);
            if (grow < M)
                v = *reinterpret_cast<const float4*>(A + (size_t)grow * K + k0 + c4 * 4);
            pa[p] = v;
        }
#pragma unroll
        for (int p = 0; p < 4; p++) {
            int idx = tid + p * 256;          // 0..1023
            int k  = idx >> 5;                // 0..31
            int n4 = (idx & 31) * 4;          // 0..124
            pb[p] = *reinterpret_cast<const float4*>(W + (size_t)(k0 + k) * N + bcol + n4);
        }
    };

    // ---- convert + store registers into smem stage ----
    auto store_tile = [&](int stage) {
        __nv_bfloat16* AsH = smem_dyn + stage * STAGE_BF16;
        __nv_bfloat16* AsL = AsH + TILE_BF16;
        __nv_bfloat16* BsH = AsL + TILE_BF16;
        __nv_bfloat16* BsL = BsH + TILE_BF16;
        uint32_t* AsH32 = reinterpret_cast<uint32_t*>(AsH);
        uint32_t* AsL32 = reinterpret_cast<uint32_t*>(AsL);
#pragma unroll
        for (int p = 0; p < 4; p++) {
            int idx = tid + p * 256;
            int row = idx >> 3;
            int c4  = idx & 7;
            float4 v = pa[p];
            float hx = __bfloat162float(__float2bfloat16(v.x));
            float hy = __bfloat162float(__float2bfloat16(v.y));
            float hz = __bfloat162float(__float2bfloat16(v.z));
            float hw = __bfloat162float(__float2bfloat16(v.w));
            int w = row * 20 + c4 * 2;
            AsH32[w]     = pack_bf16(hx, hy);
            AsH32[w + 1] = pack_bf16(hz, hw);
            AsL32[w]     = pack_bf16(v.x - hx, v.y - hy);
            AsL32[w + 1] = pack_bf16(v.z - hz, v.w - hw);
        }
#pragma unroll
        for (int p = 0; p < 4; p++) {
            int idx = tid + p * 256;
            int k  = idx >> 5;
            int n4 = (idx & 31) * 4;
            float4 v = pb[p];
            float hv[4], lv[4];
            hv[0] = __bfloat162float(__float2bfloat16(v.x)); lv[0] = v.x - hv[0];
            hv[1] = __bfloat162float(__float2bfloat16(v.y)); lv[1] = v.y - hv[1];
            hv[2] = __bfloat162float(__float2bfloat16(v.z)); lv[2] = v.z - hv[2];
            hv[3] = __bfloat162float(__float2bfloat16(v.w)); lv[3] = v.w - hv[3];
#pragma unroll
            for (int j = 0; j < 4; j++) {
                BsH[(n4 + j) * SROW + k] = __float2bfloat16(hv[j]);
                BsL[(n4 + j) * SROW + k] = __float2bfloat16(lv[j]);
            }
        }
    };

    // ---- compute one staged tile ----
    auto compute_tile = [&](int stage) {
        const uint32_t* AsH32 = reinterpret_cast<const uint32_t*>(smem_dyn + stage * STAGE_BF16);
        const uint32_t* AsL32 = AsH32 + TILE_BF16 / 2;
        const uint32_t* BsH32 = AsL32 + TILE_BF16 / 2;
        const uint32_t* BsL32 = BsH32 + TILE_BF16 / 2;
#pragma unroll
        for (int ks = 0; ks < 2; ks++) {
            int kw = ks * 8 + (lane & 3);
            uint32_t aH[2][4], aL[2][4], bH[8][2], bL[8][2];
#pragma unroll
            for (int mt = 0; mt < 2; mt++) {
                int r = wm + mt * 16 + (lane >> 2);
                aH[mt][0] = AsH32[r * 20 + kw];
                aH[mt][1] = AsH32[(r + 8) * 20 + kw];
                aH[mt][2] = AsH32[r * 20 + kw + 4];
                aH[mt][3] = AsH32[(r + 8) * 20 + kw + 4];
                aL[mt][0] = AsL32[r * 20 + kw];
                aL[mt][1] = AsL32[(r + 8) * 20 + kw];
                aL[mt][2] = AsL32[r * 20 + kw + 4];
                aL[mt][3] = AsL32[(r + 8) * 20 + kw + 4];
            }
#pragma unroll
            for (int nt = 0; nt < 8; nt++) {
                int n = wn + nt * 8 + (lane >> 2);
                bH[nt][0] = BsH32[n * 20 + kw];
                bH[nt][1] = BsH32[n * 20 + kw + 4];
                bL[nt][0] = BsL32[n * 20 + kw];
                bL[nt][1] = BsL32[n * 20 + kw + 4];
            }
#pragma unroll
            for (int mt = 0; mt < 2; mt++)
#pragma unroll
                for (int nt = 0; nt < 8; nt++) {
                    mma_bf16(acc[mt][nt], aH[mt], bH[nt]);
                    mma_bf16(acc[mt][nt], aH[mt], bL[nt]);
                    mma_bf16(acc[mt][nt], aL[mt], bH[nt]);
                }
        }
    };

    // ---- pipelined main loop ----
    load_tile(0);
    store_tile(0);
    __syncthreads();
#pragma unroll 1
    for (int t = 0; t < T; t++) {
        int cur = t & 1;
        if (t + 1 < T) load_tile(t + 1);
        compute_tile(cur);
        if (t + 1 < T) {
            store_tile(1 - cur);
            __syncthreads();
        }
    }

    // ---- epilogue ----
#pragma unroll
    for (int mt = 0; mt < 2; mt++) {
#pragma unroll
        for (int nt = 0; nt < 8; nt++) {
            int r0 = brow + wm + mt * 16 + (lane >> 2);
            int c  = bcol + wn + nt * 8 + (lane & 3) * 2;
#pragma unroll
            for (int half = 0; half < 2; half++) {
                int row = r0 + half * 8;
                if (row >= M) continue;
                float v0 = acc[mt][nt][half * 2 + 0];
                float v1 = acc[mt][nt][half * 2 + 1];
                if (add) {
                    const float2 a2 = *reinterpret_cast<const float2*>(add + (size_t)row * N + c);
                    v0 += a2.x; v1 += a2.y;
                }
                if (bias) {
                    const float2 b2 = *reinterpret_cast<const float2*>(bias + c);
                    v0 += b2.x; v1 += b2.y;
                }
                if (leaky) { v0 = lrelu(v0); v1 = lrelu(v1); }
                *reinterpret_cast<float2*>(C + (size_t)row * N + c) = make_float2(v0, v1);
            }
        }
    }
}

// ---------------- pooling + logits ------------------------------------------------
__global__ void pool_kernel(const float* __restrict__ latent, const int* __restrict__ batch,
                            float* __restrict__ pooled) {
    int i = blockIdx.x * blockDim.x + threadIdx.x;
    if (i >= N_NODES * 64) return;
    int node = i >> 6, c = i & 63;
    int g = batch[node];
    float4 v = reinterpret_cast<const float4*>(latent)[(size_t)node * 64 + c];
    red_add_v4(reinterpret_cast<float4*>(pooled) + (size_t)g * 64 + c, v);
}

__global__ void count_kernel(const int* __restrict__ batch, float* __restrict__ counts) {
    int i = blockIdx.x * blockDim.x + threadIdx.x;
    if (i < N_NODES) atomicAdd(&counts[batch[i]], 1.0f);
}

__global__ void logits_kernel(const float* __restrict__ pooled, const float* __restrict__ counts,
                              const float* __restrict__ w_lin, const float* __restrict__ b_lin,
                              float* __restrict__ out) {
    int g = blockIdx.x;
    int o = threadIdx.x;
    if (o >= OUT_CLS) return;
    float inv = 1.0f / fmaxf(counts[g], 1.0f);
    float s = 0.f;
    const float* pr = pooled + g * 256;
    for (int k = 0; k < 256; k++) s += pr[k] * w_lin[k * OUT_CLS + o];
    out[g * OUT_CLS + o] = s * inv + b_lin[o];
}

// ---------------- host launch -----------------------------------------------------
static inline void zero_buf(float* p, int nfloats) {
    int n4 = nfloats / 4;
    zero4_kernel<<<(n4 + 255) / 256, 256>>>(reinterpret_cast<float4*>(p), n4);
}

#define GEMM_SMEM (2 * STAGE_BF16 * (int)sizeof(__nv_bfloat16))

extern "C" void kernel_launch(void* const* d_in, const int* in_sizes, int n_in,
                              void* d_out, int out_size) {
    const int*   x       = (const int*)d_in[0];
    const int*   ei      = (const int*)d_in[1];
    const int*   batch   = (const int*)d_in[2];
    const float* emb     = (const float*)d_in[3];
    const float* w1_rel  = (const float*)d_in[4];
    const float* w1_root = (const float*)d_in[5];
    const float* b1      = (const float*)d_in[6];
    const float* w2_rel  = (const float*)d_in[7];
    const float* w2_root = (const float*)d_in[8];
    const float* b2      = (const float*)d_in[9];
    const float* we_rel  = (const float*)d_in[10];
    const float* we_root = (const float*)d_in[11];
    const float* be      = (const float*)d_in[12];
    const float* wd_rel  = (const float*)d_in[13];
    const float* wd_root = (const float*)d_in[14];
    const float* bd      = (const float*)d_in[15];
    const float* w_lin   = (const float*)d_in[16];
    const float* b_lin   = (const float*)d_in[17];

    const int* src = ei;
    const int* dst = ei + N_EDGES;

    float* out    = (float*)d_out;
    float* logits = out;
    float* recon  = out + OFF_RECON;
    float* orig   = out + OFF_ORIG;

    float *h0, *aggr0, *h1, *aggr1, *bufA, *bufB, *lat, *pool, *cnt;
    cudaGetSymbolAddress((void**)&h0,    g_h0);
    cudaGetSymbolAddress((void**)&aggr0, g_aggr0);
    cudaGetSymbolAddress((void**)&h1,    g_h1);
    cudaGetSymbolAddress((void**)&aggr1, g_aggr1);
    cudaGetSymbolAddress((void**)&bufA,  g_bufA);
    cudaGetSymbolAddress((void**)&bufB,  g_bufB);
    cudaGetSymbolAddress((void**)&lat,   g_lat);
    cudaGetSymbolAddress((void**)&pool,  g_pool);
    cudaGetSymbolAddress((void**)&cnt,   g_cnt);

    cudaFuncSetAttribute(gemm_bf16_dual, cudaFuncAttributeMaxDynamicSharedMemorySize, GEMM_SMEM);

    // ---- embed + conv1 ----
    embed_kernel<<<(N_NODES + 255) / 256, 256>>>(x, emb, h0);
    zero_buf(aggr0, N_NODES * 3);
    edge3_kernel<<<(N_EDGES + 255) / 256, 256>>>(h0, aggr0, src, dst);
    conv1_kernel<<<(N_NODES * 64 + 255) / 256, 256>>>(aggr0, h0, w1_rel, w1_root, b1, h1);

    // ---- conv2: original = leaky(aggr(h1)@w2_rel + h1@w2_root + b2) ----
    zero_buf(aggr1, N_NODES * 64);
    {
        int total = N_EDGES * 16;
        edge_agg_v4<<<(total + 255) / 256, 256>>>(h1, aggr1, src, dst, 4, total);
    }
    {
        dim3 grid(1024 / BN, (N_NODES + BM - 1) / BM);
        gemm_bf16_dual<<<grid, 256, GEMM_SMEM>>>(aggr1, w2_rel, 64, h1, w2_root, 64,
                                                 nullptr, b2, orig, N_NODES, 1024, 1);
    }

    // ---- enc: latent = leaky(aggr(orig@we_rel) + orig@we_root + be) ----
    {
        dim3 grid(256 / BN, (N_NODES + BM - 1) / BM);
        gemm_bf16_dual<<<grid, 256, GEMM_SMEM>>>(orig, we_rel, 1024, nullptr, nullptr, 0,
                                                 nullptr, nullptr, bufA, N_NODES, 256, 0);
    }
    zero_buf(bufB, N_NODES * 256);
    {
        int total = N_EDGES * 64;
        edge_agg_v4<<<(total + 255) / 256, 256>>>(bufA, bufB, src, dst, 6, total);
    }
    {
        dim3 grid(256 / BN, (N_NODES + BM - 1) / BM);
        gemm_bf16_dual<<<grid, 256, GEMM_SMEM>>>(orig, we_root, 1024, nullptr, nullptr, 0,
                                                 bufB, be, lat, N_NODES, 256, 1);
    }

    // ---- pool + logits ----
    zero_buf(pool, N_GRAPHS * 256);
    zero_buf(cnt, N_GRAPHS);
    pool_kernel<<<(N_NODES * 64 + 255) / 256, 256>>>(lat, batch, pool);
    count_kernel<<<(N_NODES + 255) / 256, 256>>>(batch, cnt);
    logits_kernel<<<N_GRAPHS, 32>>>(pool, cnt, w_lin, b_lin, logits);

    // ---- dec: recon = leaky(aggr(latent)@wd_rel + latent@wd_root + bd) ----
    zero_buf(bufA, N_NODES * 256);
    {
        int total = N_EDGES * 64;
        edge_agg_v4<<<(total + 255) / 256, 256>>>(lat, bufA, src, dst, 6, total);
    }
    {
        dim3 grid(1024 / BN, (N_NODES + BM - 1) / BM);
        gemm_bf16_dual<<<grid, 256, GEMM_SMEM>>>(bufA, wd_rel, 256, lat, wd_root, 256,
                                                 nullptr, bd, recon, N_NODES, 1024, 1);
    }
}

// round 4
// speedup vs baseline: 1.8243x; 1.8243x over previous
#include <cuda_runtime.h>
#include <cuda_bf16.h>
#include <cstdint>

#define N_NODES 50000
#define M_PAD   50048
#define N_EDGES 800000
#define N_GRAPHS 256
#define OUT_CLS 7
#define NEG_SLOPE 0.01f

// Output layout: logits [256*7] | reconstructed [N*1024] | original [N*1024]
#define OFF_RECON (N_GRAPHS * OUT_CLS)
#define OFF_ORIG  (OFF_RECON + N_NODES * 1024)

// ---------------- fp32 scratch ----------------------------------------------------
__device__ float g_h0   [N_NODES * 3];
__device__ float g_aggr0[N_NODES * 3];
__device__ float g_h1   [N_NODES * 64];
__device__ float g_aggr1[N_NODES * 64];
__device__ float g_bufA [N_NODES * 256];
__device__ float g_bufB [N_NODES * 256];
__device__ float g_lat  [N_NODES * 256];
__device__ float g_pool [N_GRAPHS * 256];
__device__ float g_cnt  [N_GRAPHS];

// ---------------- pre-split bf16 scratch (hi/lo), padded rows ---------------------
__device__ __nv_bfloat16 g_h1h [M_PAD * 64];
__device__ __nv_bfloat16 g_h1l [M_PAD * 64];
__device__ __nv_bfloat16 g_a1h [M_PAD * 64];
__device__ __nv_bfloat16 g_a1l [M_PAD * 64];
__device__ __nv_bfloat16 g_oh  [M_PAD * 1024];
__device__ __nv_bfloat16 g_ol  [M_PAD * 1024];
__device__ __nv_bfloat16 g_lath[M_PAD * 256];
__device__ __nv_bfloat16 g_latl[M_PAD * 256];
__device__ __nv_bfloat16 g_aggh[M_PAD * 256];
__device__ __nv_bfloat16 g_aggl[M_PAD * 256];
// transposed weights [N][K] hi/lo
__device__ __nv_bfloat16 g_w2r_h[1024 * 64],  g_w2r_l[1024 * 64];
__device__ __nv_bfloat16 g_w2o_h[1024 * 64],  g_w2o_l[1024 * 64];
__device__ __nv_bfloat16 g_wer_h[256 * 1024], g_wer_l[256 * 1024];
__device__ __nv_bfloat16 g_weo_h[256 * 1024], g_weo_l[256 * 1024];
__device__ __nv_bfloat16 g_wdr_h[1024 * 256], g_wdr_l[1024 * 256];
__device__ __nv_bfloat16 g_wdo_h[1024 * 256], g_wdo_l[1024 * 256];

// ---------------- helpers ---------------------------------------------------------
__device__ __forceinline__ void red_add_v4(float4* addr, float4 v) {
    asm volatile("red.global.add.v4.f32 [%0], {%1, %2, %3, %4};"
                 :: "l"(addr), "f"(v.x), "f"(v.y), "f"(v.z), "f"(v.w) : "memory");
}
__device__ __forceinline__ float lrelu(float v) { return v >= 0.f ? v : NEG_SLOPE * v; }

__device__ __forceinline__ uint32_t pack_bf16(float x, float y) {
    __nv_bfloat162 t = __floats2bfloat162_rn(x, y);
    return *reinterpret_cast<uint32_t*>(&t);
}

__device__ __forceinline__ void mma_bf16(float* d, const uint32_t* a, const uint32_t* b) {
    asm volatile(
        "mma.sync.aligned.m16n8k16.row.col.f32.bf16.bf16.f32 "
        "{%0,%1,%2,%3}, {%4,%5,%6,%7}, {%8,%9}, {%0,%1,%2,%3};"
        : "+f"(d[0]), "+f"(d[1]), "+f"(d[2]), "+f"(d[3])
        : "r"(a[0]), "r"(a[1]), "r"(a[2]), "r"(a[3]), "r"(b[0]), "r"(b[1]));
}

__device__ __forceinline__ void cp16(uint32_t dst, const void* src) {
    asm volatile("cp.async.cg.shared.global [%0], [%1], 16;" :: "r"(dst), "l"(src));
}
__device__ __forceinline__ void cp_commit() { asm volatile("cp.async.commit_group;"); }
template <int Np> __device__ __forceinline__ void cp_wait() {
    asm volatile("cp.async.wait_group %0;" :: "n"(Np));
}

__global__ void zero4_kernel(float4* p, int n4) {
    int i = blockIdx.x * blockDim.x + threadIdx.x;
    if (i < n4) p[i] = make_float4(0.f, 0.f, 0.f, 0.f);
}

// ---------------- hi/lo split convert (flat) --------------------------------------
__global__ void cvt_split(const float4* __restrict__ in, uint32_t* __restrict__ oh,
                          uint32_t* __restrict__ ol, int n4) {
    int i = blockIdx.x * blockDim.x + threadIdx.x;
    if (i >= n4) return;
    float4 v = in[i];
    float hx = __bfloat162float(__float2bfloat16(v.x));
    float hy = __bfloat162float(__float2bfloat16(v.y));
    float hz = __bfloat162float(__float2bfloat16(v.z));
    float hw = __bfloat162float(__float2bfloat16(v.w));
    oh[i * 2]     = pack_bf16(hx, hy);
    oh[i * 2 + 1] = pack_bf16(hz, hw);
    ol[i * 2]     = pack_bf16(v.x - hx, v.y - hy);
    ol[i * 2 + 1] = pack_bf16(v.z - hz, v.w - hw);
}

// ---------------- transpose + hi/lo split for weights: [K][N] -> [N][K] -----------
__global__ void transpose_split(const float* __restrict__ W, __nv_bfloat16* __restrict__ oh,
                                __nv_bfloat16* __restrict__ ol, int K, int N) {
    __shared__ float tile[32][33];
    int n0 = blockIdx.x * 32, k0 = blockIdx.y * 32;
    int tx = threadIdx.x, ty = threadIdx.y;
#pragma unroll
    for (int j = 0; j < 32; j += 8)
        tile[ty + j][tx] = W[(size_t)(k0 + ty + j) * N + n0 + tx];
    __syncthreads();
#pragma unroll
    for (int j = 0; j < 32; j += 8) {
        float v = tile[tx][ty + j];
        float h = __bfloat162float(__float2bfloat16(v));
        size_t o = (size_t)(n0 + ty + j) * K + k0 + tx;
        oh[o] = __float2bfloat16(h);
        ol[o] = __float2bfloat16(v - h);
    }
}

// ---------------- embedding / conv1 path ------------------------------------------
__global__ void embed_kernel(const int* __restrict__ x, const float* __restrict__ emb,
                             float* __restrict__ h0) {
    int i = blockIdx.x * blockDim.x + threadIdx.x;
    if (i < N_NODES) {
        int lab = x[i];
        const float* e = emb + lab * 3;
        float* o = h0 + i * 3;
        o[0] = e[0]; o[1] = e[1]; o[2] = e[2];
    }
}

__global__ void edge3_kernel(const float* __restrict__ xin, float* __restrict__ out,
                             const int* __restrict__ src, const int* __restrict__ dst) {
    int e = blockIdx.x * blockDim.x + threadIdx.x;
    if (e < N_EDGES) {
        int s = src[e], d = dst[e];
        atomicAdd(&out[d * 3 + 0], xin[s * 3 + 0]);
        atomicAdd(&out[d * 3 + 1], xin[s * 3 + 1]);
        atomicAdd(&out[d * 3 + 2], xin[s * 3 + 2]);
    }
}

__global__ void edge_agg_v4(const float* __restrict__ xin, float* __restrict__ out,
                            const int* __restrict__ src, const int* __restrict__ dst,
                            int c4shift, int total) {
    int i = blockIdx.x * blockDim.x + threadIdx.x;
    if (i >= total) return;
    int e = i >> c4shift;
    int c = i & ((1 << c4shift) - 1);
    int s = src[e], d = dst[e];
    int c4 = 1 << c4shift;
    float4 v = reinterpret_cast<const float4*>(xin)[(size_t)s * c4 + c];
    red_add_v4(reinterpret_cast<float4*>(out) + (size_t)d * c4 + c, v);
}

__global__ void conv1_kernel(const float* __restrict__ aggr0, const float* __restrict__ h0,
                             const float* __restrict__ w_rel, const float* __restrict__ w_root,
                             const float* __restrict__ b, float* __restrict__ h1) {
    __shared__ float swr[192], swo[192], sb[64];
    int tid = threadIdx.x;
    if (tid < 192) { swr[tid] = w_rel[tid]; swo[tid] = w_root[tid]; }
    if (tid < 64) sb[tid] = b[tid];
    __syncthreads();
    int idx = blockIdx.x * blockDim.x + tid;
    if (idx >= N_NODES * 64) return;
    int node = idx >> 6, c = idx & 63;
    float a0 = aggr0[node*3+0], a1 = aggr0[node*3+1], a2 = aggr0[node*3+2];
    float x0 = h0[node*3+0],   x1 = h0[node*3+1],   x2 = h0[node*3+2];
    float v = sb[c]
            + a0 * swr[c] + a1 * swr[64 + c] + a2 * swr[128 + c]
            + x0 * swo[c] + x1 * swo[64 + c] + x2 * swo[128 + c];
    h1[idx] = lrelu(v);
}

// ---------------- cp.async double-buffered pre-split bf16 GEMM --------------------
// C = act(A1@W1^T + A2@W2^T + add + bias); A [M_PAD][K] bf16 hi/lo, W [N][K] bf16 hi/lo.
// Block 128x64, BK=32, 256 threads, 8 warps (32x32 warp tiles).
#define SROWW 40                 // bf16 per smem row (32 + 8 pad) = 20 words
#define A_TILE_B 10240           // 128*40*2
#define B_TILE_B 5120            // 64*40*2
#define STAGE_B  30720           // AsH + AsL + BsH + BsL
#define GEMM_SMEM (2 * STAGE_B)

__global__ void __launch_bounds__(256, 2)
gemm_split(const __nv_bfloat16* __restrict__ A1h, const __nv_bfloat16* __restrict__ A1l, int K1,
           const __nv_bfloat16* __restrict__ A2h, const __nv_bfloat16* __restrict__ A2l, int K2,
           const __nv_bfloat16* __restrict__ W1h, const __nv_bfloat16* __restrict__ W1l,
           const __nv_bfloat16* __restrict__ W2h, const __nv_bfloat16* __restrict__ W2l,
           const float* __restrict__ add, const float* __restrict__ bias,
           float* __restrict__ C, int M, int N, int leaky) {
    extern __shared__ __align__(16) char smc[];
    int tid = threadIdx.x;
    int lane = tid & 31, wid = tid >> 5;
    int wm = (wid & 3) * 32;
    int wn = (wid >> 2) * 32;
    int brow = blockIdx.y * 128;
    int bcol = blockIdx.x * 64;
    uint32_t sbase = (uint32_t)__cvta_generic_to_shared(smc);

    float acc[2][4][4];
#pragma unroll
    for (int mt = 0; mt < 2; mt++)
#pragma unroll
        for (int nt = 0; nt < 4; nt++)
#pragma unroll
            for (int r = 0; r < 4; r++) acc[mt][nt][r] = 0.f;

    int T1 = A1h ? (K1 / 32) : 0;
    int T2 = A2h ? (K2 / 32) : 0;
    int T = T1 + T2;

    int srow = tid >> 2;        // 0..63
    int sc   = tid & 3;         // 16B chunk within 32 bf16

    auto issue = [&](int t, int stage) {
        const __nv_bfloat16 *Ah, *Al, *Wh, *Wl; int K, k0;
        if (t < T1) { Ah = A1h; Al = A1l; Wh = W1h; Wl = W1l; K = K1; k0 = t * 32; }
        else        { Ah = A2h; Al = A2l; Wh = W2h; Wl = W2l; K = K2; k0 = (t - T1) * 32; }
        uint32_t sb = sbase + stage * STAGE_B;
        // A rows srow and srow+64, hi+lo
        size_t go = (size_t)(brow + srow) * K + k0 + sc * 8;
        cp16(sb + srow * 80 + sc * 16, Ah + go);
        cp16(sb + A_TILE_B + srow * 80 + sc * 16, Al + go);
        size_t go2 = go + (size_t)64 * K;
        cp16(sb + (srow + 64) * 80 + sc * 16, Ah + go2);
        cp16(sb + A_TILE_B + (srow + 64) * 80 + sc * 16, Al + go2);
        // B row srow (n), hi+lo
        size_t gb = (size_t)(bcol + srow) * K + k0 + sc * 8;
        cp16(sb + 2 * A_TILE_B + srow * 80 + sc * 16, Wh + gb);
        cp16(sb + 2 * A_TILE_B + B_TILE_B + srow * 80 + sc * 16, Wl + gb);
        cp_commit();
    };

    auto compute = [&](int stage) {
        const uint32_t* AsH32 = reinterpret_cast<const uint32_t*>(smc + stage * STAGE_B);
        const uint32_t* AsL32 = AsH32 + 2560;
        const uint32_t* BsH32 = AsH32 + 5120;
        const uint32_t* BsL32 = AsH32 + 6400;
#pragma unroll
        for (int ks = 0; ks < 2; ks++) {
            int kw = ks * 8 + (lane & 3);
            uint32_t aH[2][4], aL[2][4], bH[4][2], bL[4][2];
#pragma unroll
            for (int mt = 0; mt < 2; mt++) {
                int r = wm + mt * 16 + (lane >> 2);
                aH[mt][0] = AsH32[r * 20 + kw];
                aH[mt][1] = AsH32[(r + 8) * 20 + kw];
                aH[mt][2] = AsH32[r * 20 + kw + 4];
                aH[mt][3] = AsH32[(r + 8) * 20 + kw + 4];
                aL[mt][0] = AsL32[r * 20 + kw];
                aL[mt][1] = AsL32[(r + 8) * 20 + kw];
                aL[mt][2] = AsL32[r * 20 + kw + 4];
                aL[mt][3] = AsL32[(r + 8) * 20 + kw + 4];
            }
#pragma unroll
            for (int nt = 0; nt < 4; nt++) {
                int n = wn + nt * 8 + (lane >> 2);
                bH[nt][0] = BsH32[n * 20 + kw];
                bH[nt][1] = BsH32[n * 20 + kw + 4];
                bL[nt][0] = BsL32[n * 20 + kw];
                bL[nt][1] = BsL32[n * 20 + kw + 4];
            }
#pragma unroll
            for (int mt = 0; mt < 2; mt++)
#pragma unroll
                for (int nt = 0; nt < 4; nt++) {
                    mma_bf16(acc[mt][nt], aH[mt], bH[nt]);
                    mma_bf16(acc[mt][nt], aH[mt], bL[nt]);
                    mma_bf16(acc[mt][nt], aL[mt], bH[nt]);
                }
        }
    };

    issue(0, 0);
#pragma unroll 1
    for (int t = 0; t < T; t++) {
        int cur = t & 1;
        if (t + 1 < T) { issue(t + 1, 1 - cur); cp_wait<1>(); }
        else           { cp_wait<0>(); }
        __syncthreads();
        compute(cur);
        __syncthreads();
    }

    // ---- epilogue ----
#pragma unroll
    for (int mt = 0; mt < 2; mt++) {
#pragma unroll
        for (int nt = 0; nt < 4; nt++) {
            int r0 = brow + wm + mt * 16 + (lane >> 2);
            int c  = bcol + wn + nt * 8 + (lane & 3) * 2;
#pragma unroll
            for (int half = 0; half < 2; half++) {
                int row = r0 + half * 8;
                if (row >= M) continue;
                float v0 = acc[mt][nt][half * 2 + 0];
                float v1 = acc[mt][nt][half * 2 + 1];
                if (add) {
                    const float2 a2 = *reinterpret_cast<const float2*>(add + (size_t)row * N + c);
                    v0 += a2.x; v1 += a2.y;
                }
                if (bias) {
                    const float2 b2 = *reinterpret_cast<const float2*>(bias + c);
                    v0 += b2.x; v1 += b2.y;
                }
                if (leaky) { v0 = lrelu(v0); v1 = lrelu(v1); }
                *reinterpret_cast<float2*>(C + (size_t)row * N + c) = make_float2(v0, v1);
            }
        }
    }
}

// ---------------- pooling + logits ------------------------------------------------
__global__ void pool_kernel(const float* __restrict__ latent, const int* __restrict__ batch,
                            float* __restrict__ pooled) {
    int i = blockIdx.x * blockDim.x + threadIdx.x;
    if (i >= N_NODES * 64) return;
    int node = i >> 6, c = i & 63;
    int g = batch[node];
    float4 v = reinterpret_cast<const float4*>(latent)[(size_t)node * 64 + c];
    red_add_v4(reinterpret_cast<float4*>(pooled) + (size_t)g * 64 + c, v);
}

__global__ void count_kernel(const int* __restrict__ batch, float* __restrict__ counts) {
    int i = blockIdx.x * blockDim.x + threadIdx.x;
    if (i < N_NODES) atomicAdd(&counts[batch[i]], 1.0f);
}

__global__ void logits_kernel(const float* __restrict__ pooled, const float* __restrict__ counts,
                              const float* __restrict__ w_lin, const float* __restrict__ b_lin,
                              float* __restrict__ out) {
    int g = blockIdx.x;
    int o = threadIdx.x;
    if (o >= OUT_CLS) return;
    float inv = 1.0f / fmaxf(counts[g], 1.0f);
    float s = 0.f;
    const float* pr = pooled + g * 256;
    for (int k = 0; k < 256; k++) s += pr[k] * w_lin[k * OUT_CLS + o];
    out[g * OUT_CLS + o] = s * inv + b_lin[o];
}

// ---------------- host launch -----------------------------------------------------
static inline void zero_buf(float* p, int nfloats) {
    int n4 = nfloats / 4;
    zero4_kernel<<<(n4 + 255) / 256, 256>>>(reinterpret_cast<float4*>(p), n4);
}
static inline void split(const float* in, __nv_bfloat16* oh, __nv_bfloat16* ol, int n) {
    int n4 = n / 4;
    cvt_split<<<(n4 + 255) / 256, 256>>>(reinterpret_cast<const float4*>(in),
                                         reinterpret_cast<uint32_t*>(oh),
                                         reinterpret_cast<uint32_t*>(ol), n4);
}

extern "C" void kernel_launch(void* const* d_in, const int* in_sizes, int n_in,
                              void* d_out, int out_size) {
    const int*   x       = (const int*)d_in[0];
    const int*   ei      = (const int*)d_in[1];
    const int*   batch   = (const int*)d_in[2];
    const float* emb     = (const float*)d_in[3];
    const float* w1_rel  = (const float*)d_in[4];
    const float* w1_root = (const float*)d_in[5];
    const float* b1      = (const float*)d_in[6];
    const float* w2_rel  = (const float*)d_in[7];
    const float* w2_root = (const float*)d_in[8];
    const float* b2      = (const float*)d_in[9];
    const float* we_rel  = (const float*)d_in[10];
    const float* we_root = (const float*)d_in[11];
    const float* be      = (const float*)d_in[12];
    const float* wd_rel  = (const float*)d_in[13];
    const float* wd_root = (const float*)d_in[14];
    const float* bd      = (const float*)d_in[15];
    const float* w_lin   = (const float*)d_in[16];
    const float* b_lin   = (const float*)d_in[17];

    const int* src = ei;
    const int* dst = ei + N_EDGES;

    float* out    = (float*)d_out;
    float* logits = out;
    float* recon  = out + OFF_RECON;
    float* orig   = out + OFF_ORIG;

    float *h0, *aggr0, *h1, *aggr1, *bufA, *bufB, *lat, *pool, *cnt;
    cudaGetSymbolAddress((void**)&h0,    g_h0);
    cudaGetSymbolAddress((void**)&aggr0, g_aggr0);
    cudaGetSymbolAddress((void**)&h1,    g_h1);
    cudaGetSymbolAddress((void**)&aggr1, g_aggr1);
    cudaGetSymbolAddress((void**)&bufA,  g_bufA);
    cudaGetSymbolAddress((void**)&bufB,  g_bufB);
    cudaGetSymbolAddress((void**)&lat,   g_lat);
    cudaGetSymbolAddress((void**)&pool,  g_pool);
    cudaGetSymbolAddress((void**)&cnt,   g_cnt);

    __nv_bfloat16 *h1h,*h1l,*a1h,*a1l,*oh,*ol,*lath,*latl,*aggh,*aggl;
    __nv_bfloat16 *w2rh,*w2rl,*w2oh,*w2ol,*werh,*werl,*weoh,*weol,*wdrh,*wdrl,*wdoh,*wdol;
    cudaGetSymbolAddress((void**)&h1h, g_h1h);   cudaGetSymbolAddress((void**)&h1l, g_h1l);
    cudaGetSymbolAddress((void**)&a1h, g_a1h);   cudaGetSymbolAddress((void**)&a1l, g_a1l);
    cudaGetSymbolAddress((void**)&oh,  g_oh);    cudaGetSymbolAddress((void**)&ol,  g_ol);
    cudaGetSymbolAddress((void**)&lath,g_lath);  cudaGetSymbolAddress((void**)&latl,g_latl);
    cudaGetSymbolAddress((void**)&aggh,g_aggh);  cudaGetSymbolAddress((void**)&aggl,g_aggl);
    cudaGetSymbolAddress((void**)&w2rh,g_w2r_h); cudaGetSymbolAddress((void**)&w2rl,g_w2r_l);
    cudaGetSymbolAddress((void**)&w2oh,g_w2o_h); cudaGetSymbolAddress((void**)&w2ol,g_w2o_l);
    cudaGetSymbolAddress((void**)&werh,g_wer_h); cudaGetSymbolAddress((void**)&werl,g_wer_l);
    cudaGetSymbolAddress((void**)&weoh,g_weo_h); cudaGetSymbolAddress((void**)&weol,g_weo_l);
    cudaGetSymbolAddress((void**)&wdrh,g_wdr_h); cudaGetSymbolAddress((void**)&wdrl,g_wdr_l);
    cudaGetSymbolAddress((void**)&wdoh,g_wdo_h); cudaGetSymbolAddress((void**)&wdol,g_wdo_l);

    cudaFuncSetAttribute(gemm_split, cudaFuncAttributeMaxDynamicSharedMemorySize, GEMM_SMEM);

    // ---- weight transpose + split (tiny) ----
    {
        dim3 b(32, 8);
        transpose_split<<<dim3(1024/32,  64/32), b>>>(w2_rel,  w2rh, w2rl,   64, 1024);
        transpose_split<<<dim3(1024/32,  64/32), b>>>(w2_root, w2oh, w2ol,   64, 1024);
        transpose_split<<<dim3( 256/32,1024/32), b>>>(we_rel,  werh, werl, 1024,  256);
        transpose_split<<<dim3( 256/32,1024/32), b>>>(we_root, weoh, weol, 1024,  256);
        transpose_split<<<dim3(1024/32, 256/32), b>>>(wd_rel,  wdrh, wdrl,  256, 1024);
        transpose_split<<<dim3(1024/32, 256/32), b>>>(wd_root, wdoh, wdol,  256, 1024);
    }

    // ---- embed + conv1 ----
    embed_kernel<<<(N_NODES + 255) / 256, 256>>>(x, emb, h0);
    zero_buf(aggr0, N_NODES * 3);
    edge3_kernel<<<(N_EDGES + 255) / 256, 256>>>(h0, aggr0, src, dst);
    conv1_kernel<<<(N_NODES * 64 + 255) / 256, 256>>>(aggr0, h0, w1_rel, w1_root, b1, h1);

    // ---- conv2: original = leaky(aggr(h1)@w2_rel + h1@w2_root + b2) ----
    split(h1, h1h, h1l, N_NODES * 64);
    zero_buf(aggr1, N_NODES * 64);
    {
        int total = N_EDGES * 16;
        edge_agg_v4<<<(total + 255) / 256, 256>>>(h1, aggr1, src, dst, 4, total);
    }
    split(aggr1, a1h, a1l, N_NODES * 64);
    {
        dim3 grid(1024 / 64, (N_NODES + 127) / 128);
        gemm_split<<<grid, 256, GEMM_SMEM>>>(a1h, a1l, 64, h1h, h1l, 64,
                                             w2rh, w2rl, w2oh, w2ol,
                                             nullptr, b2, orig, N_NODES, 1024, 1);
    }

    // ---- enc: latent = leaky(aggr(orig@we_rel) + orig@we_root + be) ----
    split(orig, oh, ol, N_NODES * 1024);
    {
        dim3 grid(256 / 64, (N_NODES + 127) / 128);
        gemm_split<<<grid, 256, GEMM_SMEM>>>(oh, ol, 1024, nullptr, nullptr, 0,
                                             werh, werl, nullptr, nullptr,
                                             nullptr, nullptr, bufA, N_NODES, 256, 0);
    }
    zero_buf(bufB, N_NODES * 256);
    {
        int total = N_EDGES * 64;
        edge_agg_v4<<<(total + 255) / 256, 256>>>(bufA, bufB, src, dst, 6, total);
    }
    {
        dim3 grid(256 / 64, (N_NODES + 127) / 128);
        gemm_split<<<grid, 256, GEMM_SMEM>>>(oh, ol, 1024, nullptr, nullptr, 0,
                                             weoh, weol, nullptr, nullptr,
                                             bufB, be, lat, N_NODES, 256, 1);
    }

    // ---- pool + logits ----
    zero_buf(pool, N_GRAPHS * 256);
    zero_buf(cnt, N_GRAPHS);
    pool_kernel<<<(N_NODES * 64 + 255) / 256, 256>>>(lat, batch, pool);
    count_kernel<<<(N_NODES + 255) / 256, 256>>>(batch, cnt);
    logits_kernel<<<N_GRAPHS, 32>>>(pool, cnt, w_lin, b_lin, logits);

    // ---- dec: recon = leaky(aggr(latent)@wd_rel + latent@wd_root + bd) ----
    split(lat, lath, latl, N_NODES * 256);
    zero_buf(bufA, N_NODES * 256);
    {
        int total = N_EDGES * 64;
        edge_agg_v4<<<(total + 255) / 256, 256>>>(lat, bufA, src, dst, 6, total);
    }
    split(bufA, aggh, aggl, N_NODES * 256);
    {
        dim3 grid(1024 / 64, (N_NODES + 127) / 128);
        gemm_split<<<grid, 256, GEMM_SMEM>>>(aggh, aggl, 256, lath, latl, 256,
                                             wdrh, wdrl, wdoh, wdol,
                                             nullptr, bd, recon, N_NODES, 1024, 1);
    }
}

// round 5
// speedup vs baseline: 2.1153x; 1.1595x over previous
#include <cuda_runtime.h>
#include <cuda_bf16.h>
#include <cstdint>

#define N_NODES 50000
#define M_PAD   50048
#define N_EDGES 800000
#define N_GRAPHS 256
#define OUT_CLS 7
#define NEG_SLOPE 0.01f

// Output layout: logits [256*7] | reconstructed [N*1024] | original [N*1024]
#define OFF_RECON (N_GRAPHS * OUT_CLS)
#define OFF_ORIG  (OFF_RECON + N_NODES * 1024)

// ---------------- fp32 scratch ----------------------------------------------------
__device__ float g_h1   [N_NODES * 64];
__device__ float g_bufA [N_NODES * 256];
__device__ float g_bufB [N_NODES * 256];
__device__ float g_lat  [N_NODES * 256];
__device__ float g_pool [N_GRAPHS * 256];
__device__ float g_cnt  [N_GRAPHS];

// ---------------- CSR scratch -----------------------------------------------------
__device__ int g_deg   [N_NODES];
__device__ int g_rowptr[N_NODES + 1];
__device__ int g_posn  [N_NODES];
__device__ int g_esrc  [N_EDGES];

// ---------------- pre-split bf16 scratch (hi/lo), padded rows ---------------------
__device__ __nv_bfloat16 g_h1h [M_PAD * 64];
__device__ __nv_bfloat16 g_h1l [M_PAD * 64];
__device__ __nv_bfloat16 g_a1h [M_PAD * 64];
__device__ __nv_bfloat16 g_a1l [M_PAD * 64];
__device__ __nv_bfloat16 g_oh  [M_PAD * 1024];
__device__ __nv_bfloat16 g_ol  [M_PAD * 1024];
__device__ __nv_bfloat16 g_lath[M_PAD * 256];
__device__ __nv_bfloat16 g_latl[M_PAD * 256];
__device__ __nv_bfloat16 g_aggh[M_PAD * 256];
__device__ __nv_bfloat16 g_aggl[M_PAD * 256];
// transposed weights [N][K] hi/lo
__device__ __nv_bfloat16 g_w2r_h[1024 * 64],  g_w2r_l[1024 * 64];
__device__ __nv_bfloat16 g_w2o_h[1024 * 64],  g_w2o_l[1024 * 64];
__device__ __nv_bfloat16 g_wer_h[256 * 1024], g_wer_l[256 * 1024];
__device__ __nv_bfloat16 g_weo_h[256 * 1024], g_weo_l[256 * 1024];
__device__ __nv_bfloat16 g_wdr_h[1024 * 256], g_wdr_l[1024 * 256];
__device__ __nv_bfloat16 g_wdo_h[1024 * 256], g_wdo_l[1024 * 256];

// ---------------- helpers ---------------------------------------------------------
__device__ __forceinline__ void red_add_v4(float4* addr, float4 v) {
    asm volatile("red.global.add.v4.f32 [%0], {%1, %2, %3, %4};"
                 :: "l"(addr), "f"(v.x), "f"(v.y), "f"(v.z), "f"(v.w) : "memory");
}
__device__ __forceinline__ float lrelu(float v) { return v >= 0.f ? v : NEG_SLOPE * v; }

__device__ __forceinline__ uint32_t pack_bf16(float x, float y) {
    __nv_bfloat162 t = __floats2bfloat162_rn(x, y);
    return *reinterpret_cast<uint32_t*>(&t);
}
__device__ __forceinline__ float bf_round(float v) {
    return __bfloat162float(__float2bfloat16(v));
}

__device__ __forceinline__ void mma_bf16(float* d, const uint32_t* a, const uint32_t* b) {
    asm volatile(
        "mma.sync.aligned.m16n8k16.row.col.f32.bf16.bf16.f32 "
        "{%0,%1,%2,%3}, {%4,%5,%6,%7}, {%8,%9}, {%0,%1,%2,%3};"
        : "+f"(d[0]), "+f"(d[1]), "+f"(d[2]), "+f"(d[3])
        : "r"(a[0]), "r"(a[1]), "r"(a[2]), "r"(a[3]), "r"(b[0]), "r"(b[1]));
}

__device__ __forceinline__ void cp16(uint32_t dst, const void* src) {
    asm volatile("cp.async.cg.shared.global [%0], [%1], 16;" :: "r"(dst), "l"(src));
}
__device__ __forceinline__ void cp_commit() { asm volatile("cp.async.commit_group;"); }
template <int Np> __device__ __forceinline__ void cp_wait() {
    asm volatile("cp.async.wait_group %0;" :: "n"(Np));
}

// ---------------- CSR build -------------------------------------------------------
__global__ void zero_misc(int* deg, float* pool, float* cnt) {
    int i = blockIdx.x * blockDim.x + threadIdx.x;
    if (i < N_NODES) deg[i] = 0;
    if (i < N_GRAPHS * 256) pool[i] = 0.f;
    if (i < N_GRAPHS) cnt[i] = 0.f;
}

__global__ void hist_kernel(const int* __restrict__ dst, int* __restrict__ deg) {
    int e = blockIdx.x * blockDim.x + threadIdx.x;
    if (e < N_EDGES) atomicAdd(&deg[dst[e]], 1);
}

__global__ void scan_kernel(const int* __restrict__ deg, int* __restrict__ rowptr,
                            int* __restrict__ posn) {
    __shared__ int sh[1024];
    __shared__ int carry;
    int tid = threadIdx.x;
    if (tid == 0) carry = 0;
    __syncthreads();
    for (int base = 0; base < N_NODES; base += 1024) {
        int v = (base + tid < N_NODES) ? deg[base + tid] : 0;
        sh[tid] = v;
        __syncthreads();
        for (int off = 1; off < 1024; off <<= 1) {
            int t = (tid >= off) ? sh[tid - off] : 0;
            __syncthreads();
            sh[tid] += t;
            __syncthreads();
        }
        int excl = sh[tid] - v;
        if (base + tid < N_NODES) {
            rowptr[base + tid] = carry + excl;
            posn[base + tid]   = carry + excl;
        }
        int tot = sh[1023];
        __syncthreads();
        if (tid == 0) carry += tot;
        __syncthreads();
    }
    if (tid == 0) rowptr[N_NODES] = carry;
}

__global__ void scatter_kernel(const int* __restrict__ src, const int* __restrict__ dst,
                               int* __restrict__ posn, int* __restrict__ esrc) {
    int e = blockIdx.x * blockDim.x + threadIdx.x;
    if (e < N_EDGES) {
        int idx = atomicAdd(&posn[dst[e]], 1);
        esrc[idx] = src[e];
    }
}

// ---------------- fused conv1: embed + 3-wide gather + linear + split -------------
// warp per node
__global__ void __launch_bounds__(256)
conv1_fused(const int* __restrict__ x, const float* __restrict__ emb,
            const int* __restrict__ rowptr, const int* __restrict__ esrc,
            const float* __restrict__ w_rel, const float* __restrict__ w_root,
            const float* __restrict__ b,
            float* __restrict__ h1, __nv_bfloat16* __restrict__ h1h,
            __nv_bfloat16* __restrict__ h1l) {
    __shared__ float swr[192], swo[192], sb[64];
    int tid = threadIdx.x;
    if (tid < 192) { swr[tid] = w_rel[tid]; swo[tid] = w_root[tid]; }
    if (tid < 64) sb[tid] = b[tid];
    __syncthreads();
    int node = blockIdx.x * 8 + (tid >> 5);
    int lane = tid & 31;
    if (node >= N_NODES) return;
    int bg = rowptr[node], en = rowptr[node + 1];
    float a0 = 0.f, a1 = 0.f, a2 = 0.f;
    for (int j = bg + lane; j < en; j += 32) {
        int s = esrc[j];
        int lab = x[s];
        a0 += emb[lab * 3 + 0];
        a1 += emb[lab * 3 + 1];
        a2 += emb[lab * 3 + 2];
    }
#pragma unroll
    for (int o = 16; o; o >>= 1) {
        a0 += __shfl_xor_sync(0xffffffff, a0, o);
        a1 += __shfl_xor_sync(0xffffffff, a1, o);
        a2 += __shfl_xor_sync(0xffffffff, a2, o);
    }
    int labn = x[node];
    float x0 = emb[labn * 3 + 0], x1 = emb[labn * 3 + 1], x2 = emb[labn * 3 + 2];
    int c = lane * 2;
    float v0 = sb[c]   + a0*swr[c]   + a1*swr[64+c]   + a2*swr[128+c]
                       + x0*swo[c]   + x1*swo[64+c]   + x2*swo[128+c];
    float v1 = sb[c+1] + a0*swr[c+1] + a1*swr[64+c+1] + a2*swr[128+c+1]
                       + x0*swo[c+1] + x1*swo[64+c+1] + x2*swo[128+c+1];
    v0 = lrelu(v0); v1 = lrelu(v1);
    *reinterpret_cast<float2*>(h1 + (size_t)node * 64 + c) = make_float2(v0, v1);
    float h0f = bf_round(v0), h1f = bf_round(v1);
    reinterpret_cast<uint32_t*>(h1h)[node * 32 + lane] = pack_bf16(h0f, h1f);
    reinterpret_cast<uint32_t*>(h1l)[node * 32 + lane] = pack_bf16(v0 - h0f, v1 - h1f);
}

// ---------------- CSR gather, C=64 -> hi/lo bf16 only -----------------------------
__global__ void gather_h16(const float* __restrict__ xin,
                           __nv_bfloat16* __restrict__ oh, __nv_bfloat16* __restrict__ ol,
                           const int* __restrict__ rowptr, const int* __restrict__ esrc) {
    int i = blockIdx.x * blockDim.x + threadIdx.x;
    if (i >= N_NODES * 16) return;
    int node = i >> 4, c = i & 15;
    int bg = rowptr[node], en = rowptr[node + 1];
    float4 acc = make_float4(0.f, 0.f, 0.f, 0.f);
    for (int j = bg; j < en; j++) {
        int s = esrc[j];
        float4 v = reinterpret_cast<const float4*>(xin)[(size_t)s * 16 + c];
        acc.x += v.x; acc.y += v.y; acc.z += v.z; acc.w += v.w;
    }
    float hx = bf_round(acc.x), hy = bf_round(acc.y), hz = bf_round(acc.z), hw = bf_round(acc.w);
    uint32_t* oh32 = reinterpret_cast<uint32_t*>(oh);
    uint32_t* ol32 = reinterpret_cast<uint32_t*>(ol);
    oh32[node * 32 + c * 2]     = pack_bf16(hx, hy);
    oh32[node * 32 + c * 2 + 1] = pack_bf16(hz, hw);
    ol32[node * 32 + c * 2]     = pack_bf16(acc.x - hx, acc.y - hy);
    ol32[node * 32 + c * 2 + 1] = pack_bf16(acc.z - hz, acc.w - hw);
}

// ---------------- CSR gather, C=256 -> optional fp32 / hi-lo ----------------------
__global__ void gather_c256(const float* __restrict__ xin, float* __restrict__ outf,
                            __nv_bfloat16* __restrict__ oh, __nv_bfloat16* __restrict__ ol,
                            const int* __restrict__ rowptr, const int* __restrict__ esrc) {
    int i = blockIdx.x * blockDim.x + threadIdx.x;
    if (i >= N_NODES * 64) return;
    int node = i >> 6, c = i & 63;
    int bg = rowptr[node], en = rowptr[node + 1];
    float4 acc = make_float4(0.f, 0.f, 0.f, 0.f);
    for (int j = bg; j < en; j++) {
        int s = esrc[j];
        float4 v = reinterpret_cast<const float4*>(xin)[(size_t)s * 64 + c];
        acc.x += v.x; acc.y += v.y; acc.z += v.z; acc.w += v.w;
    }
    if (outf)
        reinterpret_cast<float4*>(outf)[(size_t)node * 64 + c] = acc;
    if (oh) {
        float hx = bf_round(acc.x), hy = bf_round(acc.y), hz = bf_round(acc.z), hw = bf_round(acc.w);
        uint32_t* oh32 = reinterpret_cast<uint32_t*>(oh);
        uint32_t* ol32 = reinterpret_cast<uint32_t*>(ol);
        oh32[node * 128 + c * 2]     = pack_bf16(hx, hy);
        oh32[node * 128 + c * 2 + 1] = pack_bf16(hz, hw);
        ol32[node * 128 + c * 2]     = pack_bf16(acc.x - hx, acc.y - hy);
        ol32[node * 128 + c * 2 + 1] = pack_bf16(acc.z - hz, acc.w - hw);
    }
}

// ---------------- transpose + hi/lo split for weights: [K][N] -> [N][K] -----------
__global__ void transpose_split(const float* __restrict__ W, __nv_bfloat16* __restrict__ oh,
                                __nv_bfloat16* __restrict__ ol, int K, int N) {
    __shared__ float tile[32][33];
    int n0 = blockIdx.x * 32, k0 = blockIdx.y * 32;
    int tx = threadIdx.x, ty = threadIdx.y;
#pragma unroll
    for (int j = 0; j < 32; j += 8)
        tile[ty + j][tx] = W[(size_t)(k0 + ty + j) * N + n0 + tx];
    __syncthreads();
#pragma unroll
    for (int j = 0; j < 32; j += 8) {
        float v = tile[tx][ty + j];
        float h = bf_round(v);
        size_t o = (size_t)(n0 + ty + j) * K + k0 + tx;
        oh[o] = __float2bfloat16(h);
        ol[o] = __float2bfloat16(v - h);
    }
}

// ---------------- cp.async double-buffered pre-split bf16 GEMM --------------------
#define A_TILE_B 10240           // 128*40*2
#define B_TILE_B 5120            // 64*40*2
#define STAGE_B  30720
#define GEMM_SMEM (2 * STAGE_B)

__global__ void __launch_bounds__(256, 2)
gemm_split(const __nv_bfloat16* __restrict__ A1h, const __nv_bfloat16* __restrict__ A1l, int K1,
           const __nv_bfloat16* __restrict__ A2h, const __nv_bfloat16* __restrict__ A2l, int K2,
           const __nv_bfloat16* __restrict__ W1h, const __nv_bfloat16* __restrict__ W1l,
           const __nv_bfloat16* __restrict__ W2h, const __nv_bfloat16* __restrict__ W2l,
           const float* __restrict__ add, const float* __restrict__ bias,
           float* __restrict__ C, __nv_bfloat16* __restrict__ Ch,
           __nv_bfloat16* __restrict__ Cl, int M, int N, int leaky) {
    extern __shared__ __align__(16) char smc[];
    int tid = threadIdx.x;
    int lane = tid & 31, wid = tid >> 5;
    int wm = (wid & 3) * 32;
    int wn = (wid >> 2) * 32;
    int brow = blockIdx.y * 128;
    int bcol = blockIdx.x * 64;
    uint32_t sbase = (uint32_t)__cvta_generic_to_shared(smc);

    float acc[2][4][4];
#pragma unroll
    for (int mt = 0; mt < 2; mt++)
#pragma unroll
        for (int nt = 0; nt < 4; nt++)
#pragma unroll
            for (int r = 0; r < 4; r++) acc[mt][nt][r] = 0.f;

    int T1 = A1h ? (K1 / 32) : 0;
    int T2 = A2h ? (K2 / 32) : 0;
    int T = T1 + T2;

    int srow = tid >> 2;
    int sc   = tid & 3;

    auto issue = [&](int t, int stage) {
        const __nv_bfloat16 *Ah, *Al, *Wh, *Wl; int K, k0;
        if (t < T1) { Ah = A1h; Al = A1l; Wh = W1h; Wl = W1l; K = K1; k0 = t * 32; }
        else        { Ah = A2h; Al = A2l; Wh = W2h; Wl = W2l; K = K2; k0 = (t - T1) * 32; }
        uint32_t sb = sbase + stage * STAGE_B;
        size_t go = (size_t)(brow + srow) * K + k0 + sc * 8;
        cp16(sb + srow * 80 + sc * 16, Ah + go);
        cp16(sb + A_TILE_B + srow * 80 + sc * 16, Al + go);
        size_t go2 = go + (size_t)64 * K;
        cp16(sb + (srow + 64) * 80 + sc * 16, Ah + go2);
        cp16(sb + A_TILE_B + (srow + 64) * 80 + sc * 16, Al + go2);
        size_t gb = (size_t)(bcol + srow) * K + k0 + sc * 8;
        cp16(sb + 2 * A_TILE_B + srow * 80 + sc * 16, Wh + gb);
        cp16(sb + 2 * A_TILE_B + B_TILE_B + srow * 80 + sc * 16, Wl + gb);
        cp_commit();
    };

    auto compute = [&](int stage) {
        const uint32_t* AsH32 = reinterpret_cast<const uint32_t*>(smc + stage * STAGE_B);
        const uint32_t* AsL32 = AsH32 + 2560;
        const uint32_t* BsH32 = AsH32 + 5120;
        const uint32_t* BsL32 = AsH32 + 6400;
#pragma unroll
        for (int ks = 0; ks < 2; ks++) {
            int kw = ks * 8 + (lane & 3);
            uint32_t aH[2][4], aL[2][4], bH[4][2], bL[4][2];
#pragma unroll
            for (int mt = 0; mt < 2; mt++) {
                int r = wm + mt * 16 + (lane >> 2);
                aH[mt][0] = AsH32[r * 20 + kw];
                aH[mt][1] = AsH32[(r + 8) * 20 + kw];
                aH[mt][2] = AsH32[r * 20 + kw + 4];
                aH[mt][3] = AsH32[(r + 8) * 20 + kw + 4];
                aL[mt][0] = AsL32[r * 20 + kw];
                aL[mt][1] = AsL32[(r + 8) * 20 + kw];
                aL[mt][2] = AsL32[r * 20 + kw + 4];
                aL[mt][3] = AsL32[(r + 8) * 20 + kw + 4];
            }
#pragma unroll
            for (int nt = 0; nt < 4; nt++) {
                int n = wn + nt * 8 + (lane >> 2);
                bH[nt][0] = BsH32[n * 20 + kw];
                bH[nt][1] = BsH32[n * 20 + kw + 4];
                bL[nt][0] = BsL32[n * 20 + kw];
                bL[nt][1] = BsL32[n * 20 + kw + 4];
            }
#pragma unroll
            for (int mt = 0; mt < 2; mt++)
#pragma unroll
                for (int nt = 0; nt < 4; nt++) {
                    mma_bf16(acc[mt][nt], aH[mt], bH[nt]);
                    mma_bf16(acc[mt][nt], aH[mt], bL[nt]);
                    mma_bf16(acc[mt][nt], aL[mt], bH[nt]);
                }
        }
    };

    issue(0, 0);
#pragma unroll 1
    for (int t = 0; t < T; t++) {
        int cur = t & 1;
        if (t + 1 < T) { issue(t + 1, 1 - cur); cp_wait<1>(); }
        else           { cp_wait<0>(); }
        __syncthreads();
        compute(cur);
        __syncthreads();
    }

    // ---- epilogue ----
#pragma unroll
    for (int mt = 0; mt < 2; mt++) {
#pragma unroll
        for (int nt = 0; nt < 4; nt++) {
            int r0 = brow + wm + mt * 16 + (lane >> 2);
            int c  = bcol + wn + nt * 8 + (lane & 3) * 2;
#pragma unroll
            for (int half = 0; half < 2; half++) {
                int row = r0 + half * 8;
                if (row >= M) continue;
                float v0 = acc[mt][nt][half * 2 + 0];
                float v1 = acc[mt][nt][half * 2 + 1];
                if (add) {
                    const float2 a2 = *reinterpret_cast<const float2*>(add + (size_t)row * N + c);
                    v0 += a2.x; v1 += a2.y;
                }
                if (bias) {
                    const float2 b2 = *reinterpret_cast<const float2*>(bias + c);
                    v0 += b2.x; v1 += b2.y;
                }
                if (leaky) { v0 = lrelu(v0); v1 = lrelu(v1); }
                *reinterpret_cast<float2*>(C + (size_t)row * N + c) = make_float2(v0, v1);
                if (Ch) {
                    float h0 = bf_round(v0), h1f = bf_round(v1);
                    *reinterpret_cast<uint32_t*>(Ch + (size_t)row * N + c) = pack_bf16(h0, h1f);
                    *reinterpret_cast<uint32_t*>(Cl + (size_t)row * N + c) = pack_bf16(v0 - h0, v1 - h1f);
                }
            }
        }
    }
}

// ---------------- pooling + logits ------------------------------------------------
__global__ void pool_kernel(const float* __restrict__ latent, const int* __restrict__ batch,
                            float* __restrict__ pooled) {
    int i = blockIdx.x * blockDim.x + threadIdx.x;
    if (i >= N_NODES * 64) return;
    int node = i >> 6, c = i & 63;
    int g = batch[node];
    float4 v = reinterpret_cast<const float4*>(latent)[(size_t)node * 64 + c];
    red_add_v4(reinterpret_cast<float4*>(pooled) + (size_t)g * 64 + c, v);
}

__global__ void count_kernel(const int* __restrict__ batch, float* __restrict__ counts) {
    int i = blockIdx.x * blockDim.x + threadIdx.x;
    if (i < N_NODES) atomicAdd(&counts[batch[i]], 1.0f);
}

__global__ void logits_kernel(const float* __restrict__ pooled, const float* __restrict__ counts,
                              const float* __restrict__ w_lin, const float* __restrict__ b_lin,
                              float* __restrict__ out) {
    int g = blockIdx.x;
    int o = threadIdx.x;
    if (o >= OUT_CLS) return;
    float inv = 1.0f / fmaxf(counts[g], 1.0f);
    float s = 0.f;
    const float* pr = pooled + g * 256;
    for (int k = 0; k < 256; k++) s += pr[k] * w_lin[k * OUT_CLS + o];
    out[g * OUT_CLS + o] = s * inv + b_lin[o];
}

// ---------------- host launch -----------------------------------------------------
extern "C" void kernel_launch(void* const* d_in, const int* in_sizes, int n_in,
                              void* d_out, int out_size) {
    const int*   x       = (const int*)d_in[0];
    const int*   ei      = (const int*)d_in[1];
    const int*   batch   = (const int*)d_in[2];
    const float* emb     = (const float*)d_in[3];
    const float* w1_rel  = (const float*)d_in[4];
    const float* w1_root = (const float*)d_in[5];
    const float* b1      = (const float*)d_in[6];
    const float* w2_rel  = (const float*)d_in[7];
    const float* w2_root = (const float*)d_in[8];
    const float* b2      = (const float*)d_in[9];
    const float* we_rel  = (const float*)d_in[10];
    const float* we_root = (const float*)d_in[11];
    const float* be      = (const float*)d_in[12];
    const float* wd_rel  = (const float*)d_in[13];
    const float* wd_root = (const float*)d_in[14];
    const float* bd      = (const float*)d_in[15];
    const float* w_lin   = (const float*)d_in[16];
    const float* b_lin   = (const float*)d_in[17];

    const int* src = ei;
    const int* dst = ei + N_EDGES;

    float* out    = (float*)d_out;
    float* logits = out;
    float* recon  = out + OFF_RECON;
    float* orig   = out + OFF_ORIG;

    float *h1, *bufA, *bufB, *lat, *pool, *cnt;
    int *deg, *rowptr, *posn, *esrc;
    cudaGetSymbolAddress((void**)&h1,    g_h1);
    cudaGetSymbolAddress((void**)&bufA,  g_bufA);
    cudaGetSymbolAddress((void**)&bufB,  g_bufB);
    cudaGetSymbolAddress((void**)&lat,   g_lat);
    cudaGetSymbolAddress((void**)&pool,  g_pool);
    cudaGetSymbolAddress((void**)&cnt,   g_cnt);
    cudaGetSymbolAddress((void**)&deg,   g_deg);
    cudaGetSymbolAddress((void**)&rowptr,g_rowptr);
    cudaGetSymbolAddress((void**)&posn,  g_posn);
    cudaGetSymbolAddress((void**)&esrc,  g_esrc);

    __nv_bfloat16 *h1h,*h1l,*a1h,*a1l,*oh,*ol,*lath,*latl,*aggh,*aggl;
    __nv_bfloat16 *w2rh,*w2rl,*w2oh,*w2ol,*werh,*werl,*weoh,*weol,*wdrh,*wdrl,*wdoh,*wdol;
    cudaGetSymbolAddress((void**)&h1h, g_h1h);   cudaGetSymbolAddress((void**)&h1l, g_h1l);
    cudaGetSymbolAddress((void**)&a1h, g_a1h);   cudaGetSymbolAddress((void**)&a1l, g_a1l);
    cudaGetSymbolAddress((void**)&oh,  g_oh);    cudaGetSymbolAddress((void**)&ol,  g_ol);
    cudaGetSymbolAddress((void**)&lath,g_lath);  cudaGetSymbolAddress((void**)&latl,g_latl);
    cudaGetSymbolAddress((void**)&aggh,g_aggh);  cudaGetSymbolAddress((void**)&aggl,g_aggl);
    cudaGetSymbolAddress((void**)&w2rh,g_w2r_h); cudaGetSymbolAddress((void**)&w2rl,g_w2r_l);
    cudaGetSymbolAddress((void**)&w2oh,g_w2o_h); cudaGetSymbolAddress((void**)&w2ol,g_w2o_l);
    cudaGetSymbolAddress((void**)&werh,g_wer_h); cudaGetSymbolAddress((void**)&werl,g_wer_l);
    cudaGetSymbolAddress((void**)&weoh,g_weo_h); cudaGetSymbolAddress((void**)&weol,g_weo_l);
    cudaGetSymbolAddress((void**)&wdrh,g_wdr_h); cudaGetSymbolAddress((void**)&wdrl,g_wdr_l);
    cudaGetSymbolAddress((void**)&wdoh,g_wdo_h); cudaGetSymbolAddress((void**)&wdol,g_wdo_l);

    cudaFuncSetAttribute(gemm_split, cudaFuncAttributeMaxDynamicSharedMemorySize, GEMM_SMEM);

    // idx0: zero deg/pool/cnt
    zero_misc<<<256, 256>>>(deg, pool, cnt);
    // idx1-3: CSR build
    hist_kernel<<<(N_EDGES + 255) / 256, 256>>>(dst, deg);
    scan_kernel<<<1, 1024>>>(deg, rowptr, posn);
    scatter_kernel<<<(N_EDGES + 255) / 256, 256>>>(src, dst, posn, esrc);

    // idx4: fused conv1 (embed + gather3 + linear + split)
    conv1_fused<<<(N_NODES + 7) / 8, 256>>>(x, emb, rowptr, esrc,
                                            w1_rel, w1_root, b1, h1, h1h, h1l);

    // idx5: 64-wide gather (h1 -> aggr hi/lo)   [profiled launch]
    gather_h16<<<(N_NODES * 16 + 255) / 256, 256>>>(h1, a1h, a1l, rowptr, esrc);

    // idx6-7: w2 transposes
    {
        dim3 b(32, 8);
        transpose_split<<<dim3(1024/32, 64/32), b>>>(w2_rel,  w2rh, w2rl, 64, 1024);
        transpose_split<<<dim3(1024/32, 64/32), b>>>(w2_root, w2oh, w2ol, 64, 1024);
    }
    // idx8: conv2 GEMM -> orig (+hi/lo)
    {
        dim3 grid(1024 / 64, (N_NODES + 127) / 128);
        gemm_split<<<grid, 256, GEMM_SMEM>>>(a1h, a1l, 64, h1h, h1l, 64,
                                             w2rh, w2rl, w2oh, w2ol,
                                             nullptr, b2, orig, oh, ol, N_NODES, 1024, 1);
    }

    // idx9-10: we transposes
    {
        dim3 b(32, 8);
        transpose_split<<<dim3(256/32, 1024/32), b>>>(we_rel,  werh, werl, 1024, 256);
        transpose_split<<<dim3(256/32, 1024/32), b>>>(we_root, weoh, weol, 1024, 256);
    }
    // idx11: enc-rel GEMM -> bufA (fp32 only)
    {
        dim3 grid(256 / 64, (N_NODES + 127) / 128);
        gemm_split<<<grid, 256, GEMM_SMEM>>>(oh, ol, 1024, nullptr, nullptr, 0,
                                             werh, werl, nullptr, nullptr,
                                             nullptr, nullptr, bufA, nullptr, nullptr,
                                             N_NODES, 256, 0);
    }
    // idx12: 256-wide gather bufA -> bufB (fp32 only)
    gather_c256<<<(N_NODES * 64 + 255) / 256, 256>>>(bufA, bufB, nullptr, nullptr, rowptr, esrc);
    // idx13: enc-root GEMM -> lat (+hi/lo)
    {
        dim3 grid(256 / 64, (N_NODES + 127) / 128);
        gemm_split<<<grid, 256, GEMM_SMEM>>>(oh, ol, 1024, nullptr, nullptr, 0,
                                             weoh, weol, nullptr, nullptr,
                                             bufB, be, lat, lath, latl, N_NODES, 256, 1);
    }

    // idx14: 256-wide gather lat -> agg hi/lo (no fp32)
    gather_c256<<<(N_NODES * 64 + 255) / 256, 256>>>(lat, nullptr, aggh, aggl, rowptr, esrc);

    // idx15-17: pool + logits
    pool_kernel<<<(N_NODES * 64 + 255) / 256, 256>>>(lat, batch, pool);
    count_kernel<<<(N_NODES + 255) / 256, 256>>>(batch, cnt);
    logits_kernel<<<N_GRAPHS, 32>>>(pool, cnt, w_lin, b_lin, logits);

    // idx18-19: wd transposes
    {
        dim3 b(32, 8);
        transpose_split<<<dim3(1024/32, 256/32), b>>>(wd_rel,  wdrh, wdrl, 256, 1024);
        transpose_split<<<dim3(1024/32, 256/32), b>>>(wd_root, wdoh, wdol, 256, 1024);
    }
    // idx20: dec GEMM -> recon
    {
        dim3 grid(1024 / 64, (N_NODES + 127) / 128);
        gemm_split<<<grid, 256, GEMM_SMEM>>>(aggh, aggl, 256, lath, latl, 256,
                                             wdrh, wdrl, wdoh, wdol,
                                             nullptr, bd, recon, nullptr, nullptr,
                                             N_NODES, 1024, 1);
    }
}

// round 6
// speedup vs baseline: 2.2228x; 1.0508x over previous
#include <cuda_runtime.h>
#include <cuda_bf16.h>
#include <cstdint>

#define N_NODES 50000
#define M_PAD   50048
#define N_EDGES 800000
#define N_GRAPHS 256
#define OUT_CLS 7
#define NEG_SLOPE 0.01f

// Output layout: logits [256*7] | reconstructed [N*1024] | original [N*1024]
#define OFF_RECON (N_GRAPHS * OUT_CLS)
#define OFF_ORIG  (OFF_RECON + N_NODES * 1024)

// ---------------- fp32 scratch ----------------------------------------------------
__device__ float g_h1   [N_NODES * 64];
__device__ float g_bufA [N_NODES * 256];
__device__ float g_bufB [N_NODES * 256];
__device__ float g_lat  [N_NODES * 256];
__device__ float g_pool [N_GRAPHS * 256];
__device__ float g_cnt  [N_GRAPHS];

// ---------------- CSR scratch -----------------------------------------------------
__device__ int g_deg   [N_NODES];
__device__ int g_rowptr[N_NODES + 1];
__device__ int g_posn  [N_NODES];
__device__ int g_esrc  [N_EDGES];

// ---------------- pre-split bf16 scratch (hi/lo), padded rows ---------------------
__device__ __nv_bfloat16 g_h1h [M_PAD * 64];
__device__ __nv_bfloat16 g_h1l [M_PAD * 64];
__device__ __nv_bfloat16 g_a1h [M_PAD * 64];
__device__ __nv_bfloat16 g_a1l [M_PAD * 64];
__device__ __nv_bfloat16 g_oh  [M_PAD * 1024];
__device__ __nv_bfloat16 g_ol  [M_PAD * 1024];
__device__ __nv_bfloat16 g_lath[M_PAD * 256];
__device__ __nv_bfloat16 g_latl[M_PAD * 256];
__device__ __nv_bfloat16 g_aggh[M_PAD * 256];
__device__ __nv_bfloat16 g_aggl[M_PAD * 256];
// transposed weights [N][K] hi/lo
__device__ __nv_bfloat16 g_w2r_h[1024 * 64],  g_w2r_l[1024 * 64];
__device__ __nv_bfloat16 g_w2o_h[1024 * 64],  g_w2o_l[1024 * 64];
__device__ __nv_bfloat16 g_wer_h[256 * 1024], g_wer_l[256 * 1024];
__device__ __nv_bfloat16 g_weo_h[256 * 1024], g_weo_l[256 * 1024];
__device__ __nv_bfloat16 g_wdr_h[1024 * 256], g_wdr_l[1024 * 256];
__device__ __nv_bfloat16 g_wdo_h[1024 * 256], g_wdo_l[1024 * 256];

// ---------------- helpers ---------------------------------------------------------
__device__ __forceinline__ void red_add_v4(float4* addr, float4 v) {
    asm volatile("red.global.add.v4.f32 [%0], {%1, %2, %3, %4};"
                 :: "l"(addr), "f"(v.x), "f"(v.y), "f"(v.z), "f"(v.w) : "memory");
}
__device__ __forceinline__ float lrelu(float v) { return v >= 0.f ? v : NEG_SLOPE * v; }

__device__ __forceinline__ uint32_t pack_bf16(float x, float y) {
    __nv_bfloat162 t = __floats2bfloat162_rn(x, y);
    return *reinterpret_cast<uint32_t*>(&t);
}
__device__ __forceinline__ float bf_round(float v) {
    return __bfloat162float(__float2bfloat16(v));
}

__device__ __forceinline__ void mma_bf16(float* d, const uint32_t* a, const uint32_t* b) {
    asm volatile(
        "mma.sync.aligned.m16n8k16.row.col.f32.bf16.bf16.f32 "
        "{%0,%1,%2,%3}, {%4,%5,%6,%7}, {%8,%9}, {%0,%1,%2,%3};"
        : "+f"(d[0]), "+f"(d[1]), "+f"(d[2]), "+f"(d[3])
        : "r"(a[0]), "r"(a[1]), "r"(a[2]), "r"(a[3]), "r"(b[0]), "r"(b[1]));
}

__device__ __forceinline__ void ldsm4(uint32_t* r, uint32_t addr) {
    asm volatile("ldmatrix.sync.aligned.m8n8.x4.shared.b16 {%0,%1,%2,%3}, [%4];"
                 : "=r"(r[0]), "=r"(r[1]), "=r"(r[2]), "=r"(r[3]) : "r"(addr));
}

__device__ __forceinline__ void cp16(uint32_t dst, const void* src) {
    asm volatile("cp.async.cg.shared.global [%0], [%1], 16;" :: "r"(dst), "l"(src));
}
__device__ __forceinline__ void cp_commit() { asm volatile("cp.async.commit_group;"); }
template <int Np> __device__ __forceinline__ void cp_wait() {
    asm volatile("cp.async.wait_group %0;" :: "n"(Np));
}

// ---------------- CSR build -------------------------------------------------------
__global__ void zero_misc(int* deg, float* pool, float* cnt) {
    int i = blockIdx.x * blockDim.x + threadIdx.x;
    if (i < N_NODES) deg[i] = 0;
    if (i < N_GRAPHS * 256) pool[i] = 0.f;
    if (i < N_GRAPHS) cnt[i] = 0.f;
}

__global__ void hist_kernel(const int* __restrict__ dst, int* __restrict__ deg) {
    int e = blockIdx.x * blockDim.x + threadIdx.x;
    if (e < N_EDGES) atomicAdd(&deg[dst[e]], 1);
}

__global__ void scan_kernel(const int* __restrict__ deg, int* __restrict__ rowptr,
                            int* __restrict__ posn) {
    __shared__ int sh[1024];
    __shared__ int carry;
    int tid = threadIdx.x;
    if (tid == 0) carry = 0;
    __syncthreads();
    for (int base = 0; base < N_NODES; base += 1024) {
        int v = (base + tid < N_NODES) ? deg[base + tid] : 0;
        sh[tid] = v;
        __syncthreads();
        for (int off = 1; off < 1024; off <<= 1) {
            int t = (tid >= off) ? sh[tid - off] : 0;
            __syncthreads();
            sh[tid] += t;
            __syncthreads();
        }
        int excl = sh[tid] - v;
        if (base + tid < N_NODES) {
            rowptr[base + tid] = carry + excl;
            posn[base + tid]   = carry + excl;
        }
        int tot = sh[1023];
        __syncthreads();
        if (tid == 0) carry += tot;
        __syncthreads();
    }
    if (tid == 0) rowptr[N_NODES] = carry;
}

__global__ void scatter_kernel(const int* __restrict__ src, const int* __restrict__ dst,
                               int* __restrict__ posn, int* __restrict__ esrc) {
    int e = blockIdx.x * blockDim.x + threadIdx.x;
    if (e < N_EDGES) {
        int idx = atomicAdd(&posn[dst[e]], 1);
        esrc[idx] = src[e];
    }
}

// ---------------- fused conv1: embed + 3-wide gather + linear + split -------------
__global__ void __launch_bounds__(256)
conv1_fused(const int* __restrict__ x, const float* __restrict__ emb,
            const int* __restrict__ rowptr, const int* __restrict__ esrc,
            const float* __restrict__ w_rel, const float* __restrict__ w_root,
            const float* __restrict__ b,
            float* __restrict__ h1, __nv_bfloat16* __restrict__ h1h,
            __nv_bfloat16* __restrict__ h1l) {
    __shared__ float swr[192], swo[192], sb[64];
    int tid = threadIdx.x;
    if (tid < 192) { swr[tid] = w_rel[tid]; swo[tid] = w_root[tid]; }
    if (tid < 64) sb[tid] = b[tid];
    __syncthreads();
    int node = blockIdx.x * 8 + (tid >> 5);
    int lane = tid & 31;
    if (node >= N_NODES) return;
    int bg = rowptr[node], en = rowptr[node + 1];
    float a0 = 0.f, a1 = 0.f, a2 = 0.f;
    for (int j = bg + lane; j < en; j += 32) {
        int s = esrc[j];
        int lab = x[s];
        a0 += emb[lab * 3 + 0];
        a1 += emb[lab * 3 + 1];
        a2 += emb[lab * 3 + 2];
    }
#pragma unroll
    for (int o = 16; o; o >>= 1) {
        a0 += __shfl_xor_sync(0xffffffff, a0, o);
        a1 += __shfl_xor_sync(0xffffffff, a1, o);
        a2 += __shfl_xor_sync(0xffffffff, a2, o);
    }
    int labn = x[node];
    float x0 = emb[labn * 3 + 0], x1 = emb[labn * 3 + 1], x2 = emb[labn * 3 + 2];
    int c = lane * 2;
    float v0 = sb[c]   + a0*swr[c]   + a1*swr[64+c]   + a2*swr[128+c]
                       + x0*swo[c]   + x1*swo[64+c]   + x2*swo[128+c];
    float v1 = sb[c+1] + a0*swr[c+1] + a1*swr[64+c+1] + a2*swr[128+c+1]
                       + x0*swo[c+1] + x1*swo[64+c+1] + x2*swo[128+c+1];
    v0 = lrelu(v0); v1 = lrelu(v1);
    *reinterpret_cast<float2*>(h1 + (size_t)node * 64 + c) = make_float2(v0, v1);
    float h0f = bf_round(v0), h1f = bf_round(v1);
    reinterpret_cast<uint32_t*>(h1h)[node * 32 + lane] = pack_bf16(h0f, h1f);
    reinterpret_cast<uint32_t*>(h1l)[node * 32 + lane] = pack_bf16(v0 - h0f, v1 - h1f);
}

// ---------------- CSR gather, C=64 -> hi/lo bf16 only -----------------------------
__global__ void gather_h16(const float* __restrict__ xin,
                           __nv_bfloat16* __restrict__ oh, __nv_bfloat16* __restrict__ ol,
                           const int* __restrict__ rowptr, const int* __restrict__ esrc) {
    int i = blockIdx.x * blockDim.x + threadIdx.x;
    if (i >= N_NODES * 16) return;
    int node = i >> 4, c = i & 15;
    int bg = rowptr[node], en = rowptr[node + 1];
    float4 acc = make_float4(0.f, 0.f, 0.f, 0.f);
    for (int j = bg; j < en; j++) {
        int s = esrc[j];
        float4 v = reinterpret_cast<const float4*>(xin)[(size_t)s * 16 + c];
        acc.x += v.x; acc.y += v.y; acc.z += v.z; acc.w += v.w;
    }
    float hx = bf_round(acc.x), hy = bf_round(acc.y), hz = bf_round(acc.z), hw = bf_round(acc.w);
    uint32_t* oh32 = reinterpret_cast<uint32_t*>(oh);
    uint32_t* ol32 = reinterpret_cast<uint32_t*>(ol);
    oh32[node * 32 + c * 2]     = pack_bf16(hx, hy);
    oh32[node * 32 + c * 2 + 1] = pack_bf16(hz, hw);
    ol32[node * 32 + c * 2]     = pack_bf16(acc.x - hx, acc.y - hy);
    ol32[node * 32 + c * 2 + 1] = pack_bf16(acc.z - hz, acc.w - hw);
}

// ---------------- CSR gather, C=256 -> optional fp32 / hi-lo ----------------------
__global__ void gather_c256(const float* __restrict__ xin, float* __restrict__ outf,
                            __nv_bfloat16* __restrict__ oh, __nv_bfloat16* __restrict__ ol,
                            const int* __restrict__ rowptr, const int* __restrict__ esrc) {
    int i = blockIdx.x * blockDim.x + threadIdx.x;
    if (i >= N_NODES * 64) return;
    int node = i >> 6, c = i & 63;
    int bg = rowptr[node], en = rowptr[node + 1];
    float4 acc = make_float4(0.f, 0.f, 0.f, 0.f);
    for (int j = bg; j < en; j++) {
        int s = esrc[j];
        float4 v = reinterpret_cast<const float4*>(xin)[(size_t)s * 64 + c];
        acc.x += v.x; acc.y += v.y; acc.z += v.z; acc.w += v.w;
    }
    if (outf)
        reinterpret_cast<float4*>(outf)[(size_t)node * 64 + c] = acc;
    if (oh) {
        float hx = bf_round(acc.x), hy = bf_round(acc.y), hz = bf_round(acc.z), hw = bf_round(acc.w);
        uint32_t* oh32 = reinterpret_cast<uint32_t*>(oh);
        uint32_t* ol32 = reinterpret_cast<uint32_t*>(ol);
        oh32[node * 128 + c * 2]     = pack_bf16(hx, hy);
        oh32[node * 128 + c * 2 + 1] = pack_bf16(hz, hw);
        ol32[node * 128 + c * 2]     = pack_bf16(acc.x - hx, acc.y - hy);
        ol32[node * 128 + c * 2 + 1] = pack_bf16(acc.z - hz, acc.w - hw);
    }
}

// ---------------- transpose + hi/lo split for weights: [K][N] -> [N][K] -----------
__global__ void transpose_split(const float* __restrict__ W, __nv_bfloat16* __restrict__ oh,
                                __nv_bfloat16* __restrict__ ol, int K, int N) {
    __shared__ float tile[32][33];
    int n0 = blockIdx.x * 32, k0 = blockIdx.y * 32;
    int tx = threadIdx.x, ty = threadIdx.y;
#pragma unroll
    for (int j = 0; j < 32; j += 8)
        tile[ty + j][tx] = W[(size_t)(k0 + ty + j) * N + n0 + tx];
    __syncthreads();
#pragma unroll
    for (int j = 0; j < 32; j += 8) {
        float v = tile[tx][ty + j];
        float h = bf_round(v);
        size_t o = (size_t)(n0 + ty + j) * K + k0 + tx;
        oh[o] = __float2bfloat16(h);
        ol[o] = __float2bfloat16(v - h);
    }
}

// ---------------- cp.async double-buffered pre-split bf16 GEMM (ldmatrix) ---------
#define A_TILE_B 10240           // 128*40*2
#define B_TILE_B 5120            // 64*40*2
#define STAGE_B  30720
#define GEMM_SMEM (2 * STAGE_B)

__global__ void __launch_bounds__(256, 2)
gemm_split(const __nv_bfloat16* __restrict__ A1h, const __nv_bfloat16* __restrict__ A1l, int K1,
           const __nv_bfloat16* __restrict__ A2h, const __nv_bfloat16* __restrict__ A2l, int K2,
           const __nv_bfloat16* __restrict__ W1h, const __nv_bfloat16* __restrict__ W1l,
           const __nv_bfloat16* __restrict__ W2h, const __nv_bfloat16* __restrict__ W2l,
           const float* __restrict__ add, const float* __restrict__ bias,
           float* __restrict__ C, __nv_bfloat16* __restrict__ Ch,
           __nv_bfloat16* __restrict__ Cl, int M, int N, int leaky) {
    extern __shared__ __align__(16) char smc[];
    int tid = threadIdx.x;
    int lane = tid & 31, wid = tid >> 5;
    int wm = (wid & 3) * 32;
    int wn = (wid >> 2) * 32;
    int brow = blockIdx.y * 128;
    int bcol = blockIdx.x * 64;
    uint32_t sbase = (uint32_t)__cvta_generic_to_shared(smc);

    float acc[2][4][4];
#pragma unroll
    for (int mt = 0; mt < 2; mt++)
#pragma unroll
        for (int nt = 0; nt < 4; nt++)
#pragma unroll
            for (int r = 0; r < 4; r++) acc[mt][nt][r] = 0.f;

    int T1 = A1h ? (K1 / 32) : 0;
    int T2 = A2h ? (K2 / 32) : 0;
    int T = T1 + T2;

    int srow = tid >> 2;
    int sc   = tid & 3;

    // ---- per-lane ldmatrix base offsets (bytes, within a region) ----
    // A, per mt: lanes 0-7 rows 0-7 k0-7 | 8-15 rows 8-15 k0-7 | 16-23 rows 0-7 k8-15 | 24-31 rows 8-15 k8-15
    int lr = lane & 7;
    uint32_t a_off[2];
#pragma unroll
    for (int mt = 0; mt < 2; mt++) {
        int row = wm + mt * 16 + ((lane >> 3) & 1) * 8 + lr;
        a_off[mt] = row * 80 + (lane >> 4) * 16;
    }
    // B, per nt-pair p: lanes 0-7 n0-7 k0-7 | 8-15 n0-7 k8-15 | 16-23 n8-15 k0-7 | 24-31 n8-15 k8-15
    uint32_t b_off[2];
#pragma unroll
    for (int p = 0; p < 2; p++) {
        int n = wn + p * 16 + (lane >> 4) * 8 + lr;
        b_off[p] = n * 80 + ((lane >> 3) & 1) * 16;
    }

    auto issue = [&](int t, int stage) {
        const __nv_bfloat16 *Ah, *Al, *Wh, *Wl; int K, k0;
        if (t < T1) { Ah = A1h; Al = A1l; Wh = W1h; Wl = W1l; K = K1; k0 = t * 32; }
        else        { Ah = A2h; Al = A2l; Wh = W2h; Wl = W2l; K = K2; k0 = (t - T1) * 32; }
        uint32_t sb = sbase + stage * STAGE_B;
        size_t go = (size_t)(brow + srow) * K + k0 + sc * 8;
        cp16(sb + srow * 80 + sc * 16, Ah + go);
        cp16(sb + A_TILE_B + srow * 80 + sc * 16, Al + go);
        size_t go2 = go + (size_t)64 * K;
        cp16(sb + (srow + 64) * 80 + sc * 16, Ah + go2);
        cp16(sb + A_TILE_B + (srow + 64) * 80 + sc * 16, Al + go2);
        size_t gb = (size_t)(bcol + srow) * K + k0 + sc * 8;
        cp16(sb + 2 * A_TILE_B + srow * 80 + sc * 16, Wh + gb);
        cp16(sb + 2 * A_TILE_B + B_TILE_B + srow * 80 + sc * 16, Wl + gb);
        cp_commit();
    };

    auto compute = [&](int stage) {
        uint32_t sb = sbase + stage * STAGE_B;
#pragma unroll
        for (int ks = 0; ks < 2; ks++) {
            uint32_t koff = ks * 32;
            uint32_t aH[2][4], aL[2][4], bH[4][2], bL[4][2];
#pragma unroll
            for (int mt = 0; mt < 2; mt++) {
                ldsm4(aH[mt], sb + a_off[mt] + koff);
                ldsm4(aL[mt], sb + A_TILE_B + a_off[mt] + koff);
            }
#pragma unroll
            for (int p = 0; p < 2; p++) {
                ldsm4(&bH[p * 2][0], sb + 2 * A_TILE_B + b_off[p] + koff);
                ldsm4(&bL[p * 2][0], sb + 2 * A_TILE_B + B_TILE_B + b_off[p] + koff);
            }
#pragma unroll
            for (int mt = 0; mt < 2; mt++)
#pragma unroll
                for (int nt = 0; nt < 4; nt++) {
                    mma_bf16(acc[mt][nt], aH[mt], bH[nt]);
                    mma_bf16(acc[mt][nt], aH[mt], bL[nt]);
                    mma_bf16(acc[mt][nt], aL[mt], bH[nt]);
                }
        }
    };

    issue(0, 0);
#pragma unroll 1
    for (int t = 0; t < T; t++) {
        int cur = t & 1;
        if (t + 1 < T) { issue(t + 1, 1 - cur); cp_wait<1>(); }
        else           { cp_wait<0>(); }
        __syncthreads();
        compute(cur);
        __syncthreads();
    }

    // ---- epilogue ----
#pragma unroll
    for (int mt = 0; mt < 2; mt++) {
#pragma unroll
        for (int nt = 0; nt < 4; nt++) {
            int r0 = brow + wm + mt * 16 + (lane >> 2);
            int c  = bcol + wn + nt * 8 + (lane & 3) * 2;
#pragma unroll
            for (int half = 0; half < 2; half++) {
                int row = r0 + half * 8;
                if (row >= M) continue;
                float v0 = acc[mt][nt][half * 2 + 0];
                float v1 = acc[mt][nt][half * 2 + 1];
                if (add) {
                    const float2 a2 = *reinterpret_cast<const float2*>(add + (size_t)row * N + c);
                    v0 += a2.x; v1 += a2.y;
                }
                if (bias) {
                    const float2 b2 = *reinterpret_cast<const float2*>(bias + c);
                    v0 += b2.x; v1 += b2.y;
                }
                if (leaky) { v0 = lrelu(v0); v1 = lrelu(v1); }
                *reinterpret_cast<float2*>(C + (size_t)row * N + c) = make_float2(v0, v1);
                if (Ch) {
                    float h0 = bf_round(v0), h1f = bf_round(v1);
                    *reinterpret_cast<uint32_t*>(Ch + (size_t)row * N + c) = pack_bf16(h0, h1f);
                    *reinterpret_cast<uint32_t*>(Cl + (size_t)row * N + c) = pack_bf16(v0 - h0, v1 - h1f);
                }
            }
        }
    }
}

// ---------------- pooling + logits ------------------------------------------------
__global__ void pool_kernel(const float* __restrict__ latent, const int* __restrict__ batch,
                            float* __restrict__ pooled) {
    int i = blockIdx.x * blockDim.x + threadIdx.x;
    if (i >= N_NODES * 64) return;
    int node = i >> 6, c = i & 63;
    int g = batch[node];
    float4 v = reinterpret_cast<const float4*>(latent)[(size_t)node * 64 + c];
    red_add_v4(reinterpret_cast<float4*>(pooled) + (size_t)g * 64 + c, v);
}

__global__ void count_kernel(const int* __restrict__ batch, float* __restrict__ counts) {
    int i = blockIdx.x * blockDim.x + threadIdx.x;
    if (i < N_NODES) atomicAdd(&counts[batch[i]], 1.0f);
}

__global__ void logits_kernel(const float* __restrict__ pooled, const float* __restrict__ counts,
                              const float* __restrict__ w_lin, const float* __restrict__ b_lin,
                              float* __restrict__ out) {
    int g = blockIdx.x;
    int o = threadIdx.x;
    if (o >= OUT_CLS) return;
    float inv = 1.0f / fmaxf(counts[g], 1.0f);
    float s = 0.f;
    const float* pr = pooled + g * 256;
    for (int k = 0; k < 256; k++) s += pr[k] * w_lin[k * OUT_CLS + o];
    out[g * OUT_CLS + o] = s * inv + b_lin[o];
}

// ---------------- host launch -----------------------------------------------------
extern "C" void kernel_launch(void* const* d_in, const int* in_sizes, int n_in,
                              void* d_out, int out_size) {
    const int*   x       = (const int*)d_in[0];
    const int*   ei      = (const int*)d_in[1];
    const int*   batch   = (const int*)d_in[2];
    const float* emb     = (const float*)d_in[3];
    const float* w1_rel  = (const float*)d_in[4];
    const float* w1_root = (const float*)d_in[5];
    const float* b1      = (const float*)d_in[6];
    const float* w2_rel  = (const float*)d_in[7];
    const float* w2_root = (const float*)d_in[8];
    const float* b2      = (const float*)d_in[9];
    const float* we_rel  = (const float*)d_in[10];
    const float* we_root = (const float*)d_in[11];
    const float* be      = (const float*)d_in[12];
    const float* wd_rel  = (const float*)d_in[13];
    const float* wd_root = (const float*)d_in[14];
    const float* bd      = (const float*)d_in[15];
    const float* w_lin   = (const float*)d_in[16];
    const float* b_lin   = (const float*)d_in[17];

    const int* src = ei;
    const int* dst = ei + N_EDGES;

    float* out    = (float*)d_out;
    float* logits = out;
    float* recon  = out + OFF_RECON;
    float* orig   = out + OFF_ORIG;

    float *h1, *bufA, *bufB, *lat, *pool, *cnt;
    int *deg, *rowptr, *posn, *esrc;
    cudaGetSymbolAddress((void**)&h1,    g_h1);
    cudaGetSymbolAddress((void**)&bufA,  g_bufA);
    cudaGetSymbolAddress((void**)&bufB,  g_bufB);
    cudaGetSymbolAddress((void**)&lat,   g_lat);
    cudaGetSymbolAddress((void**)&pool,  g_pool);
    cudaGetSymbolAddress((void**)&cnt,   g_cnt);
    cudaGetSymbolAddress((void**)&deg,   g_deg);
    cudaGetSymbolAddress((void**)&rowptr,g_rowptr);
    cudaGetSymbolAddress((void**)&posn,  g_posn);
    cudaGetSymbolAddress((void**)&esrc,  g_esrc);

    __nv_bfloat16 *h1h,*h1l,*a1h,*a1l,*oh,*ol,*lath,*latl,*aggh,*aggl;
    __nv_bfloat16 *w2rh,*w2rl,*w2oh,*w2ol,*werh,*werl,*weoh,*weol,*wdrh,*wdrl,*wdoh,*wdol;
    cudaGetSymbolAddress((void**)&h1h, g_h1h);   cudaGetSymbolAddress((void**)&h1l, g_h1l);
    cudaGetSymbolAddress((void**)&a1h, g_a1h);   cudaGetSymbolAddress((void**)&a1l, g_a1l);
    cudaGetSymbolAddress((void**)&oh,  g_oh);    cudaGetSymbolAddress((void**)&ol,  g_ol);
    cudaGetSymbolAddress((void**)&lath,g_lath);  cudaGetSymbolAddress((void**)&latl,g_latl);
    cudaGetSymbolAddress((void**)&aggh,g_aggh);  cudaGetSymbolAddress((void**)&aggl,g_aggl);
    cudaGetSymbolAddress((void**)&w2rh,g_w2r_h); cudaGetSymbolAddress((void**)&w2rl,g_w2r_l);
    cudaGetSymbolAddress((void**)&w2oh,g_w2o_h); cudaGetSymbolAddress((void**)&w2ol,g_w2o_l);
    cudaGetSymbolAddress((void**)&werh,g_wer_h); cudaGetSymbolAddress((void**)&werl,g_wer_l);
    cudaGetSymbolAddress((void**)&weoh,g_weo_h); cudaGetSymbolAddress((void**)&weol,g_weo_l);
    cudaGetSymbolAddress((void**)&wdrh,g_wdr_h); cudaGetSymbolAddress((void**)&wdrl,g_wdr_l);
    cudaGetSymbolAddress((void**)&wdoh,g_wdo_h); cudaGetSymbolAddress((void**)&wdol,g_wdo_l);

    cudaFuncSetAttribute(gemm_split, cudaFuncAttributeMaxDynamicSharedMemorySize, GEMM_SMEM);

    // CSR build
    zero_misc<<<256, 256>>>(deg, pool, cnt);
    hist_kernel<<<(N_EDGES + 255) / 256, 256>>>(dst, deg);
    scan_kernel<<<1, 1024>>>(deg, rowptr, posn);
    scatter_kernel<<<(N_EDGES + 255) / 256, 256>>>(src, dst, posn, esrc);

    // fused conv1
    conv1_fused<<<(N_NODES + 7) / 8, 256>>>(x, emb, rowptr, esrc,
                                            w1_rel, w1_root, b1, h1, h1h, h1l);

    // 64-wide gather (h1 -> aggr hi/lo)
    gather_h16<<<(N_NODES * 16 + 255) / 256, 256>>>(h1, a1h, a1l, rowptr, esrc);

    // w2 transposes
    {
        dim3 b(32, 8);
        transpose_split<<<dim3(1024/32, 64/32), b>>>(w2_rel,  w2rh, w2rl, 64, 1024);
        transpose_split<<<dim3(1024/32, 64/32), b>>>(w2_root, w2oh, w2ol, 64, 1024);
    }
    // conv2 GEMM -> orig (+hi/lo)
    {
        dim3 grid(1024 / 64, (N_NODES + 127) / 128);
        gemm_split<<<grid, 256, GEMM_SMEM>>>(a1h, a1l, 64, h1h, h1l, 64,
                                             w2rh, w2rl, w2oh, w2ol,
                                             nullptr, b2, orig, oh, ol, N_NODES, 1024, 1);
    }

    // we transposes
    {
        dim3 b(32, 8);
        transpose_split<<<dim3(256/32, 1024/32), b>>>(we_rel,  werh, werl, 1024, 256);
        transpose_split<<<dim3(256/32, 1024/32), b>>>(we_root, weoh, weol, 1024, 256);
    }
    // enc-rel GEMM -> bufA (fp32 only)
    {
        dim3 grid(256 / 64, (N_NODES + 127) / 128);
        gemm_split<<<grid, 256, GEMM_SMEM>>>(oh, ol, 1024, nullptr, nullptr, 0,
                                             werh, werl, nullptr, nullptr,
                                             nullptr, nullptr, bufA, nullptr, nullptr,
                                             N_NODES, 256, 0);
    }
    // 256-wide gather bufA -> bufB
    gather_c256<<<(N_NODES * 64 + 255) / 256, 256>>>(bufA, bufB, nullptr, nullptr, rowptr, esrc);
    // enc-root GEMM -> lat (+hi/lo)
    {
        dim3 grid(256 / 64, (N_NODES + 127) / 128);
        gemm_split<<<grid, 256, GEMM_SMEM>>>(oh, ol, 1024, nullptr, nullptr, 0,
                                             weoh, weol, nullptr, nullptr,
                                             bufB, be, lat, lath, latl, N_NODES, 256, 1);
    }

    // 256-wide gather lat -> agg hi/lo
    gather_c256<<<(N_NODES * 64 + 255) / 256, 256>>>(lat, nullptr, aggh, aggl, rowptr, esrc);

    // pool + logits
    pool_kernel<<<(N_NODES * 64 + 255) / 256, 256>>>(lat, batch, pool);
    count_kernel<<<(N_NODES + 255) / 256, 256>>>(batch, cnt);
    logits_kernel<<<N_GRAPHS, 32>>>(pool, cnt, w_lin, b_lin, logits);

    // wd transposes
    {
        dim3 b(32, 8);
        transpose_split<<<dim3(1024/32, 256/32), b>>>(wd_rel,  wdrh, wdrl, 256, 1024);
        transpose_split<<<dim3(1024/32, 256/32), b>>>(wd_root, wdoh, wdol, 256, 1024);
    }
    // dec GEMM -> recon
    {
        dim3 grid(1024 / 64, (N_NODES + 127) / 128);
        gemm_split<<<grid, 256, GEMM_SMEM>>>(aggh, aggl, 256, lath, latl, 256,
                                             wdrh, wdrl, wdoh, wdol,
                                             nullptr, bd, recon, nullptr, nullptr,
                                             N_NODES, 1024, 1);
    }
}

// round 8
// speedup vs baseline: 2.4569x; 1.1053x over previous
#include <cuda_runtime.h>
#include <cuda_bf16.h>
#include <cstdint>

#define N_NODES 50000
#define M_PAD   50048
#define N_EDGES 800000
#define N_GRAPHS 256
#define OUT_CLS 7
#define NEG_SLOPE 0.01f

// Output layout: logits [256*7] | reconstructed [N*1024] | original [N*1024]
#define OFF_RECON (N_GRAPHS * OUT_CLS)
#define OFF_ORIG  (OFF_RECON + N_NODES * 1024)

// ---------------- fp32 scratch ----------------------------------------------------
__device__ float g_h1   [N_NODES * 64];
__device__ float g_enc  [N_NODES * 512];   // fused enc GEMM output: [rel(256) | root(256)]
__device__ float g_lat  [N_NODES * 256];
__device__ float g_pool [N_GRAPHS * 256];
__device__ float g_cnt  [N_GRAPHS];

// ---------------- CSR scratch -----------------------------------------------------
#define SCAN_BLOCKS ((N_NODES + 1023) / 1024)
__device__ int g_deg   [N_NODES];
__device__ int g_rowptr[N_NODES + 1];
__device__ int g_posn  [N_NODES];
__device__ int g_esrc  [N_EDGES];
__device__ int g_part  [SCAN_BLOCKS + 1];

// ---------------- pre-split bf16 scratch (hi/lo), padded rows ---------------------
__device__ __nv_bfloat16 g_h1h [M_PAD * 64];
__device__ __nv_bfloat16 g_h1l [M_PAD * 64];
__device__ __nv_bfloat16 g_a1h [M_PAD * 64];
__device__ __nv_bfloat16 g_a1l [M_PAD * 64];
__device__ __nv_bfloat16 g_oh  [M_PAD * 1024];
__device__ __nv_bfloat16 g_ol  [M_PAD * 1024];
__device__ __nv_bfloat16 g_lath[M_PAD * 256];
__device__ __nv_bfloat16 g_latl[M_PAD * 256];
__device__ __nv_bfloat16 g_aggh[M_PAD * 256];
__device__ __nv_bfloat16 g_aggl[M_PAD * 256];
// transposed weights [N][K] hi/lo
__device__ __nv_bfloat16 g_w2r_h[1024 * 64],  g_w2r_l[1024 * 64];
__device__ __nv_bfloat16 g_w2o_h[1024 * 64],  g_w2o_l[1024 * 64];
__device__ __nv_bfloat16 g_wcat_h[512 * 1024], g_wcat_l[512 * 1024];  // [we_rel ; we_root]
__device__ __nv_bfloat16 g_wdr_h[1024 * 256], g_wdr_l[1024 * 256];
__device__ __nv_bfloat16 g_wdo_h[1024 * 256], g_wdo_l[1024 * 256];

// ---------------- helpers ---------------------------------------------------------
__device__ __forceinline__ void red_add_v4(float4* addr, float4 v) {
    asm volatile("red.global.add.v4.f32 [%0], {%1, %2, %3, %4};"
                 :: "l"(addr), "f"(v.x), "f"(v.y), "f"(v.z), "f"(v.w) : "memory");
}
__device__ __forceinline__ float lrelu(float v) { return v >= 0.f ? v : NEG_SLOPE * v; }

__device__ __forceinline__ uint32_t pack_bf16(float x, float y) {
    __nv_bfloat162 t = __floats2bfloat162_rn(x, y);
    return *reinterpret_cast<uint32_t*>(&t);
}
__device__ __forceinline__ float bf_round(float v) {
    return __bfloat162float(__float2bfloat16(v));
}

__device__ __forceinline__ void mma_bf16(float* d, const uint32_t* a, const uint32_t* b) {
    asm volatile(
        "mma.sync.aligned.m16n8k16.row.col.f32.bf16.bf16.f32 "
        "{%0,%1,%2,%3}, {%4,%5,%6,%7}, {%8,%9}, {%0,%1,%2,%3};"
        : "+f"(d[0]), "+f"(d[1]), "+f"(d[2]), "+f"(d[3])
        : "r"(a[0]), "r"(a[1]), "r"(a[2]), "r"(a[3]), "r"(b[0]), "r"(b[1]));
}

__device__ __forceinline__ void ldsm4(uint32_t* r, uint32_t addr) {
    asm volatile("ldmatrix.sync.aligned.m8n8.x4.shared.b16 {%0,%1,%2,%3}, [%4];"
                 : "=r"(r[0]), "=r"(r[1]), "=r"(r[2]), "=r"(r[3]) : "r"(addr));
}

__device__ __forceinline__ void cp16(uint32_t dst, const void* src) {
    asm volatile("cp.async.cg.shared.global [%0], [%1], 16;" :: "r"(dst), "l"(src));
}
__device__ __forceinline__ void cp_commit() { asm volatile("cp.async.commit_group;"); }
template <int Np> __device__ __forceinline__ void cp_wait() {
    asm volatile("cp.async.wait_group %0;" :: "n"(Np));
}

// ---------------- CSR build -------------------------------------------------------
__global__ void zero_misc(int* deg, float* pool, float* cnt) {
    int i = blockIdx.x * blockDim.x + threadIdx.x;
    if (i < N_NODES) deg[i] = 0;
    if (i < N_GRAPHS * 256) pool[i] = 0.f;
    if (i < N_GRAPHS) cnt[i] = 0.f;
}

__global__ void hist_kernel(const int* __restrict__ dst, int* __restrict__ deg) {
    int e = blockIdx.x * blockDim.x + threadIdx.x;
    if (e < N_EDGES) atomicAdd(&deg[dst[e]], 1);
}

// 3-kernel scan: block-local, partials, add
__global__ void scan_local(const int* __restrict__ deg, int* __restrict__ rowptr,
                           int* __restrict__ part) {
    __shared__ int sh[1024];
    int tid = threadIdx.x;
    int i = blockIdx.x * 1024 + tid;
    int v = (i < N_NODES) ? deg[i] : 0;
    sh[tid] = v;
    __syncthreads();
#pragma unroll
    for (int off = 1; off < 1024; off <<= 1) {
        int t = (tid >= off) ? sh[tid - off] : 0;
        __syncthreads();
        sh[tid] += t;
        __syncthreads();
    }
    if (i < N_NODES) rowptr[i] = sh[tid] - v;   // local exclusive
    if (tid == 1023) part[blockIdx.x] = sh[1023];
}

__global__ void scan_partials(int* __restrict__ part) {
    if (threadIdx.x == 0) {
        int run = 0;
        for (int j = 0; j < SCAN_BLOCKS; j++) {
            int v = part[j];
            part[j] = run;
            run += v;
        }
        part[SCAN_BLOCKS] = run;
    }
}

__global__ void scan_add(int* __restrict__ rowptr, const int* __restrict__ part,
                         int* __restrict__ posn) {
    int i = blockIdx.x * blockDim.x + threadIdx.x;
    if (i < N_NODES) {
        int r = rowptr[i] + part[i >> 10];
        rowptr[i] = r;
        posn[i] = r;
    }
    if (i == 0) rowptr[N_NODES] = part[SCAN_BLOCKS];
}

__global__ void scatter_kernel(const int* __restrict__ src, const int* __restrict__ dst,
                               int* __restrict__ posn, int* __restrict__ esrc) {
    int e = blockIdx.x * blockDim.x + threadIdx.x;
    if (e < N_EDGES) {
        int idx = atomicAdd(&posn[dst[e]], 1);
        esrc[idx] = src[e];
    }
}

// ---------------- fused conv1: embed + 3-wide gather + linear + split -------------
__global__ void __launch_bounds__(256)
conv1_fused(const int* __restrict__ x, const float* __restrict__ emb,
            const int* __restrict__ rowptr, const int* __restrict__ esrc,
            const float* __restrict__ w_rel, const float* __restrict__ w_root,
            const float* __restrict__ b,
            float* __restrict__ h1, __nv_bfloat16* __restrict__ h1h,
            __nv_bfloat16* __restrict__ h1l) {
    __shared__ float swr[192], swo[192], sb[64];
    int tid = threadIdx.x;
    if (tid < 192) { swr[tid] = w_rel[tid]; swo[tid] = w_root[tid]; }
    if (tid < 64) sb[tid] = b[tid];
    __syncthreads();
    int node = blockIdx.x * 8 + (tid >> 5);
    int lane = tid & 31;
    if (node >= N_NODES) return;
    int bg = rowptr[node], en = rowptr[node + 1];
    float a0 = 0.f, a1 = 0.f, a2 = 0.f;
    for (int j = bg + lane; j < en; j += 32) {
        int s = esrc[j];
        int lab = x[s];
        a0 += emb[lab * 3 + 0];
        a1 += emb[lab * 3 + 1];
        a2 += emb[lab * 3 + 2];
    }
#pragma unroll
    for (int o = 16; o; o >>= 1) {
        a0 += __shfl_xor_sync(0xffffffff, a0, o);
        a1 += __shfl_xor_sync(0xffffffff, a1, o);
        a2 += __shfl_xor_sync(0xffffffff, a2, o);
    }
    int labn = x[node];
    float x0 = emb[labn * 3 + 0], x1 = emb[labn * 3 + 1], x2 = emb[labn * 3 + 2];
    int c = lane * 2;
    float v0 = sb[c]   + a0*swr[c]   + a1*swr[64+c]   + a2*swr[128+c]
                       + x0*swo[c]   + x1*swo[64+c]   + x2*swo[128+c];
    float v1 = sb[c+1] + a0*swr[c+1] + a1*swr[64+c+1] + a2*swr[128+c+1]
                       + x0*swo[c+1] + x1*swo[64+c+1] + x2*swo[128+c+1];
    v0 = lrelu(v0); v1 = lrelu(v1);
    *reinterpret_cast<float2*>(h1 + (size_t)node * 64 + c) = make_float2(v0, v1);
    float h0f = bf_round(v0), h1f = bf_round(v1);
    reinterpret_cast<uint32_t*>(h1h)[node * 32 + lane] = pack_bf16(h0f, h1f);
    reinterpret_cast<uint32_t*>(h1l)[node * 32 + lane] = pack_bf16(v0 - h0f, v1 - h1f);
}

// ---------------- CSR gather, C=64 -> hi/lo bf16 only -----------------------------
__global__ void gather_h16(const float* __restrict__ xin,
                           __nv_bfloat16* __restrict__ oh, __nv_bfloat16* __restrict__ ol,
                           const int* __restrict__ rowptr, const int* __restrict__ esrc) {
    int i = blockIdx.x * blockDim.x + threadIdx.x;
    if (i >= N_NODES * 16) return;
    int node = i >> 4, c = i & 15;
    int bg = rowptr[node], en = rowptr[node + 1];
    float4 acc = make_float4(0.f, 0.f, 0.f, 0.f);
    for (int j = bg; j < en; j++) {
        int s = esrc[j];
        float4 v = reinterpret_cast<const float4*>(xin)[(size_t)s * 16 + c];
        acc.x += v.x; acc.y += v.y; acc.z += v.z; acc.w += v.w;
    }
    float hx = bf_round(acc.x), hy = bf_round(acc.y), hz = bf_round(acc.z), hw = bf_round(acc.w);
    uint32_t* oh32 = reinterpret_cast<uint32_t*>(oh);
    uint32_t* ol32 = reinterpret_cast<uint32_t*>(ol);
    oh32[node * 32 + c * 2]     = pack_bf16(hx, hy);
    oh32[node * 32 + c * 2 + 1] = pack_bf16(hz, hw);
    ol32[node * 32 + c * 2]     = pack_bf16(acc.x - hx, acc.y - hy);
    ol32[node * 32 + c * 2 + 1] = pack_bf16(acc.z - hz, acc.w - hw);
}

// ---------------- enc finish: gather rel cols + root cols + bias + leaky + split --
// bufE [N][512]: cols 0-255 = orig@we_rel (to aggregate), cols 256-511 = orig@we_root
__global__ void gather_enc_fin(const float* __restrict__ bufE, const float* __restrict__ be,
                               float* __restrict__ lat, __nv_bfloat16* __restrict__ lath,
                               __nv_bfloat16* __restrict__ latl,
                               const int* __restrict__ rowptr, const int* __restrict__ esrc) {
    int i = blockIdx.x * blockDim.x + threadIdx.x;
    if (i >= N_NODES * 64) return;
    int node = i >> 6, c = i & 63;
    int bg = rowptr[node], en = rowptr[node + 1];
    float4 acc = make_float4(0.f, 0.f, 0.f, 0.f);
    for (int j = bg; j < en; j++) {
        int s = esrc[j];
        float4 v = reinterpret_cast<const float4*>(bufE)[(size_t)s * 128 + c];
        acc.x += v.x; acc.y += v.y; acc.z += v.z; acc.w += v.w;
    }
    float4 rt = reinterpret_cast<const float4*>(bufE)[(size_t)node * 128 + 64 + c];
    float4 b4 = reinterpret_cast<const float4*>(be)[c];
    float v0 = lrelu(acc.x + rt.x + b4.x);
    float v1 = lrelu(acc.y + rt.y + b4.y);
    float v2 = lrelu(acc.z + rt.z + b4.z);
    float v3 = lrelu(acc.w + rt.w + b4.w);
    reinterpret_cast<float4*>(lat)[(size_t)node * 64 + c] = make_float4(v0, v1, v2, v3);
    float h0 = bf_round(v0), h1 = bf_round(v1), h2 = bf_round(v2), h3 = bf_round(v3);
    uint32_t* oh32 = reinterpret_cast<uint32_t*>(lath);
    uint32_t* ol32 = reinterpret_cast<uint32_t*>(latl);
    oh32[node * 128 + c * 2]     = pack_bf16(h0, h1);
    oh32[node * 128 + c * 2 + 1] = pack_bf16(h2, h3);
    ol32[node * 128 + c * 2]     = pack_bf16(v0 - h0, v1 - h1);
    ol32[node * 128 + c * 2 + 1] = pack_bf16(v2 - h2, v3 - h3);
}

// ---------------- CSR gather, C=256 -> hi/lo (dec input) --------------------------
__global__ void gather_c256(const float* __restrict__ xin,
                            __nv_bfloat16* __restrict__ oh, __nv_bfloat16* __restrict__ ol,
                            const int* __restrict__ rowptr, const int* __restrict__ esrc) {
    int i = blockIdx.x * blockDim.x + threadIdx.x;
    if (i >= N_NODES * 64) return;
    int node = i >> 6, c = i & 63;
    int bg = rowptr[node], en = rowptr[node + 1];
    float4 acc = make_float4(0.f, 0.f, 0.f, 0.f);
    for (int j = bg; j < en; j++) {
        int s = esrc[j];
        float4 v = reinterpret_cast<const float4*>(xin)[(size_t)s * 64 + c];
        acc.x += v.x; acc.y += v.y; acc.z += v.z; acc.w += v.w;
    }
    float hx = bf_round(acc.x), hy = bf_round(acc.y), hz = bf_round(acc.z), hw = bf_round(acc.w);
    uint32_t* oh32 = reinterpret_cast<uint32_t*>(oh);
    uint32_t* ol32 = reinterpret_cast<uint32_t*>(ol);
    oh32[node * 128 + c * 2]     = pack_bf16(hx, hy);
    oh32[node * 128 + c * 2 + 1] = pack_bf16(hz, hw);
    ol32[node * 128 + c * 2]     = pack_bf16(acc.x - hx, acc.y - hy);
    ol32[node * 128 + c * 2 + 1] = pack_bf16(acc.z - hz, acc.w - hw);
}

// ---------------- transpose + hi/lo split for weights: [K][N] -> [N][K] -----------
__global__ void transpose_split(const float* __restrict__ W, __nv_bfloat16* __restrict__ oh,
                                __nv_bfloat16* __restrict__ ol, int K, int N) {
    __shared__ float tile[32][33];
    int n0 = blockIdx.x * 32, k0 = blockIdx.y * 32;
    int tx = threadIdx.x, ty = threadIdx.y;
#pragma unroll
    for (int j = 0; j < 32; j += 8)
        tile[ty + j][tx] = W[(size_t)(k0 + ty + j) * N + n0 + tx];
    __syncthreads();
#pragma unroll
    for (int j = 0; j < 32; j += 8) {
        float v = tile[tx][ty + j];
        float h = bf_round(v);
        size_t o = (size_t)(n0 + ty + j) * K + k0 + tx;
        oh[o] = __float2bfloat16(h);
        ol[o] = __float2bfloat16(v - h);
    }
}

// ---------------- cp.async double-buffered pre-split bf16 GEMM (ldmatrix) ---------
#define A_TILE_B 10240           // 128*40*2
#define B_TILE_B 5120            // 64*40*2
#define STAGE_B  30720
#define GEMM_SMEM (2 * STAGE_B)

__global__ void __launch_bounds__(256, 2)
gemm_split(const __nv_bfloat16* __restrict__ A1h, const __nv_bfloat16* __restrict__ A1l, int K1,
           const __nv_bfloat16* __restrict__ A2h, const __nv_bfloat16* __restrict__ A2l, int K2,
           const __nv_bfloat16* __restrict__ W1h, const __nv_bfloat16* __restrict__ W1l,
           const __nv_bfloat16* __restrict__ W2h, const __nv_bfloat16* __restrict__ W2l,
           const float* __restrict__ add, const float* __restrict__ bias,
           float* __restrict__ C, __nv_bfloat16* __restrict__ Ch,
           __nv_bfloat16* __restrict__ Cl, int M, int N, int leaky) {
    extern __shared__ __align__(16) char smc[];
    int tid = threadIdx.x;
    int lane = tid & 31, wid = tid >> 5;
    int wm = (wid & 3) * 32;
    int wn = (wid >> 2) * 32;
    int brow = blockIdx.y * 128;
    int bcol = blockIdx.x * 64;
    uint32_t sbase = (uint32_t)__cvta_generic_to_shared(smc);

    float acc[2][4][4];
#pragma unroll
    for (int mt = 0; mt < 2; mt++)
#pragma unroll
        for (int nt = 0; nt < 4; nt++)
#pragma unroll
            for (int r = 0; r < 4; r++) acc[mt][nt][r] = 0.f;

    int T1 = A1h ? (K1 / 32) : 0;
    int T2 = A2h ? (K2 / 32) : 0;
    int T = T1 + T2;

    int srow = tid >> 2;
    int sc   = tid & 3;

    // per-lane ldmatrix base offsets
    int lr = lane & 7;
    uint32_t a_off[2];
#pragma unroll
    for (int mt = 0; mt < 2; mt++) {
        int row = wm + mt * 16 + ((lane >> 3) & 1) * 8 + lr;
        a_off[mt] = row * 80 + (lane >> 4) * 16;
    }
    uint32_t b_off[2];
#pragma unroll
    for (int p = 0; p < 2; p++) {
        int n = wn + p * 16 + (lane >> 4) * 8 + lr;
        b_off[p] = n * 80 + ((lane >> 3) & 1) * 16;
    }

    auto issue = [&](int t, int stage) {
        const __nv_bfloat16 *Ah, *Al, *Wh, *Wl; int K, k0;
        if (t < T1) { Ah = A1h; Al = A1l; Wh = W1h; Wl = W1l; K = K1; k0 = t * 32; }
        else        { Ah = A2h; Al = A2l; Wh = W2h; Wl = W2l; K = K2; k0 = (t - T1) * 32; }
        uint32_t sb = sbase + stage * STAGE_B;
        size_t go = (size_t)(brow + srow) * K + k0 + sc * 8;
        cp16(sb + srow * 80 + sc * 16, Ah + go);
        cp16(sb + A_TILE_B + srow * 80 + sc * 16, Al + go);
        size_t go2 = go + (size_t)64 * K;
        cp16(sb + (srow + 64) * 80 + sc * 16, Ah + go2);
        cp16(sb + A_TILE_B + (srow + 64) * 80 + sc * 16, Al + go2);
        size_t gb = (size_t)(bcol + srow) * K + k0 + sc * 8;
        cp16(sb + 2 * A_TILE_B + srow * 80 + sc * 16, Wh + gb);
        cp16(sb + 2 * A_TILE_B + B_TILE_B + srow * 80 + sc * 16, Wl + gb);
        cp_commit();
    };

    auto compute = [&](int stage) {
        uint32_t sb = sbase + stage * STAGE_B;
#pragma unroll
        for (int ks = 0; ks < 2; ks++) {
            uint32_t koff = ks * 32;
            uint32_t aH[2][4], aL[2][4], bH[4][2], bL[4][2];
#pragma unroll
            for (int mt = 0; mt < 2; mt++) {
                ldsm4(aH[mt], sb + a_off[mt] + koff);
                ldsm4(aL[mt], sb + A_TILE_B + a_off[mt] + koff);
            }
#pragma unroll
            for (int p = 0; p < 2; p++) {
                ldsm4(&bH[p * 2][0], sb + 2 * A_TILE_B + b_off[p] + koff);
                ldsm4(&bL[p * 2][0], sb + 2 * A_TILE_B + B_TILE_B + b_off[p] + koff);
            }
#pragma unroll
            for (int mt = 0; mt < 2; mt++)
#pragma unroll
                for (int nt = 0; nt < 4; nt++) {
                    mma_bf16(acc[mt][nt], aH[mt], bH[nt]);
                    mma_bf16(acc[mt][nt], aH[mt], bL[nt]);
                    mma_bf16(acc[mt][nt], aL[mt], bH[nt]);
                }
        }
    };

    // ---- single-sync pipelined main loop ----
    issue(0, 0);
#pragma unroll 1
    for (int t = 0; t < T; t++) {
        int cur = t & 1;
        cp_wait<0>();
        __syncthreads();
        if (t + 1 < T) issue(t + 1, 1 - cur);
        compute(cur);
    }

    // ---- epilogue ----
#pragma unroll
    for (int mt = 0; mt < 2; mt++) {
#pragma unroll
        for (int nt = 0; nt < 4; nt++) {
            int r0 = brow + wm + mt * 16 + (lane >> 2);
            int c  = bcol + wn + nt * 8 + (lane & 3) * 2;
#pragma unroll
            for (int half = 0; half < 2; half++) {
                int row = r0 + half * 8;
                if (row >= M) continue;
                float v0 = acc[mt][nt][half * 2 + 0];
                float v1 = acc[mt][nt][half * 2 + 1];
                if (add) {
                    const float2 a2 = *reinterpret_cast<const float2*>(add + (size_t)row * N + c);
                    v0 += a2.x; v1 += a2.y;
                }
                if (bias) {
                    const float2 b2 = *reinterpret_cast<const float2*>(bias + c);
                    v0 += b2.x; v1 += b2.y;
                }
                if (leaky) { v0 = lrelu(v0); v1 = lrelu(v1); }
                *reinterpret_cast<float2*>(C + (size_t)row * N + c) = make_float2(v0, v1);
                if (Ch) {
                    float h0 = bf_round(v0), h1f = bf_round(v1);
                    *reinterpret_cast<uint32_t*>(Ch + (size_t)row * N + c) = pack_bf16(h0, h1f);
                    *reinterpret_cast<uint32_t*>(Cl + (size_t)row * N + c) = pack_bf16(v0 - h0, v1 - h1f);
                }
            }
        }
    }
}

// ---------------- pooling + logits ------------------------------------------------
__global__ void pool_kernel(const float* __restrict__ latent, const int* __restrict__ batch,
                            float* __restrict__ pooled) {
    int i = blockIdx.x * blockDim.x + threadIdx.x;
    if (i >= N_NODES * 64) return;
    int node = i >> 6, c = i & 63;
    int g = batch[node];
    float4 v = reinterpret_cast<const float4*>(latent)[(size_t)node * 64 + c];
    red_add_v4(reinterpret_cast<float4*>(pooled) + (size_t)g * 64 + c, v);
}

__global__ void count_kernel(const int* __restrict__ batch, float* __restrict__ counts) {
    int i = blockIdx.x * blockDim.x + threadIdx.x;
    if (i < N_NODES) atomicAdd(&counts[batch[i]], 1.0f);
}

__global__ void logits_kernel(const float* __restrict__ pooled, const float* __restrict__ counts,
                              const float* __restrict__ w_lin, const float* __restrict__ b_lin,
                              float* __restrict__ out) {
    int g = blockIdx.x;
    int o = threadIdx.x;
    if (o >= OUT_CLS) return;
    float inv = 1.0f / fmaxf(counts[g], 1.0f);
    float s = 0.f;
    const float* pr = pooled + g * 256;
    for (int k = 0; k < 256; k++) s += pr[k] * w_lin[k * OUT_CLS + o];
    out[g * OUT_CLS + o] = s * inv + b_lin[o];
}

// ---------------- host launch -----------------------------------------------------
extern "C" void kernel_launch(void* const* d_in, const int* in_sizes, int n_in,
                              void* d_out, int out_size) {
    const int*   x       = (const int*)d_in[0];
    const int*   ei      = (const int*)d_in[1];
    const int*   batch   = (const int*)d_in[2];
    const float* emb     = (const float*)d_in[3];
    const float* w1_rel  = (const float*)d_in[4];
    const float* w1_root = (const float*)d_in[5];
    const float* b1      = (const float*)d_in[6];
    const float* w2_rel  = (const float*)d_in[7];
    const float* w2_root = (const float*)d_in[8];
    const float* b2      = (const float*)d_in[9];
    const float* we_rel  = (const float*)d_in[10];
    const float* we_root = (const float*)d_in[11];
    const float* be      = (const float*)d_in[12];
    const float* wd_rel  = (const float*)d_in[13];
    const float* wd_root = (const float*)d_in[14];
    const float* bd      = (const float*)d_in[15];
    const float* w_lin   = (const float*)d_in[16];
    const float* b_lin   = (const float*)d_in[17];

    const int* src = ei;
    const int* dst = ei + N_EDGES;

    float* out    = (float*)d_out;
    float* logits = out;
    float* recon  = out + OFF_RECON;
    float* orig   = out + OFF_ORIG;

    float *h1, *bufE, *lat, *pool, *cnt;
    int *deg, *rowptr, *posn, *esrc, *part;
    cudaGetSymbolAddress((void**)&h1,    g_h1);
    cudaGetSymbolAddress((void**)&bufE,  g_enc);
    cudaGetSymbolAddress((void**)&lat,   g_lat);
    cudaGetSymbolAddress((void**)&pool,  g_pool);
    cudaGetSymbolAddress((void**)&cnt,   g_cnt);
    cudaGetSymbolAddress((void**)&deg,   g_deg);
    cudaGetSymbolAddress((void**)&rowptr,g_rowptr);
    cudaGetSymbolAddress((void**)&posn,  g_posn);
    cudaGetSymbolAddress((void**)&esrc,  g_esrc);
    cudaGetSymbolAddress((void**)&part,  g_part);

    __nv_bfloat16 *h1h,*h1l,*a1h,*a1l,*oh,*ol,*lath,*latl,*aggh,*aggl;
    __nv_bfloat16 *w2rh,*w2rl,*w2oh,*w2ol,*wcath,*wcatl,*wdrh,*wdrl,*wdoh,*wdol;
    cudaGetSymbolAddress((void**)&h1h, g_h1h);   cudaGetSymbolAddress((void**)&h1l, g_h1l);
    cudaGetSymbolAddress((void**)&a1h, g_a1h);   cudaGetSymbolAddress((void**)&a1l, g_a1l);
    cudaGetSymbolAddress((void**)&oh,  g_oh);    cudaGetSymbolAddress((void**)&ol,  g_ol);
    cudaGetSymbolAddress((void**)&lath,g_lath);  cudaGetSymbolAddress((void**)&latl,g_latl);
    cudaGetSymbolAddress((void**)&aggh,g_aggh);  cudaGetSymbolAddress((void**)&aggl,g_aggl);
    cudaGetSymbolAddress((void**)&w2rh,g_w2r_h); cudaGetSymbolAddress((void**)&w2rl,g_w2r_l);
    cudaGetSymbolAddress((void**)&w2oh,g_w2o_h); cudaGetSymbolAddress((void**)&w2ol,g_w2o_l);
    cudaGetSymbolAddress((void**)&wcath,g_wcat_h); cudaGetSymbolAddress((void**)&wcatl,g_wcat_l);
    cudaGetSymbolAddress((void**)&wdrh,g_wdr_h); cudaGetSymbolAddress((void**)&wdrl,g_wdr_l);
    cudaGetSymbolAddress((void**)&wdoh,g_wdo_h); cudaGetSymbolAddress((void**)&wdol,g_wdo_l);

    cudaFuncSetAttribute(gemm_split, cudaFuncAttributeMaxDynamicSharedMemorySize, GEMM_SMEM);

    // CSR build (fast 3-kernel scan)
    zero_misc<<<256, 256>>>(deg, pool, cnt);
    hist_kernel<<<(N_EDGES + 255) / 256, 256>>>(dst, deg);
    scan_local<<<SCAN_BLOCKS, 1024>>>(deg, rowptr, part);
    scan_partials<<<1, 32>>>(part);
    scan_add<<<(N_NODES + 255) / 256, 256>>>(rowptr, part, posn);
    scatter_kernel<<<(N_EDGES + 255) / 256, 256>>>(src, dst, posn, esrc);

    // fused conv1
    conv1_fused<<<(N_NODES + 7) / 8, 256>>>(x, emb, rowptr, esrc,
                                            w1_rel, w1_root, b1, h1, h1h, h1l);

    // 64-wide gather (h1 -> aggr hi/lo)
    gather_h16<<<(N_NODES * 16 + 255) / 256, 256>>>(h1, a1h, a1l, rowptr, esrc);

    // w2 transposes
    {
        dim3 b(32, 8);
        transpose_split<<<dim3(1024/32, 64/32), b>>>(w2_rel,  w2rh, w2rl, 64, 1024);
        transpose_split<<<dim3(1024/32, 64/32), b>>>(w2_root, w2oh, w2ol, 64, 1024);
    }
    // conv2 GEMM -> orig (+hi/lo)
    {
        dim3 grid(1024 / 64, (N_NODES + 127) / 128);
        gemm_split<<<grid, 256, GEMM_SMEM>>>(a1h, a1l, 64, h1h, h1l, 64,
                                             w2rh, w2rl, w2oh, w2ol,
                                             nullptr, b2, orig, oh, ol, N_NODES, 1024, 1);
    }

    // we transposes -> concatenated [512][1024]
    {
        dim3 b(32, 8);
        transpose_split<<<dim3(256/32, 1024/32), b>>>(we_rel,  wcath, wcatl, 1024, 256);
        transpose_split<<<dim3(256/32, 1024/32), b>>>(we_root, wcath + 256 * 1024,
                                                      wcatl + 256 * 1024, 1024, 256);
    }
    // fused enc GEMM (N=512): bufE = [orig@we_rel | orig@we_root]
    {
        dim3 grid(512 / 64, (N_NODES + 127) / 128);
        gemm_split<<<grid, 256, GEMM_SMEM>>>(oh, ol, 1024, nullptr, nullptr, 0,
                                             wcath, wcatl, nullptr, nullptr,
                                             nullptr, nullptr, bufE, nullptr, nullptr,
                                             N_NODES, 512, 0);
    }
    // enc finish: gather rel cols + root + bias + leaky -> lat (+hi/lo)
    gather_enc_fin<<<(N_NODES * 64 + 255) / 256, 256>>>(bufE, be, lat, lath, latl,
                                                        rowptr, esrc);

    // 256-wide gather lat -> agg hi/lo
    gather_c256<<<(N_NODES * 64 + 255) / 256, 256>>>(lat, aggh, aggl, rowptr, esrc);

    // pool + logits
    pool_kernel<<<(N_NODES * 64 + 255) / 256, 256>>>(lat, batch, pool);
    count_kernel<<<(N_NODES + 255) / 256, 256>>>(batch, cnt);
    logits_kernel<<<N_GRAPHS, 32>>>(pool, cnt, w_lin, b_lin, logits);

    // wd transposes
    {
        dim3 b(32, 8);
        transpose_split<<<dim3(1024/32, 256/32), b>>>(wd_rel,  wdrh, wdrl, 256, 1024);
        transpose_split<<<dim3(1024/32, 256/32), b>>>(wd_root, wdoh, wdol, 256, 1024);
    }
    // dec GEMM -> recon
    {
        dim3 grid(1024 / 64, (N_NODES + 127) / 128);
        gemm_split<<<grid, 256, GEMM_SMEM>>>(aggh, aggl, 256, lath, latl, 256,
                                             wdrh, wdrl, wdoh, wdol,
                                             nullptr, bd, recon, nullptr, nullptr,
                                             N_NODES, 1024, 1);
    }
}

// round 9
// speedup vs baseline: 2.6533x; 1.0799x over previous
#include <cuda_runtime.h>
#include <cuda_bf16.h>
#include <cstdint>

#define N_NODES 50000
#define M_PAD   50048
#define N_EDGES 800000
#define N_GRAPHS 256
#define OUT_CLS 7
#define NEG_SLOPE 0.01f

// Output layout: logits [256*7] | reconstructed [N*1024] | original [N*1024]
#define OFF_RECON (N_GRAPHS * OUT_CLS)
#define OFF_ORIG  (OFF_RECON + N_NODES * 1024)

// ---------------- fp32 scratch ----------------------------------------------------
__device__ float g_h1   [N_NODES * 64];
__device__ float g_enc  [N_NODES * 512];   // fused enc GEMM output: [rel(256) | root(256)]
__device__ float g_lat  [N_NODES * 256];
__device__ float g_pool [N_GRAPHS * 256];
__device__ float g_cnt  [N_GRAPHS];

// ---------------- CSR scratch -----------------------------------------------------
#define SCAN_BLOCKS ((N_NODES + 1023) / 1024)
__device__ int g_deg   [N_NODES];
__device__ int g_rowptr[N_NODES + 1];
__device__ int g_posn  [N_NODES];
__device__ int g_esrc  [N_EDGES];
__device__ int g_part  [SCAN_BLOCKS + 1];

// ---------------- pre-split bf16 scratch (hi/lo), padded rows ---------------------
__device__ __nv_bfloat16 g_h1h [M_PAD * 64];
__device__ __nv_bfloat16 g_h1l [M_PAD * 64];
__device__ __nv_bfloat16 g_a1h [M_PAD * 64];
__device__ __nv_bfloat16 g_a1l [M_PAD * 64];
__device__ __nv_bfloat16 g_oh  [M_PAD * 1024];
__device__ __nv_bfloat16 g_ol  [M_PAD * 1024];
__device__ __nv_bfloat16 g_lath[M_PAD * 256];
__device__ __nv_bfloat16 g_latl[M_PAD * 256];
__device__ __nv_bfloat16 g_aggh[M_PAD * 256];
__device__ __nv_bfloat16 g_aggl[M_PAD * 256];
// transposed weights [N][K] hi/lo
__device__ __nv_bfloat16 g_w2r_h[1024 * 64],  g_w2r_l[1024 * 64];
__device__ __nv_bfloat16 g_w2o_h[1024 * 64],  g_w2o_l[1024 * 64];
__device__ __nv_bfloat16 g_wcat_h[512 * 1024], g_wcat_l[512 * 1024];  // [we_rel ; we_root]
__device__ __nv_bfloat16 g_wdr_h[1024 * 256], g_wdr_l[1024 * 256];
__device__ __nv_bfloat16 g_wdo_h[1024 * 256], g_wdo_l[1024 * 256];

// ---------------- helpers ---------------------------------------------------------
__device__ __forceinline__ void red_add_v4(float4* addr, float4 v) {
    asm volatile("red.global.add.v4.f32 [%0], {%1, %2, %3, %4};"
                 :: "l"(addr), "f"(v.x), "f"(v.y), "f"(v.z), "f"(v.w) : "memory");
}
__device__ __forceinline__ float lrelu(float v) { return v >= 0.f ? v : NEG_SLOPE * v; }

__device__ __forceinline__ uint32_t pack_bf16(float x, float y) {
    __nv_bfloat162 t = __floats2bfloat162_rn(x, y);
    return *reinterpret_cast<uint32_t*>(&t);
}
__device__ __forceinline__ float bf_round(float v) {
    return __bfloat162float(__float2bfloat16(v));
}

__device__ __forceinline__ void mma_bf16(float* d, const uint32_t* a, const uint32_t* b) {
    asm volatile(
        "mma.sync.aligned.m16n8k16.row.col.f32.bf16.bf16.f32 "
        "{%0,%1,%2,%3}, {%4,%5,%6,%7}, {%8,%9}, {%0,%1,%2,%3};"
        : "+f"(d[0]), "+f"(d[1]), "+f"(d[2]), "+f"(d[3])
        : "r"(a[0]), "r"(a[1]), "r"(a[2]), "r"(a[3]), "r"(b[0]), "r"(b[1]));
}

__device__ __forceinline__ void ldsm4(uint32_t* r, uint32_t addr) {
    asm volatile("ldmatrix.sync.aligned.m8n8.x4.shared.b16 {%0,%1,%2,%3}, [%4];"
                 : "=r"(r[0]), "=r"(r[1]), "=r"(r[2]), "=r"(r[3]) : "r"(addr));
}

__device__ __forceinline__ void cp16(uint32_t dst, const void* src) {
    asm volatile("cp.async.cg.shared.global [%0], [%1], 16;" :: "r"(dst), "l"(src));
}
__device__ __forceinline__ void cp_commit() { asm volatile("cp.async.commit_group;"); }
template <int Np> __device__ __forceinline__ void cp_wait() {
    asm volatile("cp.async.wait_group %0;" :: "n"(Np));
}

// ---------------- CSR build -------------------------------------------------------
__global__ void zero_misc(int* deg, float* pool, float* cnt) {
    int i = blockIdx.x * blockDim.x + threadIdx.x;
    if (i < N_NODES) deg[i] = 0;
    if (i < N_GRAPHS * 256) pool[i] = 0.f;
    if (i < N_GRAPHS) cnt[i] = 0.f;
}

__global__ void hist_kernel(const int* __restrict__ dst, int* __restrict__ deg) {
    int e = blockIdx.x * blockDim.x + threadIdx.x;
    if (e < N_EDGES) atomicAdd(&deg[dst[e]], 1);
}

// 3-kernel scan: block-local, partials, add
__global__ void scan_local(const int* __restrict__ deg, int* __restrict__ rowptr,
                           int* __restrict__ part) {
    __shared__ int sh[1024];
    int tid = threadIdx.x;
    int i = blockIdx.x * 1024 + tid;
    int v = (i < N_NODES) ? deg[i] : 0;
    sh[tid] = v;
    __syncthreads();
#pragma unroll
    for (int off = 1; off < 1024; off <<= 1) {
        int t = (tid >= off) ? sh[tid - off] : 0;
        __syncthreads();
        sh[tid] += t;
        __syncthreads();
    }
    if (i < N_NODES) rowptr[i] = sh[tid] - v;   // local exclusive
    if (tid == 1023) part[blockIdx.x] = sh[1023];
}

__global__ void scan_partials(int* __restrict__ part) {
    if (threadIdx.x == 0) {
        int run = 0;
        for (int j = 0; j < SCAN_BLOCKS; j++) {
            int v = part[j];
            part[j] = run;
            run += v;
        }
        part[SCAN_BLOCKS] = run;
    }
}

__global__ void scan_add(int* __restrict__ rowptr, const int* __restrict__ part,
                         int* __restrict__ posn) {
    int i = blockIdx.x * blockDim.x + threadIdx.x;
    if (i < N_NODES) {
        int r = rowptr[i] + part[i >> 10];
        rowptr[i] = r;
        posn[i] = r;
    }
    if (i == 0) rowptr[N_NODES] = part[SCAN_BLOCKS];
}

__global__ void scatter_kernel(const int* __restrict__ src, const int* __restrict__ dst,
                               int* __restrict__ posn, int* __restrict__ esrc) {
    int e = blockIdx.x * blockDim.x + threadIdx.x;
    if (e < N_EDGES) {
        int idx = atomicAdd(&posn[dst[e]], 1);
        esrc[idx] = src[e];
    }
}

// ---------------- fused conv1: embed + 3-wide gather + linear + split -------------
__global__ void __launch_bounds__(256)
conv1_fused(const int* __restrict__ x, const float* __restrict__ emb,
            const int* __restrict__ rowptr, const int* __restrict__ esrc,
            const float* __restrict__ w_rel, const float* __restrict__ w_root,
            const float* __restrict__ b,
            float* __restrict__ h1, __nv_bfloat16* __restrict__ h1h,
            __nv_bfloat16* __restrict__ h1l) {
    __shared__ float swr[192], swo[192], sb[64];
    int tid = threadIdx.x;
    if (tid < 192) { swr[tid] = w_rel[tid]; swo[tid] = w_root[tid]; }
    if (tid < 64) sb[tid] = b[tid];
    __syncthreads();
    int node = blockIdx.x * 8 + (tid >> 5);
    int lane = tid & 31;
    if (node >= N_NODES) return;
    int bg = rowptr[node], en = rowptr[node + 1];
    float a0 = 0.f, a1 = 0.f, a2 = 0.f;
    for (int j = bg + lane; j < en; j += 32) {
        int s = esrc[j];
        int lab = x[s];
        a0 += emb[lab * 3 + 0];
        a1 += emb[lab * 3 + 1];
        a2 += emb[lab * 3 + 2];
    }
#pragma unroll
    for (int o = 16; o; o >>= 1) {
        a0 += __shfl_xor_sync(0xffffffff, a0, o);
        a1 += __shfl_xor_sync(0xffffffff, a1, o);
        a2 += __shfl_xor_sync(0xffffffff, a2, o);
    }
    int labn = x[node];
    float x0 = emb[labn * 3 + 0], x1 = emb[labn * 3 + 1], x2 = emb[labn * 3 + 2];
    int c = lane * 2;
    float v0 = sb[c]   + a0*swr[c]   + a1*swr[64+c]   + a2*swr[128+c]
                       + x0*swo[c]   + x1*swo[64+c]   + x2*swo[128+c];
    float v1 = sb[c+1] + a0*swr[c+1] + a1*swr[64+c+1] + a2*swr[128+c+1]
                       + x0*swo[c+1] + x1*swo[64+c+1] + x2*swo[128+c+1];
    v0 = lrelu(v0); v1 = lrelu(v1);
    *reinterpret_cast<float2*>(h1 + (size_t)node * 64 + c) = make_float2(v0, v1);
    float h0f = bf_round(v0), h1f = bf_round(v1);
    reinterpret_cast<uint32_t*>(h1h)[node * 32 + lane] = pack_bf16(h0f, h1f);
    reinterpret_cast<uint32_t*>(h1l)[node * 32 + lane] = pack_bf16(v0 - h0f, v1 - h1f);
}

// ---------------- CSR gather, C=64 -> hi/lo bf16 only -----------------------------
__global__ void gather_h16(const float* __restrict__ xin,
                           __nv_bfloat16* __restrict__ oh, __nv_bfloat16* __restrict__ ol,
                           const int* __restrict__ rowptr, const int* __restrict__ esrc) {
    int i = blockIdx.x * blockDim.x + threadIdx.x;
    if (i >= N_NODES * 16) return;
    int node = i >> 4, c = i & 15;
    int bg = rowptr[node], en = rowptr[node + 1];
    float4 acc = make_float4(0.f, 0.f, 0.f, 0.f);
    for (int j = bg; j < en; j++) {
        int s = esrc[j];
        float4 v = reinterpret_cast<const float4*>(xin)[(size_t)s * 16 + c];
        acc.x += v.x; acc.y += v.y; acc.z += v.z; acc.w += v.w;
    }
    float hx = bf_round(acc.x), hy = bf_round(acc.y), hz = bf_round(acc.z), hw = bf_round(acc.w);
    uint32_t* oh32 = reinterpret_cast<uint32_t*>(oh);
    uint32_t* ol32 = reinterpret_cast<uint32_t*>(ol);
    oh32[node * 32 + c * 2]     = pack_bf16(hx, hy);
    oh32[node * 32 + c * 2 + 1] = pack_bf16(hz, hw);
    ol32[node * 32 + c * 2]     = pack_bf16(acc.x - hx, acc.y - hy);
    ol32[node * 32 + c * 2 + 1] = pack_bf16(acc.z - hz, acc.w - hw);
}

// ---------------- enc finish: gather rel cols + root cols + bias + leaky + split --
__global__ void gather_enc_fin(const float* __restrict__ bufE, const float* __restrict__ be,
                               float* __restrict__ lat, __nv_bfloat16* __restrict__ lath,
                               __nv_bfloat16* __restrict__ latl,
                               const int* __restrict__ rowptr, const int* __restrict__ esrc) {
    int i = blockIdx.x * blockDim.x + threadIdx.x;
    if (i >= N_NODES * 64) return;
    int node = i >> 6, c = i & 63;
    int bg = rowptr[node], en = rowptr[node + 1];
    float4 acc = make_float4(0.f, 0.f, 0.f, 0.f);
    for (int j = bg; j < en; j++) {
        int s = esrc[j];
        float4 v = reinterpret_cast<const float4*>(bufE)[(size_t)s * 128 + c];
        acc.x += v.x; acc.y += v.y; acc.z += v.z; acc.w += v.w;
    }
    float4 rt = reinterpret_cast<const float4*>(bufE)[(size_t)node * 128 + 64 + c];
    float4 b4 = reinterpret_cast<const float4*>(be)[c];
    float v0 = lrelu(acc.x + rt.x + b4.x);
    float v1 = lrelu(acc.y + rt.y + b4.y);
    float v2 = lrelu(acc.z + rt.z + b4.z);
    float v3 = lrelu(acc.w + rt.w + b4.w);
    reinterpret_cast<float4*>(lat)[(size_t)node * 64 + c] = make_float4(v0, v1, v2, v3);
    float h0 = bf_round(v0), h1 = bf_round(v1), h2 = bf_round(v2), h3 = bf_round(v3);
    uint32_t* oh32 = reinterpret_cast<uint32_t*>(lath);
    uint32_t* ol32 = reinterpret_cast<uint32_t*>(latl);
    oh32[node * 128 + c * 2]     = pack_bf16(h0, h1);
    oh32[node * 128 + c * 2 + 1] = pack_bf16(h2, h3);
    ol32[node * 128 + c * 2]     = pack_bf16(v0 - h0, v1 - h1);
    ol32[node * 128 + c * 2 + 1] = pack_bf16(v2 - h2, v3 - h3);
}

// ---------------- CSR gather, C=256 -> hi/lo (dec input) --------------------------
__global__ void gather_c256(const float* __restrict__ xin,
                            __nv_bfloat16* __restrict__ oh, __nv_bfloat16* __restrict__ ol,
                            const int* __restrict__ rowptr, const int* __restrict__ esrc) {
    int i = blockIdx.x * blockDim.x + threadIdx.x;
    if (i >= N_NODES * 64) return;
    int node = i >> 6, c = i & 63;
    int bg = rowptr[node], en = rowptr[node + 1];
    float4 acc = make_float4(0.f, 0.f, 0.f, 0.f);
    for (int j = bg; j < en; j++) {
        int s = esrc[j];
        float4 v = reinterpret_cast<const float4*>(xin)[(size_t)s * 64 + c];
        acc.x += v.x; acc.y += v.y; acc.z += v.z; acc.w += v.w;
    }
    float hx = bf_round(acc.x), hy = bf_round(acc.y), hz = bf_round(acc.z), hw = bf_round(acc.w);
    uint32_t* oh32 = reinterpret_cast<uint32_t*>(oh);
    uint32_t* ol32 = reinterpret_cast<uint32_t*>(ol);
    oh32[node * 128 + c * 2]     = pack_bf16(hx, hy);
    oh32[node * 128 + c * 2 + 1] = pack_bf16(hz, hw);
    ol32[node * 128 + c * 2]     = pack_bf16(acc.x - hx, acc.y - hy);
    ol32[node * 128 + c * 2 + 1] = pack_bf16(acc.z - hz, acc.w - hw);
}

// ---------------- transpose + hi/lo split for weights: [K][N] -> [N][K] -----------
__global__ void transpose_split(const float* __restrict__ W, __nv_bfloat16* __restrict__ oh,
                                __nv_bfloat16* __restrict__ ol, int K, int N) {
    __shared__ float tile[32][33];
    int n0 = blockIdx.x * 32, k0 = blockIdx.y * 32;
    int tx = threadIdx.x, ty = threadIdx.y;
#pragma unroll
    for (int j = 0; j < 32; j += 8)
        tile[ty + j][tx] = W[(size_t)(k0 + ty + j) * N + n0 + tx];
    __syncthreads();
#pragma unroll
    for (int j = 0; j < 32; j += 8) {
        float v = tile[tx][ty + j];
        float h = bf_round(v);
        size_t o = (size_t)(n0 + ty + j) * K + k0 + tx;
        oh[o] = __float2bfloat16(h);
        ol[o] = __float2bfloat16(v - h);
    }
}

// ---------------- cp.async double-buffered pre-split bf16 GEMM --------------------
// Block tile 128x128, 512 threads (16 warps, 32x32 warp tiles), BK=32.
#define A_TILE_B 10240           // 128 rows * 80 B
#define OFF_AL   10240
#define OFF_BH   20480
#define OFF_BL   30720
#define STAGE_B  40960
#define GEMM_SMEM (2 * STAGE_B)

__global__ void __launch_bounds__(512, 2)
gemm_split(const __nv_bfloat16* __restrict__ A1h, const __nv_bfloat16* __restrict__ A1l, int K1,
           const __nv_bfloat16* __restrict__ A2h, const __nv_bfloat16* __restrict__ A2l, int K2,
           const __nv_bfloat16* __restrict__ W1h, const __nv_bfloat16* __restrict__ W1l,
           const __nv_bfloat16* __restrict__ W2h, const __nv_bfloat16* __restrict__ W2l,
           const float* __restrict__ add, const float* __restrict__ bias,
           float* __restrict__ C, __nv_bfloat16* __restrict__ Ch,
           __nv_bfloat16* __restrict__ Cl, int M, int N, int leaky) {
    extern __shared__ __align__(16) char smc[];
    int tid = threadIdx.x;
    int lane = tid & 31, wid = tid >> 5;
    int wm = (wid & 3) * 32;        // 4 warp-rows over 128
    int wn = (wid >> 2) * 32;       // 4 warp-cols over 128
    int brow = blockIdx.y * 128;
    int bcol = blockIdx.x * 128;
    uint32_t sbase = (uint32_t)__cvta_generic_to_shared(smc);

    float acc[2][4][4];
#pragma unroll
    for (int mt = 0; mt < 2; mt++)
#pragma unroll
        for (int nt = 0; nt < 4; nt++)
#pragma unroll
            for (int r = 0; r < 4; r++) acc[mt][nt][r] = 0.f;

    int T1 = A1h ? (K1 / 32) : 0;
    int T2 = A2h ? (K2 / 32) : 0;
    int T = T1 + T2;

    int srow = tid >> 2;            // 0..127
    int sc   = tid & 3;             // 16B chunk

    // per-lane ldmatrix base offsets
    int lr = lane & 7;
    uint32_t a_off[2];
#pragma unroll
    for (int mt = 0; mt < 2; mt++) {
        int row = wm + mt * 16 + ((lane >> 3) & 1) * 8 + lr;
        a_off[mt] = row * 80 + (lane >> 4) * 16;
    }
    uint32_t b_off[2];
#pragma unroll
    for (int p = 0; p < 2; p++) {
        int n = wn + p * 16 + (lane >> 4) * 8 + lr;
        b_off[p] = n * 80 + ((lane >> 3) & 1) * 16;
    }

    auto issue = [&](int t, int stage) {
        const __nv_bfloat16 *Ah, *Al, *Wh, *Wl; int K, k0;
        if (t < T1) { Ah = A1h; Al = A1l; Wh = W1h; Wl = W1l; K = K1; k0 = t * 32; }
        else        { Ah = A2h; Al = A2l; Wh = W2h; Wl = W2l; K = K2; k0 = (t - T1) * 32; }
        uint32_t sb = sbase + stage * STAGE_B;
        size_t go = (size_t)(brow + srow) * K + k0 + sc * 8;
        cp16(sb + srow * 80 + sc * 16, Ah + go);
        cp16(sb + OFF_AL + srow * 80 + sc * 16, Al + go);
        size_t gb = (size_t)(bcol + srow) * K + k0 + sc * 8;
        cp16(sb + OFF_BH + srow * 80 + sc * 16, Wh + gb);
        cp16(sb + OFF_BL + srow * 80 + sc * 16, Wl + gb);
        cp_commit();
    };

    auto compute = [&](int stage) {
        uint32_t sb = sbase + stage * STAGE_B;
#pragma unroll
        for (int ks = 0; ks < 2; ks++) {
            uint32_t koff = ks * 32;
            uint32_t aH[2][4], aL[2][4], bH[4][2], bL[4][2];
#pragma unroll
            for (int mt = 0; mt < 2; mt++) {
                ldsm4(aH[mt], sb + a_off[mt] + koff);
                ldsm4(aL[mt], sb + OFF_AL + a_off[mt] + koff);
            }
#pragma unroll
            for (int p = 0; p < 2; p++) {
                ldsm4(&bH[p * 2][0], sb + OFF_BH + b_off[p] + koff);
                ldsm4(&bL[p * 2][0], sb + OFF_BL + b_off[p] + koff);
            }
#pragma unroll
            for (int mt = 0; mt < 2; mt++)
#pragma unroll
                for (int nt = 0; nt < 4; nt++) {
                    mma_bf16(acc[mt][nt], aH[mt], bH[nt]);
                    mma_bf16(acc[mt][nt], aH[mt], bL[nt]);
                    mma_bf16(acc[mt][nt], aL[mt], bH[nt]);
                }
        }
    };

    // ---- single-sync pipelined main loop ----
    issue(0, 0);
#pragma unroll 1
    for (int t = 0; t < T; t++) {
        int cur = t & 1;
        cp_wait<0>();
        __syncthreads();
        if (t + 1 < T) issue(t + 1, 1 - cur);
        compute(cur);
    }

    // ---- epilogue ----
#pragma unroll
    for (int mt = 0; mt < 2; mt++) {
#pragma unroll
        for (int nt = 0; nt < 4; nt++) {
            int r0 = brow + wm + mt * 16 + (lane >> 2);
            int c  = bcol + wn + nt * 8 + (lane & 3) * 2;
#pragma unroll
            for (int half = 0; half < 2; half++) {
                int row = r0 + half * 8;
                if (row >= M) continue;
                float v0 = acc[mt][nt][half * 2 + 0];
                float v1 = acc[mt][nt][half * 2 + 1];
                if (add) {
                    const float2 a2 = *reinterpret_cast<const float2*>(add + (size_t)row * N + c);
                    v0 += a2.x; v1 += a2.y;
                }
                if (bias) {
                    const float2 b2 = *reinterpret_cast<const float2*>(bias + c);
                    v0 += b2.x; v1 += b2.y;
                }
                if (leaky) { v0 = lrelu(v0); v1 = lrelu(v1); }
                *reinterpret_cast<float2*>(C + (size_t)row * N + c) = make_float2(v0, v1);
                if (Ch) {
                    float h0 = bf_round(v0), h1f = bf_round(v1);
                    *reinterpret_cast<uint32_t*>(Ch + (size_t)row * N + c) = pack_bf16(h0, h1f);
                    *reinterpret_cast<uint32_t*>(Cl + (size_t)row * N + c) = pack_bf16(v0 - h0, v1 - h1f);
                }
            }
        }
    }
}

// ---------------- pooling + logits ------------------------------------------------
__global__ void pool_kernel(const float* __restrict__ latent, const int* __restrict__ batch,
                            float* __restrict__ pooled) {
    int i = blockIdx.x * blockDim.x + threadIdx.x;
    if (i >= N_NODES * 64) return;
    int node = i >> 6, c = i & 63;
    int g = batch[node];
    float4 v = reinterpret_cast<const float4*>(latent)[(size_t)node * 64 + c];
    red_add_v4(reinterpret_cast<float4*>(pooled) + (size_t)g * 64 + c, v);
}

__global__ void count_kernel(const int* __restrict__ batch, float* __restrict__ counts) {
    int i = blockIdx.x * blockDim.x + threadIdx.x;
    if (i < N_NODES) atomicAdd(&counts[batch[i]], 1.0f);
}

__global__ void logits_kernel(const float* __restrict__ pooled, const float* __restrict__ counts,
                              const float* __restrict__ w_lin, const float* __restrict__ b_lin,
                              float* __restrict__ out) {
    int g = blockIdx.x;
    int o = threadIdx.x;
    if (o >= OUT_CLS) return;
    float inv = 1.0f / fmaxf(counts[g], 1.0f);
    float s = 0.f;
    const float* pr = pooled + g * 256;
    for (int k = 0; k < 256; k++) s += pr[k] * w_lin[k * OUT_CLS + o];
    out[g * OUT_CLS + o] = s * inv + b_lin[o];
}

// ---------------- host launch -----------------------------------------------------
extern "C" void kernel_launch(void* const* d_in, const int* in_sizes, int n_in,
                              void* d_out, int out_size) {
    const int*   x       = (const int*)d_in[0];
    const int*   ei      = (const int*)d_in[1];
    const int*   batch   = (const int*)d_in[2];
    const float* emb     = (const float*)d_in[3];
    const float* w1_rel  = (const float*)d_in[4];
    const float* w1_root = (const float*)d_in[5];
    const float* b1      = (const float*)d_in[6];
    const float* w2_rel  = (const float*)d_in[7];
    const float* w2_root = (const float*)d_in[8];
    const float* b2      = (const float*)d_in[9];
    const float* we_rel  = (const float*)d_in[10];
    const float* we_root = (const float*)d_in[11];
    const float* be      = (const float*)d_in[12];
    const float* wd_rel  = (const float*)d_in[13];
    const float* wd_root = (const float*)d_in[14];
    const float* bd      = (const float*)d_in[15];
    const float* w_lin   = (const float*)d_in[16];
    const float* b_lin   = (const float*)d_in[17];

    const int* src = ei;
    const int* dst = ei + N_EDGES;

    float* out    = (float*)d_out;
    float* logits = out;
    float* recon  = out + OFF_RECON;
    float* orig   = out + OFF_ORIG;

    float *h1, *bufE, *lat, *pool, *cnt;
    int *deg, *rowptr, *posn, *esrc, *part;
    cudaGetSymbolAddress((void**)&h1,    g_h1);
    cudaGetSymbolAddress((void**)&bufE,  g_enc);
    cudaGetSymbolAddress((void**)&lat,   g_lat);
    cudaGetSymbolAddress((void**)&pool,  g_pool);
    cudaGetSymbolAddress((void**)&cnt,   g_cnt);
    cudaGetSymbolAddress((void**)&deg,   g_deg);
    cudaGetSymbolAddress((void**)&rowptr,g_rowptr);
    cudaGetSymbolAddress((void**)&posn,  g_posn);
    cudaGetSymbolAddress((void**)&esrc,  g_esrc);
    cudaGetSymbolAddress((void**)&part,  g_part);

    __nv_bfloat16 *h1h,*h1l,*a1h,*a1l,*oh,*ol,*lath,*latl,*aggh,*aggl;
    __nv_bfloat16 *w2rh,*w2rl,*w2oh,*w2ol,*wcath,*wcatl,*wdrh,*wdrl,*wdoh,*wdol;
    cudaGetSymbolAddress((void**)&h1h, g_h1h);   cudaGetSymbolAddress((void**)&h1l, g_h1l);
    cudaGetSymbolAddress((void**)&a1h, g_a1h);   cudaGetSymbolAddress((void**)&a1l, g_a1l);
    cudaGetSymbolAddress((void**)&oh,  g_oh);    cudaGetSymbolAddress((void**)&ol,  g_ol);
    cudaGetSymbolAddress((void**)&lath,g_lath);  cudaGetSymbolAddress((void**)&latl,g_latl);
    cudaGetSymbolAddress((void**)&aggh,g_aggh);  cudaGetSymbolAddress((void**)&aggl,g_aggl);
    cudaGetSymbolAddress((void**)&w2rh,g_w2r_h); cudaGetSymbolAddress((void**)&w2rl,g_w2r_l);
    cudaGetSymbolAddress((void**)&w2oh,g_w2o_h); cudaGetSymbolAddress((void**)&w2ol,g_w2o_l);
    cudaGetSymbolAddress((void**)&wcath,g_wcat_h); cudaGetSymbolAddress((void**)&wcatl,g_wcat_l);
    cudaGetSymbolAddress((void**)&wdrh,g_wdr_h); cudaGetSymbolAddress((void**)&wdrl,g_wdr_l);
    cudaGetSymbolAddress((void**)&wdoh,g_wdo_h); cudaGetSymbolAddress((void**)&wdol,g_wdo_l);

    cudaFuncSetAttribute(gemm_split, cudaFuncAttributeMaxDynamicSharedMemorySize, GEMM_SMEM);

    // CSR build (fast 3-kernel scan)
    zero_misc<<<256, 256>>>(deg, pool, cnt);
    hist_kernel<<<(N_EDGES + 255) / 256, 256>>>(dst, deg);
    scan_local<<<SCAN_BLOCKS, 1024>>>(deg, rowptr, part);
    scan_partials<<<1, 32>>>(part);
    scan_add<<<(N_NODES + 255) / 256, 256>>>(rowptr, part, posn);
    scatter_kernel<<<(N_EDGES + 255) / 256, 256>>>(src, dst, posn, esrc);

    // fused conv1
    conv1_fused<<<(N_NODES + 7) / 8, 256>>>(x, emb, rowptr, esrc,
                                            w1_rel, w1_root, b1, h1, h1h, h1l);

    // 64-wide gather (h1 -> aggr hi/lo)
    gather_h16<<<(N_NODES * 16 + 255) / 256, 256>>>(h1, a1h, a1l, rowptr, esrc);

    // w2 transposes
    {
        dim3 b(32, 8);
        transpose_split<<<dim3(1024/32, 64/32), b>>>(w2_rel,  w2rh, w2rl, 64, 1024);
        transpose_split<<<dim3(1024/32, 64/32), b>>>(w2_root, w2oh, w2ol, 64, 1024);
    }
    // conv2 GEMM -> orig (+hi/lo)
    {
        dim3 grid(1024 / 128, (N_NODES + 127) / 128);
        gemm_split<<<grid, 512, GEMM_SMEM>>>(a1h, a1l, 64, h1h, h1l, 64,
                                             w2rh, w2rl, w2oh, w2ol,
                                             nullptr, b2, orig, oh, ol, N_NODES, 1024, 1);
    }

    // we transposes -> concatenated [512][1024]
    {
        dim3 b(32, 8);
        transpose_split<<<dim3(256/32, 1024/32), b>>>(we_rel,  wcath, wcatl, 1024, 256);
        transpose_split<<<dim3(256/32, 1024/32), b>>>(we_root, wcath + 256 * 1024,
                                                      wcatl + 256 * 1024, 1024, 256);
    }
    // fused enc GEMM (N=512): bufE = [orig@we_rel | orig@we_root]
    {
        dim3 grid(512 / 128, (N_NODES + 127) / 128);
        gemm_split<<<grid, 512, GEMM_SMEM>>>(oh, ol, 1024, nullptr, nullptr, 0,
                                             wcath, wcatl, nullptr, nullptr,
                                             nullptr, nullptr, bufE, nullptr, nullptr,
                                             N_NODES, 512, 0);
    }
    // enc finish: gather rel cols + root + bias + leaky -> lat (+hi/lo)
    gather_enc_fin<<<(N_NODES * 64 + 255) / 256, 256>>>(bufE, be, lat, lath, latl,
                                                        rowptr, esrc);

    // 256-wide gather lat -> agg hi/lo
    gather_c256<<<(N_NODES * 64 + 255) / 256, 256>>>(lat, aggh, aggl, rowptr, esrc);

    // pool + logits
    pool_kernel<<<(N_NODES * 64 + 255) / 256, 256>>>(lat, batch, pool);
    count_kernel<<<(N_NODES + 255) / 256, 256>>>(batch, cnt);
    logits_kernel<<<N_GRAPHS, 32>>>(pool, cnt, w_lin, b_lin, logits);

    // wd transposes
    {
        dim3 b(32, 8);
        transpose_split<<<dim3(1024/32, 256/32), b>>>(wd_rel,  wdrh, wdrl, 256, 1024);
        transpose_split<<<dim3(1024/32, 256/32), b>>>(wd_root, wdoh, wdol, 256, 1024);
    }
    // dec GEMM -> recon
    {
        dim3 grid(1024 / 128, (N_NODES + 127) / 128);
        gemm_split<<<grid, 512, GEMM_SMEM>>>(aggh, aggl, 256, lath, latl, 256,
                                             wdrh, wdrl, wdoh, wdol,
                                             nullptr, bd, recon, nullptr, nullptr,
                                             N_NODES, 1024, 1);
    }
}

// round 10
// speedup vs baseline: 2.7061x; 1.0199x over previous
#include <cuda_runtime.h>
#include <cuda_bf16.h>
#include <cstdint>

#define N_NODES 50000
#define M_PAD   50048
#define N_EDGES 800000
#define N_GRAPHS 256
#define OUT_CLS 7
#define NEG_SLOPE 0.01f

// Output layout: logits [256*7] | reconstructed [N*1024] | original [N*1024]
#define OFF_RECON (N_GRAPHS * OUT_CLS)
#define OFF_ORIG  (OFF_RECON + N_NODES * 1024)

// ---------------- fp32 scratch ----------------------------------------------------
__device__ float g_h1   [N_NODES * 64];
__device__ float g_enc  [N_NODES * 512];   // fused enc GEMM output: [rel(256) | root(256)]
__device__ float g_lat  [N_NODES * 256];
__device__ float g_pool [N_GRAPHS * 256];
__device__ float g_cnt  [N_GRAPHS];

// ---------------- CSR scratch -----------------------------------------------------
#define SCAN_BLOCKS ((N_NODES + 1023) / 1024)
__device__ int g_deg   [N_NODES];
__device__ int g_rowptr[N_NODES + 1];
__device__ int g_posn  [N_NODES];
__device__ int g_esrc  [N_EDGES];
__device__ int g_part  [SCAN_BLOCKS + 1];

// ---------------- pre-split bf16 scratch (hi/lo), padded rows ---------------------
__device__ __nv_bfloat16 g_h1h [M_PAD * 64];
__device__ __nv_bfloat16 g_h1l [M_PAD * 64];
__device__ __nv_bfloat16 g_a1h [M_PAD * 64];
__device__ __nv_bfloat16 g_a1l [M_PAD * 64];
__device__ __nv_bfloat16 g_oh  [M_PAD * 1024];
__device__ __nv_bfloat16 g_ol  [M_PAD * 1024];
__device__ __nv_bfloat16 g_lath[M_PAD * 256];
__device__ __nv_bfloat16 g_latl[M_PAD * 256];
__device__ __nv_bfloat16 g_aggh[M_PAD * 256];
__device__ __nv_bfloat16 g_aggl[M_PAD * 256];
// transposed weights [N][K] hi/lo
__device__ __nv_bfloat16 g_w2r_h[1024 * 64],  g_w2r_l[1024 * 64];
__device__ __nv_bfloat16 g_w2o_h[1024 * 64],  g_w2o_l[1024 * 64];
__device__ __nv_bfloat16 g_wcat_h[512 * 1024], g_wcat_l[512 * 1024];  // [we_rel ; we_root]
__device__ __nv_bfloat16 g_wdr_h[1024 * 256], g_wdr_l[1024 * 256];
__device__ __nv_bfloat16 g_wdo_h[1024 * 256], g_wdo_l[1024 * 256];

// ---------------- helpers ---------------------------------------------------------
__device__ __forceinline__ void red_add_v4(float4* addr, float4 v) {
    asm volatile("red.global.add.v4.f32 [%0], {%1, %2, %3, %4};"
                 :: "l"(addr), "f"(v.x), "f"(v.y), "f"(v.z), "f"(v.w) : "memory");
}
__device__ __forceinline__ float lrelu(float v) { return v >= 0.f ? v : NEG_SLOPE * v; }

__device__ __forceinline__ uint32_t pack_bf16(float x, float y) {
    __nv_bfloat162 t = __floats2bfloat162_rn(x, y);
    return *reinterpret_cast<uint32_t*>(&t);
}
__device__ __forceinline__ float bf_round(float v) {
    return __bfloat162float(__float2bfloat16(v));
}

__device__ __forceinline__ void mma_bf16(float* d, const uint32_t* a, const uint32_t* b) {
    asm volatile(
        "mma.sync.aligned.m16n8k16.row.col.f32.bf16.bf16.f32 "
        "{%0,%1,%2,%3}, {%4,%5,%6,%7}, {%8,%9}, {%0,%1,%2,%3};"
        : "+f"(d[0]), "+f"(d[1]), "+f"(d[2]), "+f"(d[3])
        : "r"(a[0]), "r"(a[1]), "r"(a[2]), "r"(a[3]), "r"(b[0]), "r"(b[1]));
}

__device__ __forceinline__ void ldsm4(uint32_t* r, uint32_t addr) {
    asm volatile("ldmatrix.sync.aligned.m8n8.x4.shared.b16 {%0,%1,%2,%3}, [%4];"
                 : "=r"(r[0]), "=r"(r[1]), "=r"(r[2]), "=r"(r[3]) : "r"(addr));
}

__device__ __forceinline__ void cp16(uint32_t dst, const void* src) {
    asm volatile("cp.async.cg.shared.global [%0], [%1], 16;" :: "r"(dst), "l"(src));
}
__device__ __forceinline__ void cp_commit() { asm volatile("cp.async.commit_group;"); }
template <int Np> __device__ __forceinline__ void cp_wait() {
    asm volatile("cp.async.wait_group %0;" :: "n"(Np));
}

// ---------------- CSR build -------------------------------------------------------
__global__ void zero_misc(int* deg, float* pool, float* cnt) {
    int i = blockIdx.x * blockDim.x + threadIdx.x;
    if (i < N_NODES) deg[i] = 0;
    if (i < N_GRAPHS * 256) pool[i] = 0.f;
    if (i < N_GRAPHS) cnt[i] = 0.f;
}

// histogram of dst degrees + batch counts in one launch
__global__ void hist_kernel(const int* __restrict__ dst, int* __restrict__ deg,
                            const int* __restrict__ batch, float* __restrict__ counts) {
    int e = blockIdx.x * blockDim.x + threadIdx.x;
    if (e < N_EDGES) atomicAdd(&deg[dst[e]], 1);
    if (e < N_NODES) atomicAdd(&counts[batch[e]], 1.0f);
}

// 3-kernel scan: block-local, partials, add
__global__ void scan_local(const int* __restrict__ deg, int* __restrict__ rowptr,
                           int* __restrict__ part) {
    __shared__ int sh[1024];
    int tid = threadIdx.x;
    int i = blockIdx.x * 1024 + tid;
    int v = (i < N_NODES) ? deg[i] : 0;
    sh[tid] = v;
    __syncthreads();
#pragma unroll
    for (int off = 1; off < 1024; off <<= 1) {
        int t = (tid >= off) ? sh[tid - off] : 0;
        __syncthreads();
        sh[tid] += t;
        __syncthreads();
    }
    if (i < N_NODES) rowptr[i] = sh[tid] - v;   // local exclusive
    if (tid == 1023) part[blockIdx.x] = sh[1023];
}

__global__ void scan_partials(int* __restrict__ part) {
    __shared__ int sh[64];
    int tid = threadIdx.x;   // 64 threads
    int v = (tid < SCAN_BLOCKS) ? part[tid] : 0;
    sh[tid] = v;
    __syncthreads();
#pragma unroll
    for (int off = 1; off < 64; off <<= 1) {
        int t = (tid >= off) ? sh[tid - off] : 0;
        __syncthreads();
        sh[tid] += t;
        __syncthreads();
    }
    if (tid < SCAN_BLOCKS) part[tid] = sh[tid] - v;   // exclusive
    if (tid == 63) part[SCAN_BLOCKS] = sh[63];
}

__global__ void scan_add(int* __restrict__ rowptr, const int* __restrict__ part,
                         int* __restrict__ posn) {
    int i = blockIdx.x * blockDim.x + threadIdx.x;
    if (i < N_NODES) {
        int r = rowptr[i] + part[i >> 10];
        rowptr[i] = r;
        posn[i] = r;
    }
    if (i == 0) rowptr[N_NODES] = part[SCAN_BLOCKS];
}

__global__ void scatter_kernel(const int* __restrict__ src, const int* __restrict__ dst,
                               int* __restrict__ posn, int* __restrict__ esrc) {
    int e = blockIdx.x * blockDim.x + threadIdx.x;
    if (e < N_EDGES) {
        int idx = atomicAdd(&posn[dst[e]], 1);
        esrc[idx] = src[e];
    }
}

// ---------------- fused conv1: embed + 3-wide gather + linear + split -------------
__global__ void __launch_bounds__(256)
conv1_fused(const int* __restrict__ x, const float* __restrict__ emb,
            const int* __restrict__ rowptr, const int* __restrict__ esrc,
            const float* __restrict__ w_rel, const float* __restrict__ w_root,
            const float* __restrict__ b,
            float* __restrict__ h1, __nv_bfloat16* __restrict__ h1h,
            __nv_bfloat16* __restrict__ h1l) {
    __shared__ float swr[192], swo[192], sb[64];
    int tid = threadIdx.x;
    if (tid < 192) { swr[tid] = w_rel[tid]; swo[tid] = w_root[tid]; }
    if (tid < 64) sb[tid] = b[tid];
    __syncthreads();
    int node = blockIdx.x * 8 + (tid >> 5);
    int lane = tid & 31;
    if (node >= N_NODES) return;
    int bg = rowptr[node], en = rowptr[node + 1];
    float a0 = 0.f, a1 = 0.f, a2 = 0.f;
    for (int j = bg + lane; j < en; j += 32) {
        int s = esrc[j];
        int lab = x[s];
        a0 += emb[lab * 3 + 0];
        a1 += emb[lab * 3 + 1];
        a2 += emb[lab * 3 + 2];
    }
#pragma unroll
    for (int o = 16; o; o >>= 1) {
        a0 += __shfl_xor_sync(0xffffffff, a0, o);
        a1 += __shfl_xor_sync(0xffffffff, a1, o);
        a2 += __shfl_xor_sync(0xffffffff, a2, o);
    }
    int labn = x[node];
    float x0 = emb[labn * 3 + 0], x1 = emb[labn * 3 + 1], x2 = emb[labn * 3 + 2];
    int c = lane * 2;
    float v0 = sb[c]   + a0*swr[c]   + a1*swr[64+c]   + a2*swr[128+c]
                       + x0*swo[c]   + x1*swo[64+c]   + x2*swo[128+c];
    float v1 = sb[c+1] + a0*swr[c+1] + a1*swr[64+c+1] + a2*swr[128+c+1]
                       + x0*swo[c+1] + x1*swo[64+c+1] + x2*swo[128+c+1];
    v0 = lrelu(v0); v1 = lrelu(v1);
    *reinterpret_cast<float2*>(h1 + (size_t)node * 64 + c) = make_float2(v0, v1);
    float h0f = bf_round(v0), h1f = bf_round(v1);
    reinterpret_cast<uint32_t*>(h1h)[node * 32 + lane] = pack_bf16(h0f, h1f);
    reinterpret_cast<uint32_t*>(h1l)[node * 32 + lane] = pack_bf16(v0 - h0f, v1 - h1f);
}

// ---------------- CSR gather, C=64 -> hi/lo bf16 only -----------------------------
__global__ void gather_h16(const float* __restrict__ xin,
                           __nv_bfloat16* __restrict__ oh, __nv_bfloat16* __restrict__ ol,
                           const int* __restrict__ rowptr, const int* __restrict__ esrc) {
    int i = blockIdx.x * blockDim.x + threadIdx.x;
    if (i >= N_NODES * 16) return;
    int node = i >> 4, c = i & 15;
    int bg = rowptr[node], en = rowptr[node + 1];
    float4 acc = make_float4(0.f, 0.f, 0.f, 0.f);
    for (int j = bg; j < en; j++) {
        int s = esrc[j];
        float4 v = reinterpret_cast<const float4*>(xin)[(size_t)s * 16 + c];
        acc.x += v.x; acc.y += v.y; acc.z += v.z; acc.w += v.w;
    }
    float hx = bf_round(acc.x), hy = bf_round(acc.y), hz = bf_round(acc.z), hw = bf_round(acc.w);
    uint32_t* oh32 = reinterpret_cast<uint32_t*>(oh);
    uint32_t* ol32 = reinterpret_cast<uint32_t*>(ol);
    oh32[node * 32 + c * 2]     = pack_bf16(hx, hy);
    oh32[node * 32 + c * 2 + 1] = pack_bf16(hz, hw);
    ol32[node * 32 + c * 2]     = pack_bf16(acc.x - hx, acc.y - hy);
    ol32[node * 32 + c * 2 + 1] = pack_bf16(acc.z - hz, acc.w - hw);
}

// ---------------- enc finish (warp per node): gather rel + root + bias + leaky ----
// + split to hi/lo + pool red_add. bufE [N][512]: rel cols 0-255, root cols 256-511.
__global__ void __launch_bounds__(256)
gather_enc_fin(const float* __restrict__ bufE, const float* __restrict__ be,
               float* __restrict__ lat, __nv_bfloat16* __restrict__ lath,
               __nv_bfloat16* __restrict__ latl,
               const int* __restrict__ rowptr, const int* __restrict__ esrc,
               const int* __restrict__ batch, float* __restrict__ pooled) {
    int node = (blockIdx.x * blockDim.x + threadIdx.x) >> 5;
    int lane = threadIdx.x & 31;
    if (node >= N_NODES) return;
    int bg = rowptr[node], en = rowptr[node + 1];
    float4 acc0 = make_float4(0.f, 0.f, 0.f, 0.f);
    float4 acc1 = make_float4(0.f, 0.f, 0.f, 0.f);
    for (int j = bg; j < en; j++) {
        int s = esrc[j];                                   // broadcast load
        const float4* row = reinterpret_cast<const float4*>(bufE) + (size_t)s * 128;
        float4 v0 = row[lane];
        float4 v1 = row[lane + 32];
        acc0.x += v0.x; acc0.y += v0.y; acc0.z += v0.z; acc0.w += v0.w;
        acc1.x += v1.x; acc1.y += v1.y; acc1.z += v1.z; acc1.w += v1.w;
    }
    const float4* nrow = reinterpret_cast<const float4*>(bufE) + (size_t)node * 128 + 64;
    float4 rt0 = nrow[lane];
    float4 rt1 = nrow[lane + 32];
    float4 b0 = reinterpret_cast<const float4*>(be)[lane];
    float4 b1 = reinterpret_cast<const float4*>(be)[lane + 32];
    float4 o0, o1;
    o0.x = lrelu(acc0.x + rt0.x + b0.x); o0.y = lrelu(acc0.y + rt0.y + b0.y);
    o0.z = lrelu(acc0.z + rt0.z + b0.z); o0.w = lrelu(acc0.w + rt0.w + b0.w);
    o1.x = lrelu(acc1.x + rt1.x + b1.x); o1.y = lrelu(acc1.y + rt1.y + b1.y);
    o1.z = lrelu(acc1.z + rt1.z + b1.z); o1.w = lrelu(acc1.w + rt1.w + b1.w);
    float4* lrow = reinterpret_cast<float4*>(lat) + (size_t)node * 64;
    lrow[lane] = o0;
    lrow[lane + 32] = o1;
    // hi/lo split
    uint32_t* oh32 = reinterpret_cast<uint32_t*>(lath) + (size_t)node * 128;
    uint32_t* ol32 = reinterpret_cast<uint32_t*>(latl) + (size_t)node * 128;
    {
        float h0 = bf_round(o0.x), h1 = bf_round(o0.y), h2 = bf_round(o0.z), h3 = bf_round(o0.w);
        oh32[lane * 2]     = pack_bf16(h0, h1);
        oh32[lane * 2 + 1] = pack_bf16(h2, h3);
        ol32[lane * 2]     = pack_bf16(o0.x - h0, o0.y - h1);
        ol32[lane * 2 + 1] = pack_bf16(o0.z - h2, o0.w - h3);
        float g0 = bf_round(o1.x), g1 = bf_round(o1.y), g2 = bf_round(o1.z), g3 = bf_round(o1.w);
        oh32[(lane + 32) * 2]     = pack_bf16(g0, g1);
        oh32[(lane + 32) * 2 + 1] = pack_bf16(g2, g3);
        ol32[(lane + 32) * 2]     = pack_bf16(o1.x - g0, o1.y - g1);
        ol32[(lane + 32) * 2 + 1] = pack_bf16(o1.z - g2, o1.w - g3);
    }
    // pool
    int g = batch[node];
    float4* prow = reinterpret_cast<float4*>(pooled) + (size_t)g * 64;
    red_add_v4(prow + lane, o0);
    red_add_v4(prow + lane + 32, o1);
}

// ---------------- CSR gather (warp per node), C=256 -> hi/lo (dec input) ----------
__global__ void __launch_bounds__(256)
gather_c256(const float* __restrict__ xin,
            __nv_bfloat16* __restrict__ oh, __nv_bfloat16* __restrict__ ol,
            const int* __restrict__ rowptr, const int* __restrict__ esrc) {
    int node = (blockIdx.x * blockDim.x + threadIdx.x) >> 5;
    int lane = threadIdx.x & 31;
    if (node >= N_NODES) return;
    int bg = rowptr[node], en = rowptr[node + 1];
    float4 acc0 = make_float4(0.f, 0.f, 0.f, 0.f);
    float4 acc1 = make_float4(0.f, 0.f, 0.f, 0.f);
    for (int j = bg; j < en; j++) {
        int s = esrc[j];                                   // broadcast load
        const float4* row = reinterpret_cast<const float4*>(xin) + (size_t)s * 64;
        float4 v0 = row[lane];
        float4 v1 = row[lane + 32];
        acc0.x += v0.x; acc0.y += v0.y; acc0.z += v0.z; acc0.w += v0.w;
        acc1.x += v1.x; acc1.y += v1.y; acc1.z += v1.z; acc1.w += v1.w;
    }
    uint32_t* oh32 = reinterpret_cast<uint32_t*>(oh) + (size_t)node * 128;
    uint32_t* ol32 = reinterpret_cast<uint32_t*>(ol) + (size_t)node * 128;
    float h0 = bf_round(acc0.x), h1 = bf_round(acc0.y), h2 = bf_round(acc0.z), h3 = bf_round(acc0.w);
    oh32[lane * 2]     = pack_bf16(h0, h1);
    oh32[lane * 2 + 1] = pack_bf16(h2, h3);
    ol32[lane * 2]     = pack_bf16(acc0.x - h0, acc0.y - h1);
    ol32[lane * 2 + 1] = pack_bf16(acc0.z - h2, acc0.w - h3);
    float g0 = bf_round(acc1.x), g1 = bf_round(acc1.y), g2 = bf_round(acc1.z), g3 = bf_round(acc1.w);
    oh32[(lane + 32) * 2]     = pack_bf16(g0, g1);
    oh32[(lane + 32) * 2 + 1] = pack_bf16(g2, g3);
    ol32[(lane + 32) * 2]     = pack_bf16(acc1.x - g0, acc1.y - g1);
    ol32[(lane + 32) * 2 + 1] = pack_bf16(acc1.z - g2, acc1.w - g3);
}

// ---------------- transpose + hi/lo split (paired): [K][N] -> [N][K] --------------
__global__ void transpose_split2(const float* __restrict__ W1, __nv_bfloat16* __restrict__ oh1,
                                 __nv_bfloat16* __restrict__ ol1,
                                 const float* __restrict__ W2, __nv_bfloat16* __restrict__ oh2,
                                 __nv_bfloat16* __restrict__ ol2, int K, int N) {
    const float* W = blockIdx.z ? W2 : W1;
    __nv_bfloat16* oh = blockIdx.z ? oh2 : oh1;
    __nv_bfloat16* ol = blockIdx.z ? ol2 : ol1;
    __shared__ float tile[32][33];
    int n0 = blockIdx.x * 32, k0 = blockIdx.y * 32;
    int tx = threadIdx.x, ty = threadIdx.y;
#pragma unroll
    for (int j = 0; j < 32; j += 8)
        tile[ty + j][tx] = W[(size_t)(k0 + ty + j) * N + n0 + tx];
    __syncthreads();
#pragma unroll
    for (int j = 0; j < 32; j += 8) {
        float v = tile[tx][ty + j];
        float h = bf_round(v);
        size_t o = (size_t)(n0 + ty + j) * K + k0 + tx;
        oh[o] = __float2bfloat16(h);
        ol[o] = __float2bfloat16(v - h);
    }
}

// ---------------- cp.async double-buffered pre-split bf16 GEMM --------------------
// Block tile 128x128, 512 threads (16 warps, 32x32 warp tiles), BK=32.
#define A_TILE_B 10240           // 128 rows * 80 B
#define OFF_AL   10240
#define OFF_BH   20480
#define OFF_BL   30720
#define STAGE_B  40960
#define GEMM_SMEM (2 * STAGE_B)

__global__ void __launch_bounds__(512, 2)
gemm_split(const __nv_bfloat16* __restrict__ A1h, const __nv_bfloat16* __restrict__ A1l, int K1,
           const __nv_bfloat16* __restrict__ A2h, const __nv_bfloat16* __restrict__ A2l, int K2,
           const __nv_bfloat16* __restrict__ W1h, const __nv_bfloat16* __restrict__ W1l,
           const __nv_bfloat16* __restrict__ W2h, const __nv_bfloat16* __restrict__ W2l,
           const float* __restrict__ add, const float* __restrict__ bias,
           float* __restrict__ C, __nv_bfloat16* __restrict__ Ch,
           __nv_bfloat16* __restrict__ Cl, int M, int N, int leaky) {
    extern __shared__ __align__(16) char smc[];
    int tid = threadIdx.x;
    int lane = tid & 31, wid = tid >> 5;
    int wm = (wid & 3) * 32;        // 4 warp-rows over 128
    int wn = (wid >> 2) * 32;       // 4 warp-cols over 128
    int brow = blockIdx.y * 128;
    int bcol = blockIdx.x * 128;
    uint32_t sbase = (uint32_t)__cvta_generic_to_shared(smc);

    float acc[2][4][4];
#pragma unroll
    for (int mt = 0; mt < 2; mt++)
#pragma unroll
        for (int nt = 0; nt < 4; nt++)
#pragma unroll
            for (int r = 0; r < 4; r++) acc[mt][nt][r] = 0.f;

    int T1 = A1h ? (K1 / 32) : 0;
    int T2 = A2h ? (K2 / 32) : 0;
    int T = T1 + T2;

    int srow = tid >> 2;            // 0..127
    int sc   = tid & 3;             // 16B chunk

    // per-lane ldmatrix base offsets
    int lr = lane & 7;
    uint32_t a_off[2];
#pragma unroll
    for (int mt = 0; mt < 2; mt++) {
        int row = wm + mt * 16 + ((lane >> 3) & 1) * 8 + lr;
        a_off[mt] = row * 80 + (lane >> 4) * 16;
    }
    uint32_t b_off[2];
#pragma unroll
    for (int p = 0; p < 2; p++) {
        int n = wn + p * 16 + (lane >> 4) * 8 + lr;
        b_off[p] = n * 80 + ((lane >> 3) & 1) * 16;
    }

    auto issue = [&](int t, int stage) {
        const __nv_bfloat16 *Ah, *Al, *Wh, *Wl; int K, k0;
        if (t < T1) { Ah = A1h; Al = A1l; Wh = W1h; Wl = W1l; K = K1; k0 = t * 32; }
        else        { Ah = A2h; Al = A2l; Wh = W2h; Wl = W2l; K = K2; k0 = (t - T1) * 32; }
        uint32_t sb = sbase + stage * STAGE_B;
        size_t go = (size_t)(brow + srow) * K + k0 + sc * 8;
        cp16(sb + srow * 80 + sc * 16, Ah + go);
        cp16(sb + OFF_AL + srow * 80 + sc * 16, Al + go);
        size_t gb = (size_t)(bcol + srow) * K + k0 + sc * 8;
        cp16(sb + OFF_BH + srow * 80 + sc * 16, Wh + gb);
        cp16(sb + OFF_BL + srow * 80 + sc * 16, Wl + gb);
        cp_commit();
    };

    auto compute = [&](int stage) {
        uint32_t sb = sbase + stage * STAGE_B;
#pragma unroll
        for (int ks = 0; ks < 2; ks++) {
            uint32_t koff = ks * 32;
            uint32_t aH[2][4], aL[2][4], bH[4][2], bL[4][2];
#pragma unroll
            for (int mt = 0; mt < 2; mt++) {
                ldsm4(aH[mt], sb + a_off[mt] + koff);
                ldsm4(aL[mt], sb + OFF_AL + a_off[mt] + koff);
            }
#pragma unroll
            for (int p = 0; p < 2; p++) {
                ldsm4(&bH[p * 2][0], sb + OFF_BH + b_off[p] + koff);
                ldsm4(&bL[p * 2][0], sb + OFF_BL + b_off[p] + koff);
            }
#pragma unroll
            for (int mt = 0; mt < 2; mt++)
#pragma unroll
                for (int nt = 0; nt < 4; nt++) {
                    mma_bf16(acc[mt][nt], aH[mt], bH[nt]);
                    mma_bf16(acc[mt][nt], aH[mt], bL[nt]);
                    mma_bf16(acc[mt][nt], aL[mt], bH[nt]);
                }
        }
    };

    // ---- single-sync pipelined main loop ----
    issue(0, 0);
#pragma unroll 1
    for (int t = 0; t < T; t++) {
        int cur = t & 1;
        cp_wait<0>();
        __syncthreads();
        if (t + 1 < T) issue(t + 1, 1 - cur);
        compute(cur);
    }

    // ---- epilogue ----
#pragma unroll
    for (int mt = 0; mt < 2; mt++) {
#pragma unroll
        for (int nt = 0; nt < 4; nt++) {
            int r0 = brow + wm + mt * 16 + (lane >> 2);
            int c  = bcol + wn + nt * 8 + (lane & 3) * 2;
#pragma unroll
            for (int half = 0; half < 2; half++) {
                int row = r0 + half * 8;
                if (row >= M) continue;
                float v0 = acc[mt][nt][half * 2 + 0];
                float v1 = acc[mt][nt][half * 2 + 1];
                if (add) {
                    const float2 a2 = *reinterpret_cast<const float2*>(add + (size_t)row * N + c);
                    v0 += a2.x; v1 += a2.y;
                }
                if (bias) {
                    const float2 b2 = *reinterpret_cast<const float2*>(bias + c);
                    v0 += b2.x; v1 += b2.y;
                }
                if (leaky) { v0 = lrelu(v0); v1 = lrelu(v1); }
                *reinterpret_cast<float2*>(C + (size_t)row * N + c) = make_float2(v0, v1);
                if (Ch) {
                    float h0 = bf_round(v0), h1f = bf_round(v1);
                    *reinterpret_cast<uint32_t*>(Ch + (size_t)row * N + c) = pack_bf16(h0, h1f);
                    *reinterpret_cast<uint32_t*>(Cl + (size_t)row * N + c) = pack_bf16(v0 - h0, v1 - h1f);
                }
            }
        }
    }
}

// ---------------- logits ----------------------------------------------------------
__global__ void logits_kernel(const float* __restrict__ pooled, const float* __restrict__ counts,
                              const float* __restrict__ w_lin, const float* __restrict__ b_lin,
                              float* __restrict__ out) {
    int g = blockIdx.x;
    int o = threadIdx.x;
    if (o >= OUT_CLS) return;
    float inv = 1.0f / fmaxf(counts[g], 1.0f);
    float s = 0.f;
    const float* pr = pooled + g * 256;
    for (int k = 0; k < 256; k++) s += pr[k] * w_lin[k * OUT_CLS + o];
    out[g * OUT_CLS + o] = s * inv + b_lin[o];
}

// ---------------- host launch -----------------------------------------------------
extern "C" void kernel_launch(void* const* d_in, const int* in_sizes, int n_in,
                              void* d_out, int out_size) {
    const int*   x       = (const int*)d_in[0];
    const int*   ei      = (const int*)d_in[1];
    const int*   batch   = (const int*)d_in[2];
    const float* emb     = (const float*)d_in[3];
    const float* w1_rel  = (const float*)d_in[4];
    const float* w1_root = (const float*)d_in[5];
    const float* b1      = (const float*)d_in[6];
    const float* w2_rel  = (const float*)d_in[7];
    const float* w2_root = (const float*)d_in[8];
    const float* b2      = (const float*)d_in[9];
    const float* we_rel  = (const float*)d_in[10];
    const float* we_root = (const float*)d_in[11];
    const float* be      = (const float*)d_in[12];
    const float* wd_rel  = (const float*)d_in[13];
    const float* wd_root = (const float*)d_in[14];
    const float* bd      = (const float*)d_in[15];
    const float* w_lin   = (const float*)d_in[16];
    const float* b_lin   = (const float*)d_in[17];

    const int* src = ei;
    const int* dst = ei + N_EDGES;

    float* out    = (float*)d_out;
    float* logits = out;
    float* recon  = out + OFF_RECON;
    float* orig   = out + OFF_ORIG;

    float *h1, *bufE, *lat, *pool, *cnt;
    int *deg, *rowptr, *posn, *esrc, *part;
    cudaGetSymbolAddress((void**)&h1,    g_h1);
    cudaGetSymbolAddress((void**)&bufE,  g_enc);
    cudaGetSymbolAddress((void**)&lat,   g_lat);
    cudaGetSymbolAddress((void**)&pool,  g_pool);
    cudaGetSymbolAddress((void**)&cnt,   g_cnt);
    cudaGetSymbolAddress((void**)&deg,   g_deg);
    cudaGetSymbolAddress((void**)&rowptr,g_rowptr);
    cudaGetSymbolAddress((void**)&posn,  g_posn);
    cudaGetSymbolAddress((void**)&esrc,  g_esrc);
    cudaGetSymbolAddress((void**)&part,  g_part);

    __nv_bfloat16 *h1h,*h1l,*a1h,*a1l,*oh,*ol,*lath,*latl,*aggh,*aggl;
    __nv_bfloat16 *w2rh,*w2rl,*w2oh,*w2ol,*wcath,*wcatl,*wdrh,*wdrl,*wdoh,*wdol;
    cudaGetSymbolAddress((void**)&h1h, g_h1h);   cudaGetSymbolAddress((void**)&h1l, g_h1l);
    cudaGetSymbolAddress((void**)&a1h, g_a1h);   cudaGetSymbolAddress((void**)&a1l, g_a1l);
    cudaGetSymbolAddress((void**)&oh,  g_oh);    cudaGetSymbolAddress((void**)&ol,  g_ol);
    cudaGetSymbolAddress((void**)&lath,g_lath);  cudaGetSymbolAddress((void**)&latl,g_latl);
    cudaGetSymbolAddress((void**)&aggh,g_aggh);  cudaGetSymbolAddress((void**)&aggl,g_aggl);
    cudaGetSymbolAddress((void**)&w2rh,g_w2r_h); cudaGetSymbolAddress((void**)&w2rl,g_w2r_l);
    cudaGetSymbolAddress((void**)&w2oh,g_w2o_h); cudaGetSymbolAddress((void**)&w2ol,g_w2o_l);
    cudaGetSymbolAddress((void**)&wcath,g_wcat_h); cudaGetSymbolAddress((void**)&wcatl,g_wcat_l);
    cudaGetSymbolAddress((void**)&wdrh,g_wdr_h); cudaGetSymbolAddress((void**)&wdrl,g_wdr_l);
    cudaGetSymbolAddress((void**)&wdoh,g_wdo_h); cudaGetSymbolAddress((void**)&wdol,g_wdo_l);

    cudaFuncSetAttribute(gemm_split, cudaFuncAttributeMaxDynamicSharedMemorySize, GEMM_SMEM);

    // CSR build
    zero_misc<<<256, 256>>>(deg, pool, cnt);
    hist_kernel<<<(N_EDGES + 255) / 256, 256>>>(dst, deg, batch, cnt);
    scan_local<<<SCAN_BLOCKS, 1024>>>(deg, rowptr, part);
    scan_partials<<<1, 64>>>(part);
    scan_add<<<(N_NODES + 255) / 256, 256>>>(rowptr, part, posn);
    scatter_kernel<<<(N_EDGES + 255) / 256, 256>>>(src, dst, posn, esrc);

    // fused conv1
    conv1_fused<<<(N_NODES + 7) / 8, 256>>>(x, emb, rowptr, esrc,
                                            w1_rel, w1_root, b1, h1, h1h, h1l);

    // 64-wide gather (h1 -> aggr hi/lo)
    gather_h16<<<(N_NODES * 16 + 255) / 256, 256>>>(h1, a1h, a1l, rowptr, esrc);

    // w2 transposes (paired)
    {
        dim3 b(32, 8);
        transpose_split2<<<dim3(1024/32, 64/32, 2), b>>>(w2_rel, w2rh, w2rl,
                                                         w2_root, w2oh, w2ol, 64, 1024);
    }
    // conv2 GEMM -> orig (+hi/lo)
    {
        dim3 grid(1024 / 128, (N_NODES + 127) / 128);
        gemm_split<<<grid, 512, GEMM_SMEM>>>(a1h, a1l, 64, h1h, h1l, 64,
                                             w2rh, w2rl, w2oh, w2ol,
                                             nullptr, b2, orig, oh, ol, N_NODES, 1024, 1);
    }

    // we transposes (paired) -> concatenated [512][1024]
    {
        dim3 b(32, 8);
        transpose_split2<<<dim3(256/32, 1024/32, 2), b>>>(we_rel, wcath, wcatl,
                                                          we_root, wcath + 256 * 1024,
                                                          wcatl + 256 * 1024, 1024, 256);
    }
    // fused enc GEMM (N=512): bufE = [orig@we_rel | orig@we_root]
    {
        dim3 grid(512 / 128, (N_NODES + 127) / 128);
        gemm_split<<<grid, 512, GEMM_SMEM>>>(oh, ol, 1024, nullptr, nullptr, 0,
                                             wcath, wcatl, nullptr, nullptr,
                                             nullptr, nullptr, bufE, nullptr, nullptr,
                                             N_NODES, 512, 0);
    }
    // enc finish (warp/node): gather rel + root + bias + leaky -> lat (+hi/lo) + pool
    gather_enc_fin<<<(N_NODES * 32 + 255) / 256, 256>>>(bufE, be, lat, lath, latl,
                                                        rowptr, esrc, batch, pool);

    // 256-wide gather (warp/node) lat -> agg hi/lo
    gather_c256<<<(N_NODES * 32 + 255) / 256, 256>>>(lat, aggh, aggl, rowptr, esrc);

    // logits
    logits_kernel<<<N_GRAPHS, 32>>>(pool, cnt, w_lin, b_lin, logits);

    // wd transposes (paired)
    {
        dim3 b(32, 8);
        transpose_split2<<<dim3(1024/32, 256/32, 2), b>>>(wd_rel, wdrh, wdrl,
                                                          wd_root, wdoh, wdol, 256, 1024);
    }
    // dec GEMM -> recon
    {
        dim3 grid(1024 / 128, (N_NODES + 127) / 128);
        gemm_split<<<grid, 512, GEMM_SMEM>>>(aggh, aggl, 256, lath, latl, 256,
                                             wdrh, wdrl, wdoh, wdol,
                                             nullptr, bd, recon, nullptr, nullptr,
                                             N_NODES, 1024, 1);
    }
}